// round 6
// baseline (speedup 1.0000x reference)
#include <cuda_runtime.h>
#include <math.h>
#include <stdint.h>

#define E_TOTAL 500000
#define TM 64
#define NTILES ((E_TOTAL + TM - 1) / TM)   // 7813
#define NCOL 384
#define CDIM 128

// fused weights/bias: cols [0,128)=attn-u path, [128,256)=GeGLU x, [256,384)=GeGLU gate
__device__ float g_W[256 * NCOL];
__device__ float g_c[NCOL];
__device__ int   g_idx64;

// packed f32x2 helpers (sm_103a)
#define FFMA2(d, a, b) asm("fma.rn.f32x2 %0, %1, %2, %0;" : "+l"(d) : "l"(a), "l"(b))
#define UNPACK2(lo, hi, v) asm("mov.b64 {%0, %1}, %2;" : "=f"(lo), "=f"(hi) : "l"(v))

// ---------------------------------------------------------------------------
__global__ void detect_idx_kernel(const int* __restrict__ idx32) {
    if (threadIdx.x == 0) {
        int nz = 0;
        for (int i = 0; i < 256; i++) nz |= idx32[2 * i + 1];
        g_idx64 = (nz == 0) ? 1 : 0;
    }
}

// g_W[k][j] = fused weight; k<128 uses Ws row, else Wt row
__global__ void precompute_W_kernel(const float* __restrict__ Ws, const float* __restrict__ Wt,
                                    const float* __restrict__ Wa1, const float* __restrict__ We) {
    int t = blockIdx.x * blockDim.x + threadIdx.x;
    if (t >= 256 * NCOL) return;
    int k = t / NCOL;
    int j = t % NCOL;
    const float* arow = (k < 128) ? (Ws + k * 128) : (Wt + (k - 128) * 128);
    const int off = (k < 128) ? 0 : 128;
    float sum = 0.f;
    if (j < 128) {
        const float* bcol = Wa1 + off * 128 + j;
        #pragma unroll 4
        for (int m = 0; m < 128; m++) sum = fmaf(arow[m], bcol[m * 128], sum);
    } else {
        const float* bcol = We + off * 256 + (j - 128);
        #pragma unroll 4
        for (int m = 0; m < 128; m++) sum = fmaf(arow[m], bcol[m * 256], sum);
    }
    g_W[k * NCOL + j] = sum;
}

__global__ void precompute_c_kernel(const float* __restrict__ Wa1, const float* __restrict__ We,
                                    const float* __restrict__ bs, const float* __restrict__ bt,
                                    const float* __restrict__ ba1) {
    int j = blockIdx.x * blockDim.x + threadIdx.x;
    if (j >= NCOL) return;
    float s;
    if (j < 128) {
        s = ba1[j];
        for (int m = 0; m < 128; m++)
            s += bs[m] * Wa1[m * 128 + j] + bt[m] * Wa1[(128 + m) * 128 + j];
    } else {
        const int jj = j - 128;
        s = 0.f;
        for (int m = 0; m < 128; m++)
            s += bs[m] * We[m * 256 + jj] + bt[m] * We[(128 + m) * 256 + jj];
    }
    g_c[j] = s;
}

// ---------------------------------------------------------------------------
// Fused kernel: Y[64, 384] = X_tile[64, 256] @ g_W + g_c, then
//   attn = sigmoid(relu(Y[:, :128]) . Wa2 + ba2)     (warp shfl reduction)
//   z    = attn * Y[:, 128:] + be ; GeGLU ; LayerNorm ; store.
// 256 threads = 8 warps (rowg) x 32 lanes (colg); thread = 8 rows x 12 cols
// (3 float4 col-groups at 4*colg + 128*jq). Inner loop is pure FFMA2:
// A duplicated in smem -> broadcast LDS.64 gives (a,a) pairs with zero MOVs;
// B pairs come packed from LDS.128.
// ---------------------------------------------------------------------------
// smem: 98304 (sB) + 32768 (sAd) + 4096 (sC/sWa2/sBe/sGa/sBt) + 512 (idx) = 135680
#define SMEM_BYTES 135680

__global__ void __launch_bounds__(256, 1) fused_kernel(
    const float* __restrict__ emb, const void* __restrict__ eidx,
    const float* __restrict__ Wa2, const float* __restrict__ ba2,
    const float* __restrict__ be, const float* __restrict__ gamma,
    const float* __restrict__ beta, float* __restrict__ out)
{
    extern __shared__ float sm[];
    float* sB   = sm;                    // 64*384 = 24576 floats
    float* sAd  = sB + 64 * NCOL;        // 64k x 64r duplicated: 8192 floats
    float* sC   = sAd + 64 * 128;        // 384
    float* sWa2 = sC + NCOL;             // 128
    float* sBe  = sWa2 + 128;            // 256
    float* sGa  = sBe + 256;             // 128
    float* sBt  = sGa + 128;             // 128
    int*   sSrc = (int*)(sBt + 128);     // 64
    int*   sTgt = sSrc + 64;             // 64

    const int tid = threadIdx.x;
    if (tid < 128) { sWa2[tid] = Wa2[tid]; sGa[tid] = gamma[tid]; sBt[tid] = beta[tid]; }
    sBe[tid] = be[tid];
    for (int i = tid; i < NCOL; i += 256) sC[i] = g_c[i];

    const int e0 = blockIdx.x * TM;
    const int cnt = min(TM, E_TOTAL - e0);
    if (tid < TM) {
        int s = 0, t = 0;
        if (tid < cnt) {
            if (g_idx64) {
                const long long* p = (const long long*)eidx;
                s = (int)p[e0 + tid]; t = (int)p[E_TOTAL + e0 + tid];
            } else {
                const int* p = (const int*)eidx;
                s = p[e0 + tid]; t = p[E_TOTAL + e0 + tid];
            }
        }
        sSrc[tid] = s; sTgt[tid] = t;
    }

    const int rowg = tid >> 5;   // warp id: rows rowg*8 .. +7
    const int colg = tid & 31;   // col base 4*colg (+128*jq)

    unsigned long long acc[8][6];
    #pragma unroll
    for (int i = 0; i < 8; i++) {
        #pragma unroll
        for (int j = 0; j < 6; j++) acc[i][j] = 0ull;
    }

    #pragma unroll 1
    for (int kc = 0; kc < 4; kc++) {
        __syncthreads();
        {   // stream fused-weight chunk [64 x 384] (L2-resident, coalesced)
            const float4* gB = (const float4*)(g_W + kc * 64 * NCOL);
            float4* s4 = (float4*)sB;
            #pragma unroll
            for (int q = 0; q < 24; q++) s4[tid + q * 256] = gB[tid + q * 256];
        }
        {   // gather A chunk, stored DUPLICATED: sAd[kk] holds (x,x) per row
            const int r = tid >> 2, qt = tid & 3;
            const int node = (kc < 2) ? sSrc[r] : sTgt[r];
            const float4* src = (const float4*)(emb + (size_t)node * CDIM + (kc & 1) * 64 + qt * 16);
            float2* sd = (float2*)sAd;
            #pragma unroll
            for (int q = 0; q < 4; q++) {
                float4 v = src[q];
                const int kk = qt * 16 + q * 4;
                sd[(kk + 0) * TM + r] = make_float2(v.x, v.x);
                sd[(kk + 1) * TM + r] = make_float2(v.y, v.y);
                sd[(kk + 2) * TM + r] = make_float2(v.z, v.z);
                sd[(kk + 3) * TM + r] = make_float2(v.w, v.w);
            }
        }
        __syncthreads();
        const unsigned long long* sAd64 = (const unsigned long long*)sAd;
        #pragma unroll 4
        for (int kk = 0; kk < 64; kk++) {
            // broadcast (a,a) pairs — no packing MOVs
            unsigned long long ad[8];
            #pragma unroll
            for (int i = 0; i < 8; i++) ad[i] = sAd64[kk * TM + rowg * 8 + i];
            const float* br = sB + kk * NCOL + colg * 4;
            ulonglong2 b0 = *(const ulonglong2*)br;            // u cols
            ulonglong2 b1 = *(const ulonglong2*)(br + 128);    // x cols
            ulonglong2 b2 = *(const ulonglong2*)(br + 256);    // gate cols
            #pragma unroll
            for (int i = 0; i < 8; i++) {
                FFMA2(acc[i][0], ad[i], b0.x);
                FFMA2(acc[i][1], ad[i], b0.y);
                FFMA2(acc[i][2], ad[i], b1.x);
                FFMA2(acc[i][3], ad[i], b1.y);
                FFMA2(acc[i][4], ad[i], b2.x);
                FFMA2(acc[i][5], ad[i], b2.y);
            }
        }
    }

    // ---- epilogue ----
    const float ba2v = ba2[0];
    const int cb = colg * 4;
    #pragma unroll 1
    for (int i = 0; i < 8; i++) {
        const int r = rowg * 8 + i;
        // attention gate: relu(u) . Wa2 over this thread's 4 u-cols, warp-reduce
        float u0, u1, u2, u3;
        UNPACK2(u0, u1, acc[i][0]);
        UNPACK2(u2, u3, acc[i][1]);
        u0 = fmaxf(u0 + sC[cb + 0], 0.f);
        u1 = fmaxf(u1 + sC[cb + 1], 0.f);
        u2 = fmaxf(u2 + sC[cb + 2], 0.f);
        u3 = fmaxf(u3 + sC[cb + 3], 0.f);
        float part = u0 * sWa2[cb] + u1 * sWa2[cb + 1] + u2 * sWa2[cb + 2] + u3 * sWa2[cb + 3];
        #pragma unroll
        for (int o = 16; o >= 1; o >>= 1)
            part += __shfl_xor_sync(0xffffffffu, part, o);
        const float attn = 1.f / (1.f + expf(-(part + ba2v)));

        // GeGLU
        float x0, x1, x2, x3, g0, g1, g2, g3;
        UNPACK2(x0, x1, acc[i][2]);
        UNPACK2(x2, x3, acc[i][3]);
        UNPACK2(g0, g1, acc[i][4]);
        UNPACK2(g2, g3, acc[i][5]);
        float xv[4] = {x0, x1, x2, x3};
        float gvv[4] = {g0, g1, g2, g3};
        float gv[4];
        #pragma unroll
        for (int q = 0; q < 4; q++) {
            const int m = cb + q;
            const float zx = fmaf(attn, xv[q]  + sC[128 + m], sBe[m]);
            const float zg = fmaf(attn, gvv[q] + sC[256 + m], sBe[128 + m]);
            const float gel = 0.5f * zg * (1.f + erff(zg * 0.70710678118654752f));
            gv[q] = zx * gel;
        }
        // LayerNorm over 128 cols (32 lanes x 4)
        float s1 = gv[0] + gv[1] + gv[2] + gv[3];
        float s2 = gv[0] * gv[0] + gv[1] * gv[1] + gv[2] * gv[2] + gv[3] * gv[3];
        #pragma unroll
        for (int o = 16; o >= 1; o >>= 1) {
            s1 += __shfl_xor_sync(0xffffffffu, s1, o);
            s2 += __shfl_xor_sync(0xffffffffu, s2, o);
        }
        const float mu = s1 * (1.f / 128.f);
        const float var = s2 * (1.f / 128.f) - mu * mu;
        const float rstd = rsqrtf(var + 1e-5f);
        if (r < cnt) {
            float4 o4;
            o4.x = (gv[0] - mu) * rstd * sGa[cb + 0] + sBt[cb + 0];
            o4.y = (gv[1] - mu) * rstd * sGa[cb + 1] + sBt[cb + 1];
            o4.z = (gv[2] - mu) * rstd * sGa[cb + 2] + sBt[cb + 2];
            o4.w = (gv[3] - mu) * rstd * sGa[cb + 3] + sBt[cb + 3];
            *(float4*)(out + (size_t)(e0 + r) * CDIM + cb) = o4;
        }
    }
}

// ---------------------------------------------------------------------------
extern "C" void kernel_launch(void* const* d_in, const int* in_sizes, int n_in,
                              void* d_out, int out_size) {
    const float* emb   = (const float*)d_in[0];
    const void*  eidx  = d_in[1];
    const float* Ws    = (const float*)d_in[2];
    const float* bs    = (const float*)d_in[3];
    const float* Wt    = (const float*)d_in[4];
    const float* bt    = (const float*)d_in[5];
    const float* Wa1   = (const float*)d_in[6];
    const float* ba1   = (const float*)d_in[7];
    const float* Wa2   = (const float*)d_in[8];
    const float* ba2   = (const float*)d_in[9];
    const float* We    = (const float*)d_in[10];
    const float* be    = (const float*)d_in[11];
    const float* gamma = (const float*)d_in[12];
    const float* beta  = (const float*)d_in[13];
    float* out = (float*)d_out;

    cudaFuncSetAttribute(fused_kernel, cudaFuncAttributeMaxDynamicSharedMemorySize, SMEM_BYTES);

    detect_idx_kernel<<<1, 32>>>((const int*)eidx);
    precompute_W_kernel<<<(256 * NCOL + 255) / 256, 256>>>(Ws, Wt, Wa1, We);
    precompute_c_kernel<<<2, 256>>>(Wa1, We, bs, bt, ba1);
    fused_kernel<<<NTILES, 256, SMEM_BYTES>>>(emb, eidx, Wa2, ba2, be, gamma, beta, out);
}

// round 8
// speedup vs baseline: 2.3609x; 2.3609x over previous
#include <cuda_runtime.h>
#include <cuda_bf16.h>
#include <math.h>
#include <stdint.h>

#define E_TOTAL 500000
#define TM 64
#define NTILES ((E_TOTAL + TM - 1) / TM)   // 7813
#define NCOL 384
#define CDIM 128

// fused fp32 weights (logical cols: 0..127 attn-u, 128..255 GeGLU-x, 256..383 gate)
__device__ float g_W[256 * NCOL];
__device__ float g_c[NCOL];
__device__ int   g_idx64;
// bf16 hi/lo split of reordered W^T, XOR-swizzled, per 64-K chunk:
// physical col p (0..383): w=p/192, q=p%192; q<64->u[64w+q], q<128->x, else gate.
// layout [kc][p][64 bf16 k-values], byte-in-row swizzled by ((p&7)<<4).
__device__ __nv_bfloat16 g_Wswhi[4 * 384 * 64];
__device__ __nv_bfloat16 g_Wswlo[4 * 384 * 64];

// ---------------------------------------------------------------------------
__device__ __forceinline__ uint32_t smem_u32(const void* p) {
    uint32_t a;
    asm("{ .reg .u64 t; cvta.to.shared.u64 t, %1; cvt.u32.u64 %0, t; }" : "=r"(a) : "l"(p));
    return a;
}

#define LDMATRIX_X4(r0, r1, r2, r3, addr) \
    asm volatile("ldmatrix.sync.aligned.m8n8.x4.shared.b16 {%0,%1,%2,%3}, [%4];" \
        : "=r"(r0), "=r"(r1), "=r"(r2), "=r"(r3) : "r"(addr))

#define MMA_BF16(d, a0, a1, a2, a3, b0, b1) \
    asm volatile("mma.sync.aligned.m16n8k16.row.col.f32.bf16.bf16.f32 " \
        "{%0,%1,%2,%3}, {%4,%5,%6,%7}, {%8,%9}, {%0,%1,%2,%3};" \
        : "+f"((d)[0]), "+f"((d)[1]), "+f"((d)[2]), "+f"((d)[3]) \
        : "r"(a0), "r"(a1), "r"(a2), "r"(a3), "r"(b0), "r"(b1))

// smem byte offsets
#define OFF_BHI   0u
#define OFF_BLO   49152u
#define OFF_AHI   98304u
#define OFF_ALO   106496u
#define OFF_SRC   114688u
#define OFF_TGT   114944u
#define OFF_C     115200u
#define OFF_WA2   116736u
#define OFF_BE    117248u
#define OFF_GA    118272u
#define OFF_BT    118784u
#define OFF_P     119296u     // 128 f
#define OFF_S1    119808u     // 128 f
#define OFF_S2    120320u     // 128 f
#define SMEM_BYTES 120832

// ---------------------------------------------------------------------------
__global__ void detect_idx_kernel(const int* __restrict__ idx32) {
    if (threadIdx.x == 0) {
        int nz = 0;
        for (int i = 0; i < 256; i++) nz |= idx32[2 * i + 1];
        g_idx64 = (nz == 0) ? 1 : 0;
    }
}

__global__ void precompute_W_kernel(const float* __restrict__ Ws, const float* __restrict__ Wt,
                                    const float* __restrict__ Wa1, const float* __restrict__ We) {
    int t = blockIdx.x * blockDim.x + threadIdx.x;
    if (t >= 256 * NCOL) return;
    int k = t / NCOL;
    int j = t % NCOL;
    const float* arow = (k < 128) ? (Ws + k * 128) : (Wt + (k - 128) * 128);
    const int off = (k < 128) ? 0 : 128;
    float sum = 0.f;
    if (j < 128) {
        const float* bcol = Wa1 + off * 128 + j;
        #pragma unroll 4
        for (int m = 0; m < 128; m++) sum = fmaf(arow[m], bcol[m * 128], sum);
    } else {
        const float* bcol = We + off * 256 + (j - 128);
        #pragma unroll 4
        for (int m = 0; m < 128; m++) sum = fmaf(arow[m], bcol[m * 256], sum);
    }
    g_W[k * NCOL + j] = sum;
}

__global__ void precompute_c_kernel(const float* __restrict__ Wa1, const float* __restrict__ We,
                                    const float* __restrict__ bs, const float* __restrict__ bt,
                                    const float* __restrict__ ba1) {
    int j = blockIdx.x * blockDim.x + threadIdx.x;
    if (j >= NCOL) return;
    float s;
    if (j < 128) {
        s = ba1[j];
        for (int m = 0; m < 128; m++)
            s += bs[m] * Wa1[m * 128 + j] + bt[m] * Wa1[(128 + m) * 128 + j];
    } else {
        const int jj = j - 128;
        s = 0.f;
        for (int m = 0; m < 128; m++)
            s += bs[m] * We[m * 256 + jj] + bt[m] * We[(128 + m) * 256 + jj];
    }
    g_c[j] = s;
}

// reorder cols, split hi/lo bf16, transpose to [p][k], bake XOR swizzle
__global__ void convert_W_kernel() {
    int t = blockIdx.x * blockDim.x + threadIdx.x;
    if (t >= 4 * 384 * 64) return;
    const int kc = t / (384 * 64);
    const int rem = t % (384 * 64);
    const int p = rem / 64;      // physical B row (output col)
    const int c = rem % 64;      // k within chunk
    const int w = p / 192, q = p % 192;
    int L;
    if (q < 64)       L = 64 * w + q;               // u
    else if (q < 128) L = 128 + 64 * w + (q - 64);  // x
    else              L = 256 + 64 * w + (q - 128); // gate
    const float v = g_W[(kc * 64 + c) * NCOL + L];
    const __nv_bfloat16 hi = __float2bfloat16(v);
    const __nv_bfloat16 lo = __float2bfloat16(v - __bfloat162float(hi));
    const int sw_byte = (c * 2) ^ ((p & 7) << 4);
    const int idx = kc * (384 * 64) + p * 64 + sw_byte / 2;
    g_Wswhi[idx] = hi;
    g_Wswlo[idx] = lo;
}

// ---------------------------------------------------------------------------
__device__ __forceinline__ void split2(float a, float b, unsigned& h, unsigned& l) {
    __nv_bfloat16 ha = __float2bfloat16(a), hb = __float2bfloat16(b);
    float ra = a - __bfloat162float(ha);
    float rb = b - __bfloat162float(hb);
    __nv_bfloat16 la = __float2bfloat16(ra), lb = __float2bfloat16(rb);
    h = (unsigned)__bfloat16_as_ushort(ha) | ((unsigned)__bfloat16_as_ushort(hb) << 16);
    l = (unsigned)__bfloat16_as_ushort(la) | ((unsigned)__bfloat16_as_ushort(lb) << 16);
}

// ---------------------------------------------------------------------------
// One CTA per 64-edge tile. 8 warps = 4 rowg x 2 colg; warp = 16 rows x 192
// physical cols (24 n8 accumulator tiles). bf16 mma.sync with hi/lo 3-product
// split; fused attn-gate + GeGLU + LayerNorm epilogue on register fragments.
// ---------------------------------------------------------------------------
__global__ void __launch_bounds__(256, 1) fused_kernel(
    const float* __restrict__ emb, const void* __restrict__ eidx,
    const float* __restrict__ Wa2, const float* __restrict__ ba2,
    const float* __restrict__ be, const float* __restrict__ gamma,
    const float* __restrict__ beta, float* __restrict__ out)
{
    extern __shared__ char smem[];
    const uint32_t sbase = smem_u32(smem);
    const int tid = threadIdx.x;
    const int wid = tid >> 5;
    const int lane = tid & 31;
    const int rowg = wid >> 1;
    const int colg = wid & 1;

    float* sC   = (float*)(smem + OFF_C);
    float* sWa2 = (float*)(smem + OFF_WA2);
    float* sBe  = (float*)(smem + OFF_BE);
    float* sGa  = (float*)(smem + OFF_GA);
    float* sBt  = (float*)(smem + OFF_BT);
    float* sP   = (float*)(smem + OFF_P);
    float* sS1  = (float*)(smem + OFF_S1);
    float* sS2  = (float*)(smem + OFF_S2);
    int*   sSrc = (int*)(smem + OFF_SRC);
    int*   sTgt = (int*)(smem + OFF_TGT);

    if (tid < 128) { sWa2[tid] = Wa2[tid]; sGa[tid] = gamma[tid]; sBt[tid] = beta[tid]; }
    sBe[tid] = be[tid];
    for (int i = tid; i < NCOL; i += 256) sC[i] = g_c[i];

    const int e0 = blockIdx.x * TM;
    const int cnt = min(TM, E_TOTAL - e0);
    if (tid < TM) {
        int s = 0, t = 0;
        if (tid < cnt) {
            if (g_idx64) {
                const long long* p = (const long long*)eidx;
                s = (int)p[e0 + tid]; t = (int)p[E_TOTAL + e0 + tid];
            } else {
                const int* p = (const int*)eidx;
                s = p[e0 + tid]; t = p[E_TOTAL + e0 + tid];
            }
        }
        sSrc[tid] = s; sTgt[tid] = t;
    }

    // ldmatrix per-lane addressing (constant across k-steps except XOR'd k byte)
    const uint32_t a_row = rowg * 16 + ((lane >> 3) & 1) * 8 + (lane & 7);
    const uint32_t a_k   = (lane >> 4) * 16;
    const uint32_t b_row = colg * 192 + (lane >> 4) * 8 + (lane & 7);
    const uint32_t b_k   = ((lane >> 3) & 1) * 16;
    const uint32_t swz   = (lane & 7) << 4;     // a_row&7 == b_row&7 == lane&7
    const uint32_t a_off = a_row * 128;
    const uint32_t b_off = b_row * 128;

    float acc[24][4];
    #pragma unroll
    for (int t = 0; t < 24; t++) {
        #pragma unroll
        for (int q = 0; q < 4; q++) acc[t][q] = 0.f;
    }

    const int r_g = tid >> 2;       // gather row (0..63)
    const int qt  = tid & 3;        // k-quarter (16 floats)

    #pragma unroll 1
    for (int kc = 0; kc < 4; kc++) {
        __syncthreads();
        {   // stream pre-swizzled weight chunk (hi+lo, 96KB, linear)
            const uint4* ghi = (const uint4*)g_Wswhi + kc * 3072;
            const uint4* glo = (const uint4*)g_Wswlo + kc * 3072;
            uint4* dhi = (uint4*)(smem + OFF_BHI);
            uint4* dlo = (uint4*)(smem + OFF_BLO);
            #pragma unroll
            for (int q = 0; q < 12; q++) {
                dhi[tid + q * 256] = ghi[tid + q * 256];
                dlo[tid + q * 256] = glo[tid + q * 256];
            }
        }
        {   // gather X chunk, split hi/lo, swizzled store
            const int node = (kc < 2) ? sSrc[r_g] : sTgt[r_g];
            const float4* src = (const float4*)(emb + (size_t)node * CDIM + (kc & 1) * 64 + qt * 16);
            const float4 v0 = src[0], v1 = src[1], v2 = src[2], v3 = src[3];
            uint4 H0, L0, H1, L1;
            split2(v0.x, v0.y, H0.x, L0.x);
            split2(v0.z, v0.w, H0.y, L0.y);
            split2(v1.x, v1.y, H0.z, L0.z);
            split2(v1.z, v1.w, H0.w, L0.w);
            split2(v2.x, v2.y, H1.x, L1.x);
            split2(v2.z, v2.w, H1.y, L1.y);
            split2(v3.x, v3.y, H1.z, L1.z);
            split2(v3.z, v3.w, H1.w, L1.w);
            const uint32_t rs = (uint32_t)(r_g & 7) << 4;
            const int s0 = r_g * 128 + ((qt * 32) ^ rs);
            const int s1 = r_g * 128 + ((qt * 32 + 16) ^ rs);
            *(uint4*)(smem + OFF_AHI + s0) = H0;
            *(uint4*)(smem + OFF_AHI + s1) = H1;
            *(uint4*)(smem + OFF_ALO + s0) = L0;
            *(uint4*)(smem + OFF_ALO + s1) = L1;
        }
        __syncthreads();

        #pragma unroll
        for (int p = 0; p < 3; p++) {
            const uint32_t abase = sbase + (p == 2 ? OFF_ALO : OFF_AHI) + a_off;
            const uint32_t bbase = sbase + (p == 1 ? OFF_BLO : OFF_BHI) + b_off;
            #pragma unroll
            for (int s = 0; s < 4; s++) {
                uint32_t A0, A1, A2, A3;
                LDMATRIX_X4(A0, A1, A2, A3, abase + (((uint32_t)s * 32 + a_k) ^ swz));
                const uint32_t bk = ((uint32_t)s * 32 + b_k) ^ swz;
                #pragma unroll
                for (int jj = 0; jj < 12; jj++) {
                    uint32_t B0, B1, B2, B3;
                    LDMATRIX_X4(B0, B1, B2, B3, bbase + jj * 2048 + bk);
                    MMA_BF16(acc[jj * 2],     A0, A1, A2, A3, B0, B1);
                    MMA_BF16(acc[jj * 2 + 1], A0, A1, A2, A3, B2, B3);
                }
            }
        }
    }

    // ---- epilogue on register fragments ----
    // thread owns rows rl=rowg*16+(lane>>2) and rl+8; tile t: cols colg*192+t*8+(lane&3)*2+{0,1}
    const int rl = rowg * 16 + (lane >> 2);
    const int ql = lane & 3;
    const float ba2v = ba2[0];

    // attn-u partial (tiles 0..7 = u cols 64*colg + ...)
    float part[2] = {0.f, 0.f};
    #pragma unroll
    for (int j = 0; j < 8; j++) {
        #pragma unroll
        for (int q = 0; q < 2; q++) {
            const int ucol = colg * 64 + j * 8 + ql * 2 + q;
            const float cu = sC[ucol], wv = sWa2[ucol];
            part[0] = fmaf(fmaxf(acc[j][q]     + cu, 0.f), wv, part[0]);
            part[1] = fmaf(fmaxf(acc[j][2 + q] + cu, 0.f), wv, part[1]);
        }
    }
    #pragma unroll
    for (int h = 0; h < 2; h++) {
        part[h] += __shfl_xor_sync(0xffffffffu, part[h], 1);
        part[h] += __shfl_xor_sync(0xffffffffu, part[h], 2);
    }
    if (ql == 0) {
        sP[colg * 64 + rl]     = part[0];
        sP[colg * 64 + rl + 8] = part[1];
    }
    __syncthreads();
    float attn[2];
    #pragma unroll
    for (int h = 0; h < 2; h++) {
        const int r = rl + 8 * h;
        attn[h] = 1.f / (1.f + expf(-(sP[r] + sP[64 + r] + ba2v)));
    }

    // GeGLU: x tiles 8..15 pair with gate tiles 16..23 (same thread, same offset)
    float gv[2][16];
    float s1[2] = {0.f, 0.f}, s2[2] = {0.f, 0.f};
    #pragma unroll
    for (int j = 0; j < 8; j++) {
        #pragma unroll
        for (int q = 0; q < 2; q++) {
            const int m = colg * 64 + j * 8 + ql * 2 + q;
            const float cx = sC[128 + m], cg = sC[256 + m];
            const float bx = sBe[m], bg = sBe[128 + m];
            #pragma unroll
            for (int h = 0; h < 2; h++) {
                const float zx = fmaf(attn[h], acc[8 + j][2 * h + q]  + cx, bx);
                const float zg = fmaf(attn[h], acc[16 + j][2 * h + q] + cg, bg);
                const float gel = 0.5f * zg * (1.f + erff(zg * 0.70710678118654752f));
                const float v = zx * gel;
                gv[h][j * 2 + q] = v;
                s1[h] += v;
                s2[h] = fmaf(v, v, s2[h]);
            }
        }
    }
    #pragma unroll
    for (int h = 0; h < 2; h++) {
        s1[h] += __shfl_xor_sync(0xffffffffu, s1[h], 1);
        s1[h] += __shfl_xor_sync(0xffffffffu, s1[h], 2);
        s2[h] += __shfl_xor_sync(0xffffffffu, s2[h], 1);
        s2[h] += __shfl_xor_sync(0xffffffffu, s2[h], 2);
    }
    if (ql == 0) {
        sS1[colg * 64 + rl]     = s1[0];
        sS1[colg * 64 + rl + 8] = s1[1];
        sS2[colg * 64 + rl]     = s2[0];
        sS2[colg * 64 + rl + 8] = s2[1];
    }
    __syncthreads();
    #pragma unroll
    for (int h = 0; h < 2; h++) {
        const int r = rl + 8 * h;
        const float S1 = sS1[r] + sS1[64 + r];
        const float S2 = sS2[r] + sS2[64 + r];
        const float mu = S1 * (1.f / 128.f);
        const float var = S2 * (1.f / 128.f) - mu * mu;
        const float rstd = rsqrtf(var + 1e-5f);
        if (r < cnt) {
            float* orow = out + (size_t)(e0 + r) * CDIM;
            #pragma unroll
            for (int j = 0; j < 8; j++) {
                const int m = colg * 64 + j * 8 + ql * 2;
                float2 o;
                o.x = (gv[h][j * 2]     - mu) * rstd * sGa[m]     + sBt[m];
                o.y = (gv[h][j * 2 + 1] - mu) * rstd * sGa[m + 1] + sBt[m + 1];
                *(float2*)(orow + m) = o;
            }
        }
    }
}

// ---------------------------------------------------------------------------
extern "C" void kernel_launch(void* const* d_in, const int* in_sizes, int n_in,
                              void* d_out, int out_size) {
    const float* emb   = (const float*)d_in[0];
    const void*  eidx  = d_in[1];
    const float* Ws    = (const float*)d_in[2];
    const float* bs    = (const float*)d_in[3];
    const float* Wt    = (const float*)d_in[4];
    const float* bt    = (const float*)d_in[5];
    const float* Wa1   = (const float*)d_in[6];
    const float* ba1   = (const float*)d_in[7];
    const float* Wa2   = (const float*)d_in[8];
    const float* ba2   = (const float*)d_in[9];
    const float* We    = (const float*)d_in[10];
    const float* be    = (const float*)d_in[11];
    const float* gamma = (const float*)d_in[12];
    const float* beta  = (const float*)d_in[13];
    float* out = (float*)d_out;

    cudaFuncSetAttribute(fused_kernel, cudaFuncAttributeMaxDynamicSharedMemorySize, SMEM_BYTES);

    detect_idx_kernel<<<1, 32>>>((const int*)eidx);
    precompute_W_kernel<<<(256 * NCOL + 255) / 256, 256>>>(Ws, Wt, Wa1, We);
    precompute_c_kernel<<<2, 256>>>(Wa1, We, bs, bt, ba1);
    convert_W_kernel<<<(4 * 384 * 64 + 255) / 256, 256>>>();
    fused_kernel<<<NTILES, 256, SMEM_BYTES>>>(emb, eidx, Wa2, ba2, be, gamma, beta, out);
}

// round 9
// speedup vs baseline: 2.8095x; 1.1900x over previous
#include <cuda_runtime.h>
#include <cuda_bf16.h>
#include <math.h>
#include <stdint.h>

#define E_TOTAL 500000
#define TM 64
#define NTILES ((E_TOTAL + TM - 1) / TM)   // 7813
#define NCOL 384
#define CDIM 128

// fused fp32 weights (logical cols: 0..127 attn-u, 128..255 GeGLU-x, 256..383 gate)
__device__ float g_W[256 * NCOL];
__device__ float g_c[NCOL];
__device__ int   g_idx64;
// bf16 hi/lo of reordered W^T, pair-packed + swizzled, in 8 K32 chunks:
// [chunk c][prod hi/lo][24576 B]; element (p,k): r=p>>1, h=p&1,
// off = r*128 + (((h<<6)|(k*2)) ^ ((r&7)<<4)).
__device__ __align__(16) char g_Wdb[8 * 2 * 24576];

// ---------------------------------------------------------------------------
__device__ __forceinline__ uint32_t smem_u32(const void* p) {
    uint32_t a;
    asm("{ .reg .u64 t; cvta.to.shared.u64 t, %1; cvt.u32.u64 %0, t; }" : "=r"(a) : "l"(p));
    return a;
}
#define LDMX4(arr, addr) \
    asm volatile("ldmatrix.sync.aligned.m8n8.x4.shared.b16 {%0,%1,%2,%3}, [%4];" \
        : "=r"((arr)[0]), "=r"((arr)[1]), "=r"((arr)[2]), "=r"((arr)[3]) : "r"(addr))
#define MMA_BF16(d, a, b0, b1) \
    asm volatile("mma.sync.aligned.m16n8k16.row.col.f32.bf16.bf16.f32 " \
        "{%0,%1,%2,%3}, {%4,%5,%6,%7}, {%8,%9}, {%0,%1,%2,%3};" \
        : "+f"((d)[0]), "+f"((d)[1]), "+f"((d)[2]), "+f"((d)[3]) \
        : "r"((a)[0]), "r"((a)[1]), "r"((a)[2]), "r"((a)[3]), "r"(b0), "r"(b1))
#define CP_ASYNC16(dst, src) \
    asm volatile("cp.async.cg.shared.global [%0], [%1], 16;" :: "r"(dst), "l"(src) : "memory")
#define CP_COMMIT() asm volatile("cp.async.commit_group;" ::: "memory")
#define CP_WAIT1()  asm volatile("cp.async.wait_group 1;" ::: "memory")
#define CP_WAIT0()  asm volatile("cp.async.wait_group 0;" ::: "memory")

// smem byte offsets
#define OFF_A    0u        // 65536: [kc4][prod2][64 rows x 128B swizzled]
#define OFF_B    65536u    // 98304: 2 bufs x [prod2][24576]
#define OFF_C    163840u   // 384 f
#define OFF_WA2  165376u   // 128 f
#define OFF_BE   165888u   // 256 f
#define OFF_GA   166912u   // 128 f
#define OFF_BT   167424u   // 128 f
#define OFF_SRC  167936u   // 64 i
#define OFF_TGT  168192u   // 64 i
#define OFF_P    168448u   // 4x64 f
#define OFF_S1   169472u   // 4x64 f
#define OFF_S2   170496u   // 4x64 f
#define OFF_ATT  171520u   // 64 f
#define OFF_MU   171776u   // 64 f
#define OFF_RS   172032u   // 64 f
#define SMEM_BYTES 172288

// ---------------------------------------------------------------------------
__global__ void detect_idx_kernel(const int* __restrict__ idx32) {
    if (threadIdx.x == 0) {
        int nz = 0;
        for (int i = 0; i < 256; i++) nz |= idx32[2 * i + 1];
        g_idx64 = (nz == 0) ? 1 : 0;
    }
}

__global__ void precompute_W_kernel(const float* __restrict__ Ws, const float* __restrict__ Wt,
                                    const float* __restrict__ Wa1, const float* __restrict__ We) {
    int t = blockIdx.x * blockDim.x + threadIdx.x;
    if (t >= 256 * NCOL) return;
    int k = t / NCOL;
    int j = t % NCOL;
    const float* arow = (k < 128) ? (Ws + k * 128) : (Wt + (k - 128) * 128);
    const int off = (k < 128) ? 0 : 128;
    float sum = 0.f;
    if (j < 128) {
        const float* bcol = Wa1 + off * 128 + j;
        #pragma unroll 4
        for (int m = 0; m < 128; m++) sum = fmaf(arow[m], bcol[m * 128], sum);
    } else {
        const float* bcol = We + off * 256 + (j - 128);
        #pragma unroll 4
        for (int m = 0; m < 128; m++) sum = fmaf(arow[m], bcol[m * 256], sum);
    }
    g_W[k * NCOL + j] = sum;
}

__global__ void precompute_c_kernel(const float* __restrict__ Wa1, const float* __restrict__ We,
                                    const float* __restrict__ bs, const float* __restrict__ bt,
                                    const float* __restrict__ ba1) {
    int j = blockIdx.x * blockDim.x + threadIdx.x;
    if (j >= NCOL) return;
    float s;
    if (j < 128) {
        s = ba1[j];
        for (int m = 0; m < 128; m++)
            s += bs[m] * Wa1[m * 128 + j] + bt[m] * Wa1[(128 + m) * 128 + j];
    } else {
        const int jj = j - 128;
        s = 0.f;
        for (int m = 0; m < 128; m++)
            s += bs[m] * We[m * 256 + jj] + bt[m] * We[(128 + m) * 256 + jj];
    }
    g_c[j] = s;
}

// col reorder (4 col-groups of 96: u32|x32|gate32), hi/lo split, pair-pack + swizzle
__global__ void convert_W_kernel() {
    int t = blockIdx.x * blockDim.x + threadIdx.x;
    if (t >= 8 * 384 * 32) return;
    const int c = t / (384 * 32);
    const int rem = t % (384 * 32);
    const int p = rem / 32;      // physical B row (output col)
    const int k = rem % 32;      // k within K32 chunk
    const int g = p / 96, q = p % 96;
    int L;
    if (q < 32)      L = 32 * g + q;                // u
    else if (q < 64) L = 128 + 32 * g + (q - 32);   // x
    else             L = 256 + 32 * g + (q - 64);   // gate
    const float v = g_W[(c * 32 + k) * NCOL + L];
    const __nv_bfloat16 hi = __float2bfloat16(v);
    const __nv_bfloat16 lo = __float2bfloat16(v - __bfloat162float(hi));
    const int r = p >> 1, h = p & 1;
    const int off = r * 128 + ((((h << 6) | (k * 2))) ^ ((r & 7) << 4));
    *(__nv_bfloat16*)(g_Wdb + c * 49152 + off) = hi;
    *(__nv_bfloat16*)(g_Wdb + c * 49152 + 24576 + off) = lo;
}

// ---------------------------------------------------------------------------
__device__ __forceinline__ void split2(float a, float b, unsigned& h, unsigned& l) {
    __nv_bfloat16 ha = __float2bfloat16(a), hb = __float2bfloat16(b);
    float ra = a - __bfloat162float(ha);
    float rb = b - __bfloat162float(hb);
    __nv_bfloat16 la = __float2bfloat16(ra), lb = __float2bfloat16(rb);
    h = (unsigned)__bfloat16_as_ushort(ha) | ((unsigned)__bfloat16_as_ushort(hb) << 16);
    l = (unsigned)__bfloat16_as_ushort(la) | ((unsigned)__bfloat16_as_ushort(lb) << 16);
}

// ---------------------------------------------------------------------------
// One CTA per 64-edge tile, 256 threads = 2 rowg x 4 colg warps; warp =
// 32 rows x 96 cols (2x12 m16n8 tiles). bf16 3-product hi/lo split with
// fragment reuse; weights cp.async double-buffered in 8 K32 chunks; A
// gathered/split once up-front. Fused attn + GeGLU + LayerNorm epilogue.
// ---------------------------------------------------------------------------
__global__ void __launch_bounds__(256, 1) fused_kernel(
    const float* __restrict__ emb, const void* __restrict__ eidx,
    const float* __restrict__ Wa2, const float* __restrict__ ba2,
    const float* __restrict__ be, const float* __restrict__ gamma,
    const float* __restrict__ beta, float* __restrict__ out)
{
    extern __shared__ char smem[];
    const uint32_t sbase = smem_u32(smem);
    const int tid = threadIdx.x;
    const int wid = tid >> 5;
    const int lane = tid & 31;
    const int rowg = wid >> 2;     // 0..1
    const int cg   = wid & 3;      // 0..3

    float* sC   = (float*)(smem + OFF_C);
    float* sWa2 = (float*)(smem + OFF_WA2);
    float* sBe  = (float*)(smem + OFF_BE);
    float* sGa  = (float*)(smem + OFF_GA);
    float* sBt  = (float*)(smem + OFF_BT);
    float* sP   = (float*)(smem + OFF_P);
    float* sS1  = (float*)(smem + OFF_S1);
    float* sS2  = (float*)(smem + OFF_S2);
    float* sAtt = (float*)(smem + OFF_ATT);
    float* sMu  = (float*)(smem + OFF_MU);
    float* sRs  = (float*)(smem + OFF_RS);
    int*   sSrc = (int*)(smem + OFF_SRC);
    int*   sTgt = (int*)(smem + OFF_TGT);

    if (tid < 128) { sWa2[tid] = Wa2[tid]; sGa[tid] = gamma[tid]; sBt[tid] = beta[tid]; }
    sBe[tid] = be[tid];
    for (int i = tid; i < NCOL; i += 256) sC[i] = g_c[i];

    const int e0 = blockIdx.x * TM;
    const int cnt = min(TM, E_TOTAL - e0);
    if (tid < TM) {
        int s = 0, t = 0;
        if (tid < cnt) {
            if (g_idx64) {
                const long long* p = (const long long*)eidx;
                s = (int)p[e0 + tid]; t = (int)p[E_TOTAL + e0 + tid];
            } else {
                const int* p = (const int*)eidx;
                s = p[e0 + tid]; t = p[E_TOTAL + e0 + tid];
            }
        }
        sSrc[tid] = s; sTgt[tid] = t;
    }

    // kick off weight chunk 0 while we gather A
    {
        const char* src = g_Wdb;
        const uint32_t dst = sbase + OFF_B;
        #pragma unroll
        for (int it = 0; it < 12; it++)
            CP_ASYNC16(dst + tid * 16 + it * 4096, src + tid * 16 + it * 4096);
        CP_COMMIT();
    }
    __syncthreads();   // sSrc/sTgt visible

    // gather + split A: all 4 K64 chunks, hi/lo, swizzled rows of 128B
    {
        const int r_g = tid >> 2, qt = tid & 3;
        const uint32_t rs = (uint32_t)(r_g & 7) << 4;
        #pragma unroll
        for (int kc = 0; kc < 4; kc++) {
            const int node = (kc < 2) ? sSrc[r_g] : sTgt[r_g];
            const float4* src = (const float4*)(emb + (size_t)node * CDIM + (kc & 1) * 64 + qt * 16);
            const float4 v0 = src[0], v1 = src[1], v2 = src[2], v3 = src[3];
            uint4 H0, L0, H1, L1;
            split2(v0.x, v0.y, H0.x, L0.x);
            split2(v0.z, v0.w, H0.y, L0.y);
            split2(v1.x, v1.y, H0.z, L0.z);
            split2(v1.z, v1.w, H0.w, L0.w);
            split2(v2.x, v2.y, H1.x, L1.x);
            split2(v2.z, v2.w, H1.y, L1.y);
            split2(v3.x, v3.y, H1.z, L1.z);
            split2(v3.z, v3.w, H1.w, L1.w);
            const uint32_t base = OFF_A + kc * 16384 + r_g * 128;
            const uint32_t s0 = base + (((uint32_t)qt * 32) ^ rs);
            const uint32_t s1 = base + (((uint32_t)qt * 32 + 16) ^ rs);
            *(uint4*)(smem + s0) = H0;
            *(uint4*)(smem + s1) = H1;
            *(uint4*)(smem + s0 + 8192) = L0;
            *(uint4*)(smem + s1 + 8192) = L1;
        }
    }

    // per-lane ldmatrix constants
    const uint32_t a_row = (uint32_t)rowg * 32 + ((lane >> 3) & 1) * 8 + (lane & 7);
    const uint32_t a_k   = (uint32_t)(lane >> 4) * 16;
    const uint32_t aconst = a_row * 128 + (a_k ^ (((uint32_t)(lane & 7)) << 4)); // +rt*2048
    const uint32_t p0  = (uint32_t)cg * 96 + (uint32_t)(lane >> 4) * 8 + (lane & 7); // +m*16
    const uint32_t r0  = p0 >> 1;
    const uint32_t h0  = p0 & 1;
    const uint32_t b_k = ((lane >> 3) & 1) * 16;
    const uint32_t bconst = r0 * 128 + (((h0 << 6) ^ ((r0 & 7) << 4)) ^ b_k);    // +m*1024, ^s*32
    const uint32_t aB = sbase + OFF_A;
    const uint32_t bB = sbase + OFF_B;

    float acc[2][12][4];
    #pragma unroll
    for (int rt = 0; rt < 2; rt++)
        #pragma unroll
        for (int j = 0; j < 12; j++)
            #pragma unroll
            for (int q = 0; q < 4; q++) acc[rt][j][q] = 0.f;

    #pragma unroll 1
    for (int c = 0; c < 8; c++) {
        const uint32_t bufB = bB + (uint32_t)(c & 1) * 49152;
        if (c < 7) {
            const char* src = g_Wdb + (c + 1) * 49152;
            const uint32_t dst = bB + (uint32_t)((c + 1) & 1) * 49152;
            #pragma unroll
            for (int it = 0; it < 12; it++)
                CP_ASYNC16(dst + tid * 16 + it * 4096, src + tid * 16 + it * 4096);
            CP_COMMIT();
            CP_WAIT1();
        } else {
            CP_WAIT0();
        }
        __syncthreads();

        const uint32_t kcA = aB + (uint32_t)(c >> 1) * 16384;
        const uint32_t kx0 = (uint32_t)(c & 1) * 64;
        #pragma unroll
        for (int s = 0; s < 2; s++) {
            const uint32_t akx = kx0 + (uint32_t)s * 32;
            uint32_t Ah[2][4], Al[2][4];
            #pragma unroll
            for (int rt = 0; rt < 2; rt++) {
                LDMX4(Ah[rt], kcA + (uint32_t)rt * 2048 + (aconst ^ akx));
                LDMX4(Al[rt], kcA + 8192 + (uint32_t)rt * 2048 + (aconst ^ akx));
            }
            #pragma unroll
            for (int half = 0; half < 2; half++) {
                uint32_t Bh[3][4], Bl[3][4];
                #pragma unroll
                for (int mi = 0; mi < 3; mi++) {
                    const int m = half * 3 + mi;
                    const uint32_t addr = bufB + ((bconst + (uint32_t)m * 1024) ^ ((uint32_t)s * 32));
                    LDMX4(Bh[mi], addr);
                    LDMX4(Bl[mi], addr + 24576);
                }
                #pragma unroll
                for (int rt = 0; rt < 2; rt++)
                    #pragma unroll
                    for (int mi = 0; mi < 3; mi++) {
                        const int jj = half * 6 + mi * 2;
                        MMA_BF16(acc[rt][jj],     Ah[rt], Bh[mi][0], Bh[mi][1]);
                        MMA_BF16(acc[rt][jj + 1], Ah[rt], Bh[mi][2], Bh[mi][3]);
                        MMA_BF16(acc[rt][jj],     Ah[rt], Bl[mi][0], Bl[mi][1]);
                        MMA_BF16(acc[rt][jj + 1], Ah[rt], Bl[mi][2], Bl[mi][3]);
                        MMA_BF16(acc[rt][jj],     Al[rt], Bh[mi][0], Bh[mi][1]);
                        MMA_BF16(acc[rt][jj + 1], Al[rt], Bh[mi][2], Bh[mi][3]);
                    }
            }
        }
        __syncthreads();
    }

    // ---- epilogue ----
    const int rl = rowg * 32 + (lane >> 2);   // + rt*16 + h*8
    const int ql = lane & 3;
    const float ba2v = ba2[0];

    // attention partials over this warp's 8 u-cols
    float part[2][2] = {{0.f, 0.f}, {0.f, 0.f}};
    #pragma unroll
    for (int rt = 0; rt < 2; rt++)
        #pragma unroll
        for (int j = 0; j < 4; j++)
            #pragma unroll
            for (int q = 0; q < 2; q++) {
                const int uc = cg * 32 + j * 8 + ql * 2 + q;
                const float cu = sC[uc], wv = sWa2[uc];
                part[rt][0] = fmaf(fmaxf(acc[rt][j][q]     + cu, 0.f), wv, part[rt][0]);
                part[rt][1] = fmaf(fmaxf(acc[rt][j][2 + q] + cu, 0.f), wv, part[rt][1]);
            }
    #pragma unroll
    for (int rt = 0; rt < 2; rt++)
        #pragma unroll
        for (int h = 0; h < 2; h++) {
            part[rt][h] += __shfl_xor_sync(0xffffffffu, part[rt][h], 1);
            part[rt][h] += __shfl_xor_sync(0xffffffffu, part[rt][h], 2);
        }
    if (ql == 0) {
        #pragma unroll
        for (int rt = 0; rt < 2; rt++)
            #pragma unroll
            for (int h = 0; h < 2; h++)
                sP[cg * 64 + rl + rt * 16 + h * 8] = part[rt][h];
    }
    __syncthreads();
    if (tid < 64) {
        const float s = sP[tid] + sP[64 + tid] + sP[128 + tid] + sP[192 + tid] + ba2v;
        sAtt[tid] = 1.f / (1.f + expf(-s));
    }
    __syncthreads();

    // GeGLU (x tiles 4..7 pair gate tiles 8..11) + LN partials
    float gvv[2][2][8];
    float s1[2][2] = {{0.f, 0.f}, {0.f, 0.f}};
    float s2[2][2] = {{0.f, 0.f}, {0.f, 0.f}};
    #pragma unroll
    for (int rt = 0; rt < 2; rt++)
        #pragma unroll
        for (int h = 0; h < 2; h++) {
            const float at = sAtt[rl + rt * 16 + h * 8];
            #pragma unroll
            for (int j = 0; j < 4; j++)
                #pragma unroll
                for (int q = 0; q < 2; q++) {
                    const int m = cg * 32 + j * 8 + ql * 2 + q;
                    const float zx = fmaf(at, acc[rt][4 + j][2 * h + q] + sC[128 + m], sBe[m]);
                    const float zg = fmaf(at, acc[rt][8 + j][2 * h + q] + sC[256 + m], sBe[128 + m]);
                    const float gel = 0.5f * zg * (1.f + erff(zg * 0.70710678118654752f));
                    const float v = zx * gel;
                    gvv[rt][h][j * 2 + q] = v;
                    s1[rt][h] += v;
                    s2[rt][h] = fmaf(v, v, s2[rt][h]);
                }
        }
    #pragma unroll
    for (int rt = 0; rt < 2; rt++)
        #pragma unroll
        for (int h = 0; h < 2; h++) {
            s1[rt][h] += __shfl_xor_sync(0xffffffffu, s1[rt][h], 1);
            s1[rt][h] += __shfl_xor_sync(0xffffffffu, s1[rt][h], 2);
            s2[rt][h] += __shfl_xor_sync(0xffffffffu, s2[rt][h], 1);
            s2[rt][h] += __shfl_xor_sync(0xffffffffu, s2[rt][h], 2);
        }
    if (ql == 0) {
        #pragma unroll
        for (int rt = 0; rt < 2; rt++)
            #pragma unroll
            for (int h = 0; h < 2; h++) {
                sS1[cg * 64 + rl + rt * 16 + h * 8] = s1[rt][h];
                sS2[cg * 64 + rl + rt * 16 + h * 8] = s2[rt][h];
            }
    }
    __syncthreads();
    if (tid < 64) {
        const float S1 = sS1[tid] + sS1[64 + tid] + sS1[128 + tid] + sS1[192 + tid];
        const float S2 = sS2[tid] + sS2[64 + tid] + sS2[128 + tid] + sS2[192 + tid];
        const float mu = S1 * (1.f / 128.f);
        const float var = S2 * (1.f / 128.f) - mu * mu;
        sMu[tid] = mu;
        sRs[tid] = rsqrtf(var + 1e-5f);
    }
    __syncthreads();

    #pragma unroll
    for (int rt = 0; rt < 2; rt++)
        #pragma unroll
        for (int h = 0; h < 2; h++) {
            const int r = rl + rt * 16 + h * 8;
            if (r < cnt) {
                const float mu = sMu[r], rs = sRs[r];
                float* orow = out + (size_t)(e0 + r) * CDIM;
                #pragma unroll
                for (int j = 0; j < 4; j++) {
                    const int m = cg * 32 + j * 8 + ql * 2;
                    float2 o;
                    o.x = (gvv[rt][h][j * 2]     - mu) * rs * sGa[m]     + sBt[m];
                    o.y = (gvv[rt][h][j * 2 + 1] - mu) * rs * sGa[m + 1] + sBt[m + 1];
                    *(float2*)(orow + m) = o;
                }
            }
        }
}

// ---------------------------------------------------------------------------
extern "C" void kernel_launch(void* const* d_in, const int* in_sizes, int n_in,
                              void* d_out, int out_size) {
    const float* emb   = (const float*)d_in[0];
    const void*  eidx  = d_in[1];
    const float* Ws    = (const float*)d_in[2];
    const float* bs    = (const float*)d_in[3];
    const float* Wt    = (const float*)d_in[4];
    const float* bt    = (const float*)d_in[5];
    const float* Wa1   = (const float*)d_in[6];
    const float* ba1   = (const float*)d_in[7];
    const float* Wa2   = (const float*)d_in[8];
    const float* ba2   = (const float*)d_in[9];
    const float* We    = (const float*)d_in[10];
    const float* be    = (const float*)d_in[11];
    const float* gamma = (const float*)d_in[12];
    const float* beta  = (const float*)d_in[13];
    float* out = (float*)d_out;

    cudaFuncSetAttribute(fused_kernel, cudaFuncAttributeMaxDynamicSharedMemorySize, SMEM_BYTES);

    detect_idx_kernel<<<1, 32>>>((const int*)eidx);
    precompute_W_kernel<<<(256 * NCOL + 255) / 256, 256>>>(Ws, Wt, Wa1, We);
    precompute_c_kernel<<<2, 256>>>(Wa1, We, bs, bt, ba1);
    convert_W_kernel<<<(8 * 384 * 32 + 255) / 256, 256>>>();
    fused_kernel<<<NTILES, 256, SMEM_BYTES>>>(emb, eidx, Wa2, ba2, be, gamma, beta, out);
}

// round 10
// speedup vs baseline: 2.8293x; 1.0070x over previous
#include <cuda_runtime.h>
#include <cuda_bf16.h>
#include <math.h>
#include <stdint.h>

#define E_TOTAL 500000
#define TM 64
#define NTILES ((E_TOTAL + TM - 1) / TM)   // 7813
#define NCOL 384
#define CDIM 128

// fused fp32 weights (logical cols: 0..127 attn-u, 128..255 GeGLU-x, 256..383 gate)
__device__ float g_W[256 * NCOL];
__device__ float g_c[NCOL];
__device__ int   g_idx64;
// bf16 hi/lo of reordered W^T, pair-packed + swizzled, 8 K32 chunks:
// [chunk][hi 24576 | lo 24576]; element (p,k): r=p>>1, h=p&1,
// off = r*128 + (((h<<6)|(k*2)) ^ ((r&7)<<4)).
// col reorder: 8 groups of 48 = 16u|16x|16gate.
__device__ __align__(16) char g_Wdb[8 * 2 * 24576];

// ---------------------------------------------------------------------------
__device__ __forceinline__ uint32_t smem_u32(const void* p) {
    uint32_t a;
    asm("{ .reg .u64 t; cvta.to.shared.u64 t, %1; cvt.u32.u64 %0, t; }" : "=r"(a) : "l"(p));
    return a;
}
#define LDMX4(arr, addr) \
    asm volatile("ldmatrix.sync.aligned.m8n8.x4.shared.b16 {%0,%1,%2,%3}, [%4];" \
        : "=r"((arr)[0]), "=r"((arr)[1]), "=r"((arr)[2]), "=r"((arr)[3]) : "r"(addr))
#define MMA_BF16(d, a, b0, b1) \
    asm volatile("mma.sync.aligned.m16n8k16.row.col.f32.bf16.bf16.f32 " \
        "{%0,%1,%2,%3}, {%4,%5,%6,%7}, {%8,%9}, {%0,%1,%2,%3};" \
        : "+f"((d)[0]), "+f"((d)[1]), "+f"((d)[2]), "+f"((d)[3]) \
        : "r"((a)[0]), "r"((a)[1]), "r"((a)[2]), "r"((a)[3]), "r"(b0), "r"(b1))
#define CP_ASYNC16(dst, src) \
    asm volatile("cp.async.cg.shared.global [%0], [%1], 16;" :: "r"(dst), "l"(src) : "memory")
#define CP_COMMIT() asm volatile("cp.async.commit_group;" ::: "memory")
#define CP_WAIT1()  asm volatile("cp.async.wait_group 1;" ::: "memory")
#define CP_WAIT0()  asm volatile("cp.async.wait_group 0;" ::: "memory")

// smem byte offsets
#define OFF_A    0u        // 65536: [kc4][hi 8192 | lo 8192] (64 rows x 128B swizzled)
#define OFF_B    65536u    // 98304: 2 bufs x [hi 24576 | lo 24576]
#define OFF_C    163840u   // 384 f
#define OFF_WA2  165376u   // 128 f
#define OFF_BE   165888u   // 256 f
#define OFF_GA   166912u   // 128 f
#define OFF_BT   167424u   // 128 f
#define OFF_SRC  167936u   // 64 i
#define OFF_TGT  168192u   // 64 i
#define OFF_P    168448u   // 8x64 f
#define OFF_S1   170496u   // 8x64 f
#define OFF_S2   172544u   // 8x64 f
#define OFF_ATT  174592u   // 64 f
#define OFF_MU   174848u   // 64 f
#define OFF_RS   175104u   // 64 f
#define SMEM_BYTES 175360

// ---------------------------------------------------------------------------
__global__ void detect_idx_kernel(const int* __restrict__ idx32) {
    if (threadIdx.x == 0) {
        int nz = 0;
        for (int i = 0; i < 256; i++) nz |= idx32[2 * i + 1];
        g_idx64 = (nz == 0) ? 1 : 0;
    }
}

__global__ void precompute_W_kernel(const float* __restrict__ Ws, const float* __restrict__ Wt,
                                    const float* __restrict__ Wa1, const float* __restrict__ We) {
    int t = blockIdx.x * blockDim.x + threadIdx.x;
    if (t >= 256 * NCOL) return;
    int k = t / NCOL;
    int j = t % NCOL;
    const float* arow = (k < 128) ? (Ws + k * 128) : (Wt + (k - 128) * 128);
    const int off = (k < 128) ? 0 : 128;
    float sum = 0.f;
    if (j < 128) {
        const float* bcol = Wa1 + off * 128 + j;
        #pragma unroll 4
        for (int m = 0; m < 128; m++) sum = fmaf(arow[m], bcol[m * 128], sum);
    } else {
        const float* bcol = We + off * 256 + (j - 128);
        #pragma unroll 4
        for (int m = 0; m < 128; m++) sum = fmaf(arow[m], bcol[m * 256], sum);
    }
    g_W[k * NCOL + j] = sum;
}

__global__ void precompute_c_kernel(const float* __restrict__ Wa1, const float* __restrict__ We,
                                    const float* __restrict__ bs, const float* __restrict__ bt,
                                    const float* __restrict__ ba1) {
    int j = blockIdx.x * blockDim.x + threadIdx.x;
    if (j >= NCOL) return;
    float s;
    if (j < 128) {
        s = ba1[j];
        for (int m = 0; m < 128; m++)
            s += bs[m] * Wa1[m * 128 + j] + bt[m] * Wa1[(128 + m) * 128 + j];
    } else {
        const int jj = j - 128;
        s = 0.f;
        for (int m = 0; m < 128; m++)
            s += bs[m] * We[m * 256 + jj] + bt[m] * We[(128 + m) * 256 + jj];
    }
    g_c[j] = s;
}

// col reorder (8 groups of 48 = 16u|16x|16gate), hi/lo split, pair-pack + swizzle
__global__ void convert_W_kernel() {
    int t = blockIdx.x * blockDim.x + threadIdx.x;
    if (t >= 8 * 384 * 32) return;
    const int c = t / (384 * 32);
    const int rem = t % (384 * 32);
    const int p = rem / 32;      // physical B row (output col)
    const int k = rem % 32;      // k within K32 chunk
    const int g = p / 48, q = p % 48;
    int L;
    if (q < 16)      L = 16 * g + q;                // u
    else if (q < 32) L = 128 + 16 * g + (q - 16);   // x
    else             L = 256 + 16 * g + (q - 32);   // gate
    const float v = g_W[(c * 32 + k) * NCOL + L];
    const __nv_bfloat16 hi = __float2bfloat16(v);
    const __nv_bfloat16 lo = __float2bfloat16(v - __bfloat162float(hi));
    const int r = p >> 1, h = p & 1;
    const int off = r * 128 + ((((h << 6) | (k * 2))) ^ ((r & 7) << 4));
    *(__nv_bfloat16*)(g_Wdb + c * 49152 + off) = hi;
    *(__nv_bfloat16*)(g_Wdb + c * 49152 + 24576 + off) = lo;
}

// ---------------------------------------------------------------------------
__device__ __forceinline__ void split2(float a, float b, unsigned& h, unsigned& l) {
    __nv_bfloat16 ha = __float2bfloat16(a), hb = __float2bfloat16(b);
    float ra = a - __bfloat162float(ha);
    float rb = b - __bfloat162float(hb);
    __nv_bfloat16 la = __float2bfloat16(ra), lb = __float2bfloat16(rb);
    h = (unsigned)__bfloat16_as_ushort(ha) | ((unsigned)__bfloat16_as_ushort(hb) << 16);
    l = (unsigned)__bfloat16_as_ushort(la) | ((unsigned)__bfloat16_as_ushort(lb) << 16);
}

// ---------------------------------------------------------------------------
// One CTA per 64-edge tile, 512 threads = 2 rowg x 8 cg warps; warp =
// 32 rows x 48 cols (2rt x 6 n8 tiles: 2u,2x,2gate). bf16 3-product split
// with fragment reuse; weights cp.async double-buffered (8 K32 chunks);
// A gathered/split once up-front. Balanced fused epilogue.
// ---------------------------------------------------------------------------
__global__ void __launch_bounds__(512, 1) fused_kernel(
    const float* __restrict__ emb, const void* __restrict__ eidx,
    const float* __restrict__ Wa2, const float* __restrict__ ba2,
    const float* __restrict__ be, const float* __restrict__ gamma,
    const float* __restrict__ beta, float* __restrict__ out)
{
    extern __shared__ char smem[];
    const uint32_t sbase = smem_u32(smem);
    const int tid = threadIdx.x;
    const int wid = tid >> 5;
    const int lane = tid & 31;
    const int rowg = wid >> 3;     // 0..1
    const int cg   = wid & 7;      // 0..7

    float* sC   = (float*)(smem + OFF_C);
    float* sWa2 = (float*)(smem + OFF_WA2);
    float* sBe  = (float*)(smem + OFF_BE);
    float* sGa  = (float*)(smem + OFF_GA);
    float* sBt  = (float*)(smem + OFF_BT);
    float* sP   = (float*)(smem + OFF_P);
    float* sS1  = (float*)(smem + OFF_S1);
    float* sS2  = (float*)(smem + OFF_S2);
    float* sAtt = (float*)(smem + OFF_ATT);
    float* sMu  = (float*)(smem + OFF_MU);
    float* sRs  = (float*)(smem + OFF_RS);
    int*   sSrc = (int*)(smem + OFF_SRC);
    int*   sTgt = (int*)(smem + OFF_TGT);

    if (tid < 128) { sWa2[tid] = Wa2[tid]; sGa[tid] = gamma[tid]; sBt[tid] = beta[tid]; }
    if (tid < 256) sBe[tid] = be[tid];
    if (tid < 384) sC[tid] = g_c[tid];

    const int e0 = blockIdx.x * TM;
    const int cnt = min(TM, E_TOTAL - e0);
    if (tid < TM) {
        int s = 0, t = 0;
        if (tid < cnt) {
            if (g_idx64) {
                const long long* p = (const long long*)eidx;
                s = (int)p[e0 + tid]; t = (int)p[E_TOTAL + e0 + tid];
            } else {
                const int* p = (const int*)eidx;
                s = p[e0 + tid]; t = p[E_TOTAL + e0 + tid];
            }
        }
        sSrc[tid] = s; sTgt[tid] = t;
    }

    // kick off weight chunk 0 while we gather A
    {
        const char* src = g_Wdb;
        const uint32_t dst = sbase + OFF_B;
        #pragma unroll
        for (int it = 0; it < 6; it++)
            CP_ASYNC16(dst + tid * 16 + it * 8192, src + tid * 16 + it * 8192);
        CP_COMMIT();
    }
    __syncthreads();   // sSrc/sTgt visible

    // gather + split A: all 4 K64 chunks, hi/lo, swizzled rows of 128B
    if (tid < 256) {
        const int r_g = tid >> 2, qt = tid & 3;
        const uint32_t rs = (uint32_t)(r_g & 7) << 4;
        #pragma unroll
        for (int kc = 0; kc < 4; kc++) {
            const int node = (kc < 2) ? sSrc[r_g] : sTgt[r_g];
            const float4* src = (const float4*)(emb + (size_t)node * CDIM + (kc & 1) * 64 + qt * 16);
            const float4 v0 = src[0], v1 = src[1], v2 = src[2], v3 = src[3];
            uint4 H0, L0, H1, L1;
            split2(v0.x, v0.y, H0.x, L0.x);
            split2(v0.z, v0.w, H0.y, L0.y);
            split2(v1.x, v1.y, H0.z, L0.z);
            split2(v1.z, v1.w, H0.w, L0.w);
            split2(v2.x, v2.y, H1.x, L1.x);
            split2(v2.z, v2.w, H1.y, L1.y);
            split2(v3.x, v3.y, H1.z, L1.z);
            split2(v3.z, v3.w, H1.w, L1.w);
            const uint32_t base = OFF_A + kc * 16384 + r_g * 128;
            const uint32_t s0 = base + (((uint32_t)qt * 32) ^ rs);
            const uint32_t s1 = base + (((uint32_t)qt * 32 + 16) ^ rs);
            *(uint4*)(smem + s0) = H0;
            *(uint4*)(smem + s1) = H1;
            *(uint4*)(smem + s0 + 8192) = L0;
            *(uint4*)(smem + s1 + 8192) = L1;
        }
    }

    // per-lane ldmatrix constants
    const uint32_t a_row = (uint32_t)rowg * 32 + ((lane >> 3) & 1) * 8 + (lane & 7);
    const uint32_t a_k   = (uint32_t)(lane >> 4) * 16;
    const uint32_t aconst = a_row * 128 + (a_k ^ (((uint32_t)(lane & 7)) << 4)); // +rt*2048
    const uint32_t p0  = (uint32_t)cg * 48 + (uint32_t)(lane >> 4) * 8 + (lane & 7); // +m*16
    const uint32_t r0  = p0 >> 1;
    const uint32_t h0  = p0 & 1;
    const uint32_t b_k = ((lane >> 3) & 1) * 16;
    const uint32_t bconst = r0 * 128 + (((h0 << 6) ^ ((r0 & 7) << 4)) ^ b_k);    // +m*1024, ^s*32
    const uint32_t aB = sbase + OFF_A;
    const uint32_t bB = sbase + OFF_B;

    float acc[2][6][4];
    #pragma unroll
    for (int rt = 0; rt < 2; rt++)
        #pragma unroll
        for (int j = 0; j < 6; j++)
            #pragma unroll
            for (int q = 0; q < 4; q++) acc[rt][j][q] = 0.f;

    #pragma unroll 1
    for (int c = 0; c < 8; c++) {
        const uint32_t bufB = bB + (uint32_t)(c & 1) * 49152;
        if (c < 7) {
            const char* src = g_Wdb + (c + 1) * 49152;
            const uint32_t dst = bB + (uint32_t)((c + 1) & 1) * 49152;
            #pragma unroll
            for (int it = 0; it < 6; it++)
                CP_ASYNC16(dst + tid * 16 + it * 8192, src + tid * 16 + it * 8192);
            CP_COMMIT();
            CP_WAIT1();
        } else {
            CP_WAIT0();
        }
        __syncthreads();

        const uint32_t kcA = aB + (uint32_t)(c >> 1) * 16384;
        const uint32_t kx0 = (uint32_t)(c & 1) * 64;
        #pragma unroll
        for (int s = 0; s < 2; s++) {
            const uint32_t akx = kx0 + (uint32_t)s * 32;
            uint32_t Ah[2][4], Al[2][4];
            #pragma unroll
            for (int rt = 0; rt < 2; rt++) {
                LDMX4(Ah[rt], kcA + (uint32_t)rt * 2048 + (aconst ^ akx));
                LDMX4(Al[rt], kcA + 8192 + (uint32_t)rt * 2048 + (aconst ^ akx));
            }
            uint32_t Bh[3][4], Bl[3][4];
            #pragma unroll
            for (int mi = 0; mi < 3; mi++) {
                const uint32_t addr = bufB + ((bconst + (uint32_t)mi * 1024) ^ ((uint32_t)s * 32));
                LDMX4(Bh[mi], addr);
                LDMX4(Bl[mi], addr + 24576);
            }
            #pragma unroll
            for (int rt = 0; rt < 2; rt++)
                #pragma unroll
                for (int mi = 0; mi < 3; mi++) {
                    const int jj = mi * 2;
                    MMA_BF16(acc[rt][jj],     Ah[rt], Bh[mi][0], Bh[mi][1]);
                    MMA_BF16(acc[rt][jj + 1], Ah[rt], Bh[mi][2], Bh[mi][3]);
                    MMA_BF16(acc[rt][jj],     Ah[rt], Bl[mi][0], Bl[mi][1]);
                    MMA_BF16(acc[rt][jj + 1], Ah[rt], Bl[mi][2], Bl[mi][3]);
                    MMA_BF16(acc[rt][jj],     Al[rt], Bh[mi][0], Bh[mi][1]);
                    MMA_BF16(acc[rt][jj + 1], Al[rt], Bh[mi][2], Bh[mi][3]);
                }
        }
        __syncthreads();
    }

    // ---- epilogue ----
    const int rl = rowg * 32 + (lane >> 2);   // + rt*16 + h*8
    const int ql = lane & 3;
    const float ba2v = ba2[0];

    // attention partials: u tiles 0,1 -> cols 16*cg + j*8 + ql*2 + q
    float part[2][2] = {{0.f, 0.f}, {0.f, 0.f}};
    #pragma unroll
    for (int rt = 0; rt < 2; rt++)
        #pragma unroll
        for (int j = 0; j < 2; j++)
            #pragma unroll
            for (int q = 0; q < 2; q++) {
                const int uc = cg * 16 + j * 8 + ql * 2 + q;
                const float cu = sC[uc], wv = sWa2[uc];
                part[rt][0] = fmaf(fmaxf(acc[rt][j][q]     + cu, 0.f), wv, part[rt][0]);
                part[rt][1] = fmaf(fmaxf(acc[rt][j][2 + q] + cu, 0.f), wv, part[rt][1]);
            }
    #pragma unroll
    for (int rt = 0; rt < 2; rt++)
        #pragma unroll
        for (int h = 0; h < 2; h++) {
            part[rt][h] += __shfl_xor_sync(0xffffffffu, part[rt][h], 1);
            part[rt][h] += __shfl_xor_sync(0xffffffffu, part[rt][h], 2);
        }
    if (ql == 0) {
        #pragma unroll
        for (int rt = 0; rt < 2; rt++)
            #pragma unroll
            for (int h = 0; h < 2; h++)
                sP[cg * 64 + rl + rt * 16 + h * 8] = part[rt][h];
    }
    __syncthreads();
    if (tid < 64) {
        float s = ba2v;
        #pragma unroll
        for (int g = 0; g < 8; g++) s += sP[g * 64 + tid];
        sAtt[tid] = 1.f / (1.f + expf(-s));
    }
    __syncthreads();

    // GeGLU: x tiles 2,3 pair gate tiles 4,5 (same thread), m = 16*cg + j*8 + ql*2 + q
    float gvv[2][2][4];
    float s1[2][2] = {{0.f, 0.f}, {0.f, 0.f}};
    float s2[2][2] = {{0.f, 0.f}, {0.f, 0.f}};
    #pragma unroll
    for (int rt = 0; rt < 2; rt++)
        #pragma unroll
        for (int h = 0; h < 2; h++) {
            const float at = sAtt[rl + rt * 16 + h * 8];
            #pragma unroll
            for (int j = 0; j < 2; j++)
                #pragma unroll
                for (int q = 0; q < 2; q++) {
                    const int m = cg * 16 + j * 8 + ql * 2 + q;
                    const float zx = fmaf(at, acc[rt][2 + j][2 * h + q] + sC[128 + m], sBe[m]);
                    const float zg = fmaf(at, acc[rt][4 + j][2 * h + q] + sC[256 + m], sBe[128 + m]);
                    const float gel = 0.5f * zg * (1.f + erff(zg * 0.70710678118654752f));
                    const float v = zx * gel;
                    gvv[rt][h][j * 2 + q] = v;
                    s1[rt][h] += v;
                    s2[rt][h] = fmaf(v, v, s2[rt][h]);
                }
        }
    #pragma unroll
    for (int rt = 0; rt < 2; rt++)
        #pragma unroll
        for (int h = 0; h < 2; h++) {
            s1[rt][h] += __shfl_xor_sync(0xffffffffu, s1[rt][h], 1);
            s1[rt][h] += __shfl_xor_sync(0xffffffffu, s1[rt][h], 2);
            s2[rt][h] += __shfl_xor_sync(0xffffffffu, s2[rt][h], 1);
            s2[rt][h] += __shfl_xor_sync(0xffffffffu, s2[rt][h], 2);
        }
    if (ql == 0) {
        #pragma unroll
        for (int rt = 0; rt < 2; rt++)
            #pragma unroll
            for (int h = 0; h < 2; h++) {
                sS1[cg * 64 + rl + rt * 16 + h * 8] = s1[rt][h];
                sS2[cg * 64 + rl + rt * 16 + h * 8] = s2[rt][h];
            }
    }
    __syncthreads();
    if (tid < 64) {
        float S1 = 0.f, S2 = 0.f;
        #pragma unroll
        for (int g = 0; g < 8; g++) { S1 += sS1[g * 64 + tid]; S2 += sS2[g * 64 + tid]; }
        const float mu = S1 * (1.f / 128.f);
        const float var = S2 * (1.f / 128.f) - mu * mu;
        sMu[tid] = mu;
        sRs[tid] = rsqrtf(var + 1e-5f);
    }
    __syncthreads();

    #pragma unroll
    for (int rt = 0; rt < 2; rt++)
        #pragma unroll
        for (int h = 0; h < 2; h++) {
            const int r = rl + rt * 16 + h * 8;
            if (r < cnt) {
                const float mu = sMu[r], rs = sRs[r];
                float* orow = out + (size_t)(e0 + r) * CDIM;
                #pragma unroll
                for (int j = 0; j < 2; j++) {
                    const int m = cg * 16 + j * 8 + ql * 2;
                    float2 o;
                    o.x = (gvv[rt][h][j * 2]     - mu) * rs * sGa[m]     + sBt[m];
                    o.y = (gvv[rt][h][j * 2 + 1] - mu) * rs * sGa[m + 1] + sBt[m + 1];
                    *(float2*)(orow + m) = o;
                }
            }
        }
}

// ---------------------------------------------------------------------------
extern "C" void kernel_launch(void* const* d_in, const int* in_sizes, int n_in,
                              void* d_out, int out_size) {
    const float* emb   = (const float*)d_in[0];
    const void*  eidx  = d_in[1];
    const float* Ws    = (const float*)d_in[2];
    const float* bs    = (const float*)d_in[3];
    const float* Wt    = (const float*)d_in[4];
    const float* bt    = (const float*)d_in[5];
    const float* Wa1   = (const float*)d_in[6];
    const float* ba1   = (const float*)d_in[7];
    const float* Wa2   = (const float*)d_in[8];
    const float* ba2   = (const float*)d_in[9];
    const float* We    = (const float*)d_in[10];
    const float* be    = (const float*)d_in[11];
    const float* gamma = (const float*)d_in[12];
    const float* beta  = (const float*)d_in[13];
    float* out = (float*)d_out;

    cudaFuncSetAttribute(fused_kernel, cudaFuncAttributeMaxDynamicSharedMemorySize, SMEM_BYTES);

    detect_idx_kernel<<<1, 32>>>((const int*)eidx);
    precompute_W_kernel<<<(256 * NCOL + 255) / 256, 256>>>(Ws, Wt, Wa1, We);
    precompute_c_kernel<<<2, 256>>>(Wa1, We, bs, bt, ba1);
    convert_W_kernel<<<(8 * 384 * 32 + 255) / 256, 256>>>();
    fused_kernel<<<NTILES, 512, SMEM_BYTES>>>(emb, eidx, Wa2, ba2, be, gamma, beta, out);
}

// round 11
// speedup vs baseline: 3.5559x; 1.2568x over previous
#include <cuda_runtime.h>
#include <cuda_fp16.h>
#include <math.h>
#include <stdint.h>

#define E_TOTAL 500000
#define TM 64
#define NTILES ((E_TOTAL + TM - 1) / TM)   // 7813
#define NCOL 384
#define CDIM 128

// fused fp32 weights (logical cols: 0..127 attn-u, 128..255 GeGLU-x, 256..383 gate)
__device__ float g_W[256 * NCOL];
__device__ float g_c[NCOL];
__device__ int   g_idx64;
// f16 hi/lo of reordered W^T, pair-packed + swizzled, 8 K32 chunks:
// [chunk][hi 24576 | lo 24576]; element (p,k): r=p>>1, h=p&1,
// off = r*128 + (((h<<6)|(k*2)) ^ ((r&7)<<4)).
// col reorder: 8 groups of 48 = 16u|16x|16gate.
__device__ __align__(16) char g_Wdb[8 * 2 * 24576];

// ---------------------------------------------------------------------------
__device__ __forceinline__ uint32_t smem_u32(const void* p) {
    uint32_t a;
    asm("{ .reg .u64 t; cvta.to.shared.u64 t, %1; cvt.u32.u64 %0, t; }" : "=r"(a) : "l"(p));
    return a;
}
#define LDMX4(arr, addr) \
    asm volatile("ldmatrix.sync.aligned.m8n8.x4.shared.b16 {%0,%1,%2,%3}, [%4];" \
        : "=r"((arr)[0]), "=r"((arr)[1]), "=r"((arr)[2]), "=r"((arr)[3]) : "r"(addr))
#define MMA_F16(d, a, b0, b1) \
    asm volatile("mma.sync.aligned.m16n8k16.row.col.f32.f16.f16.f32 " \
        "{%0,%1,%2,%3}, {%4,%5,%6,%7}, {%8,%9}, {%0,%1,%2,%3};" \
        : "+f"((d)[0]), "+f"((d)[1]), "+f"((d)[2]), "+f"((d)[3]) \
        : "r"((a)[0]), "r"((a)[1]), "r"((a)[2]), "r"((a)[3]), "r"(b0), "r"(b1))
#define CP_ASYNC16(dst, src) \
    asm volatile("cp.async.cg.shared.global [%0], [%1], 16;" :: "r"(dst), "l"(src) : "memory")
#define CP_COMMIT() asm volatile("cp.async.commit_group;" ::: "memory")
#define CP_WAIT1()  asm volatile("cp.async.wait_group 1;" ::: "memory")
#define CP_WAIT0()  asm volatile("cp.async.wait_group 0;" ::: "memory")

// smem byte offsets
#define OFF_A    0u        // 32768: [kc4] 64 rows x 128B swizzled (f16)
#define OFF_B    32768u    // 98304: 2 bufs x [hi 24576 | lo 24576]
#define OFF_C    131072u   // 384 f
#define OFF_WA2  132608u   // 128 f
#define OFF_BE   133120u   // 256 f
#define OFF_GA   134144u   // 128 f
#define OFF_BT   134656u   // 128 f
#define OFF_SRC  135168u   // 64 i
#define OFF_TGT  135424u   // 64 i
#define OFF_P    135680u   // 8x64 f
#define OFF_S1   137728u   // 8x64 f
#define OFF_S2   139776u   // 8x64 f
#define OFF_ATT  141824u   // 64 f
#define OFF_MU   142080u   // 64 f
#define OFF_RS   142336u   // 64 f
#define SMEM_BYTES 142592

// ---------------------------------------------------------------------------
__global__ void detect_idx_kernel(const int* __restrict__ idx32) {
    if (threadIdx.x == 0) {
        int nz = 0;
        for (int i = 0; i < 256; i++) nz |= idx32[2 * i + 1];
        g_idx64 = (nz == 0) ? 1 : 0;
    }
}

__global__ void precompute_W_kernel(const float* __restrict__ Ws, const float* __restrict__ Wt,
                                    const float* __restrict__ Wa1, const float* __restrict__ We) {
    int t = blockIdx.x * blockDim.x + threadIdx.x;
    if (t >= 256 * NCOL) return;
    int k = t / NCOL;
    int j = t % NCOL;
    const float* arow = (k < 128) ? (Ws + k * 128) : (Wt + (k - 128) * 128);
    const int off = (k < 128) ? 0 : 128;
    float sum = 0.f;
    if (j < 128) {
        const float* bcol = Wa1 + off * 128 + j;
        #pragma unroll 4
        for (int m = 0; m < 128; m++) sum = fmaf(arow[m], bcol[m * 128], sum);
    } else {
        const float* bcol = We + off * 256 + (j - 128);
        #pragma unroll 4
        for (int m = 0; m < 128; m++) sum = fmaf(arow[m], bcol[m * 256], sum);
    }
    g_W[k * NCOL + j] = sum;
}

__global__ void precompute_c_kernel(const float* __restrict__ Wa1, const float* __restrict__ We,
                                    const float* __restrict__ bs, const float* __restrict__ bt,
                                    const float* __restrict__ ba1) {
    int j = blockIdx.x * blockDim.x + threadIdx.x;
    if (j >= NCOL) return;
    float s;
    if (j < 128) {
        s = ba1[j];
        for (int m = 0; m < 128; m++)
            s += bs[m] * Wa1[m * 128 + j] + bt[m] * Wa1[(128 + m) * 128 + j];
    } else {
        const int jj = j - 128;
        s = 0.f;
        for (int m = 0; m < 128; m++)
            s += bs[m] * We[m * 256 + jj] + bt[m] * We[(128 + m) * 256 + jj];
    }
    g_c[j] = s;
}

// col reorder (8 groups of 48 = 16u|16x|16gate), f16 hi/lo split, pair-pack + swizzle
__global__ void convert_W_kernel() {
    int t = blockIdx.x * blockDim.x + threadIdx.x;
    if (t >= 8 * 384 * 32) return;
    const int c = t / (384 * 32);
    const int rem = t % (384 * 32);
    const int p = rem / 32;      // physical B row (output col)
    const int k = rem % 32;      // k within K32 chunk
    const int g = p / 48, q = p % 48;
    int L;
    if (q < 16)      L = 16 * g + q;                // u
    else if (q < 32) L = 128 + 16 * g + (q - 16);   // x
    else             L = 256 + 16 * g + (q - 32);   // gate
    const float v = g_W[(c * 32 + k) * NCOL + L];
    const __half hi = __float2half_rn(v);
    const __half lo = __float2half_rn(v - __half2float(hi));
    const int r = p >> 1, h = p & 1;
    const int off = r * 128 + ((((h << 6) | (k * 2))) ^ ((r & 7) << 4));
    *(__half*)(g_Wdb + c * 49152 + off) = hi;
    *(__half*)(g_Wdb + c * 49152 + 24576 + off) = lo;
}

// ---------------------------------------------------------------------------
__device__ __forceinline__ unsigned pack2(float a, float b) {
    const __half2 h = __floats2half2_rn(a, b);   // a -> low half
    return *reinterpret_cast<const unsigned*>(&h);
}

// ---------------------------------------------------------------------------
// One CTA per 64-edge tile, 512 threads = 2 rowg x 8 cg warps; warp =
// 32 rows x 48 cols (2rt x 6 n8 tiles: 2u,2x,2gate). f16 2-product split:
// D = A_f16 * (Whi + Wlo), fp32 accum. Weights cp.async double-buffered
// (8 K32 chunks); A gathered once up-front. Fused attn+GeGLU+LN epilogue.
// ---------------------------------------------------------------------------
__global__ void __launch_bounds__(512, 1) fused_kernel(
    const float* __restrict__ emb, const void* __restrict__ eidx,
    const float* __restrict__ Wa2, const float* __restrict__ ba2,
    const float* __restrict__ be, const float* __restrict__ gamma,
    const float* __restrict__ beta, float* __restrict__ out)
{
    extern __shared__ char smem[];
    const uint32_t sbase = smem_u32(smem);
    const int tid = threadIdx.x;
    const int wid = tid >> 5;
    const int lane = tid & 31;
    const int rowg = wid >> 3;     // 0..1
    const int cg   = wid & 7;      // 0..7

    float* sC   = (float*)(smem + OFF_C);
    float* sWa2 = (float*)(smem + OFF_WA2);
    float* sBe  = (float*)(smem + OFF_BE);
    float* sGa  = (float*)(smem + OFF_GA);
    float* sBt  = (float*)(smem + OFF_BT);
    float* sP   = (float*)(smem + OFF_P);
    float* sS1  = (float*)(smem + OFF_S1);
    float* sS2  = (float*)(smem + OFF_S2);
    float* sAtt = (float*)(smem + OFF_ATT);
    float* sMu  = (float*)(smem + OFF_MU);
    float* sRs  = (float*)(smem + OFF_RS);
    int*   sSrc = (int*)(smem + OFF_SRC);
    int*   sTgt = (int*)(smem + OFF_TGT);

    if (tid < 128) { sWa2[tid] = Wa2[tid]; sGa[tid] = gamma[tid]; sBt[tid] = beta[tid]; }
    if (tid < 256) sBe[tid] = be[tid];
    if (tid < 384) sC[tid] = g_c[tid];

    const int e0 = blockIdx.x * TM;
    const int cnt = min(TM, E_TOTAL - e0);
    if (tid < TM) {
        int s = 0, t = 0;
        if (tid < cnt) {
            if (g_idx64) {
                const long long* p = (const long long*)eidx;
                s = (int)p[e0 + tid]; t = (int)p[E_TOTAL + e0 + tid];
            } else {
                const int* p = (const int*)eidx;
                s = p[e0 + tid]; t = p[E_TOTAL + e0 + tid];
            }
        }
        sSrc[tid] = s; sTgt[tid] = t;
    }

    // kick off weight chunk 0 while we gather A
    {
        const char* src = g_Wdb;
        const uint32_t dst = sbase + OFF_B;
        #pragma unroll
        for (int it = 0; it < 6; it++)
            CP_ASYNC16(dst + tid * 16 + it * 8192, src + tid * 16 + it * 8192);
        CP_COMMIT();
    }
    __syncthreads();   // sSrc/sTgt visible

    // gather A: all 4 K64 chunks, single f16, swizzled 128B rows
    if (tid < 256) {
        const int r_g = tid >> 2, qt = tid & 3;
        const uint32_t rs = (uint32_t)(r_g & 7) << 4;
        #pragma unroll
        for (int kc = 0; kc < 4; kc++) {
            const int node = (kc < 2) ? sSrc[r_g] : sTgt[r_g];
            const float4* src = (const float4*)(emb + (size_t)node * CDIM + (kc & 1) * 64 + qt * 16);
            const float4 v0 = src[0], v1 = src[1], v2 = src[2], v3 = src[3];
            uint4 H0, H1;
            H0.x = pack2(v0.x, v0.y); H0.y = pack2(v0.z, v0.w);
            H0.z = pack2(v1.x, v1.y); H0.w = pack2(v1.z, v1.w);
            H1.x = pack2(v2.x, v2.y); H1.y = pack2(v2.z, v2.w);
            H1.z = pack2(v3.x, v3.y); H1.w = pack2(v3.z, v3.w);
            const uint32_t base = OFF_A + kc * 8192 + r_g * 128;
            *(uint4*)(smem + base + (((uint32_t)qt * 32) ^ rs)) = H0;
            *(uint4*)(smem + base + (((uint32_t)qt * 32 + 16) ^ rs)) = H1;
        }
    }

    // per-lane ldmatrix constants
    const uint32_t a_row = (uint32_t)rowg * 32 + ((lane >> 3) & 1) * 8 + (lane & 7);
    const uint32_t a_k   = (uint32_t)(lane >> 4) * 16;
    const uint32_t aconst = a_row * 128 + (a_k ^ (((uint32_t)(lane & 7)) << 4)); // +rt*2048
    const uint32_t p0  = (uint32_t)cg * 48 + (uint32_t)(lane >> 4) * 8 + (lane & 7); // +m*16
    const uint32_t r0  = p0 >> 1;
    const uint32_t h0  = p0 & 1;
    const uint32_t b_k = ((lane >> 3) & 1) * 16;
    const uint32_t bconst = r0 * 128 + (((h0 << 6) ^ ((r0 & 7) << 4)) ^ b_k);    // +m*1024, ^s*32
    const uint32_t aB = sbase + OFF_A;
    const uint32_t bB = sbase + OFF_B;

    float acc[2][6][4];
    #pragma unroll
    for (int rt = 0; rt < 2; rt++)
        #pragma unroll
        for (int j = 0; j < 6; j++)
            #pragma unroll
            for (int q = 0; q < 4; q++) acc[rt][j][q] = 0.f;

    #pragma unroll 1
    for (int c = 0; c < 8; c++) {
        const uint32_t bufB = bB + (uint32_t)(c & 1) * 49152;
        if (c < 7) {
            const char* src = g_Wdb + (c + 1) * 49152;
            const uint32_t dst = bB + (uint32_t)((c + 1) & 1) * 49152;
            #pragma unroll
            for (int it = 0; it < 6; it++)
                CP_ASYNC16(dst + tid * 16 + it * 8192, src + tid * 16 + it * 8192);
            CP_COMMIT();
            CP_WAIT1();
        } else {
            CP_WAIT0();
        }
        __syncthreads();

        const uint32_t kcA = aB + (uint32_t)(c >> 1) * 8192;
        const uint32_t kx0 = (uint32_t)(c & 1) * 64;
        #pragma unroll
        for (int s = 0; s < 2; s++) {
            const uint32_t akx = kx0 + (uint32_t)s * 32;
            uint32_t Ah[2][4];
            #pragma unroll
            for (int rt = 0; rt < 2; rt++)
                LDMX4(Ah[rt], kcA + (uint32_t)rt * 2048 + (aconst ^ akx));
            uint32_t Bh[3][4], Bl[3][4];
            #pragma unroll
            for (int mi = 0; mi < 3; mi++) {
                const uint32_t addr = bufB + ((bconst + (uint32_t)mi * 1024) ^ ((uint32_t)s * 32));
                LDMX4(Bh[mi], addr);
                LDMX4(Bl[mi], addr + 24576);
            }
            #pragma unroll
            for (int rt = 0; rt < 2; rt++)
                #pragma unroll
                for (int mi = 0; mi < 3; mi++) {
                    const int jj = mi * 2;
                    MMA_F16(acc[rt][jj],     Ah[rt], Bh[mi][0], Bh[mi][1]);
                    MMA_F16(acc[rt][jj + 1], Ah[rt], Bh[mi][2], Bh[mi][3]);
                    MMA_F16(acc[rt][jj],     Ah[rt], Bl[mi][0], Bl[mi][1]);
                    MMA_F16(acc[rt][jj + 1], Ah[rt], Bl[mi][2], Bl[mi][3]);
                }
        }
        __syncthreads();
    }

    // ---- epilogue ----
    const int rl = rowg * 32 + (lane >> 2);   // + rt*16 + h*8
    const int ql = lane & 3;
    const float ba2v = ba2[0];

    // attention partials: u tiles 0,1 -> cols 16*cg + j*8 + ql*2 + q
    float part[2][2] = {{0.f, 0.f}, {0.f, 0.f}};
    #pragma unroll
    for (int rt = 0; rt < 2; rt++)
        #pragma unroll
        for (int j = 0; j < 2; j++)
            #pragma unroll
            for (int q = 0; q < 2; q++) {
                const int uc = cg * 16 + j * 8 + ql * 2 + q;
                const float cu = sC[uc], wv = sWa2[uc];
                part[rt][0] = fmaf(fmaxf(acc[rt][j][q]     + cu, 0.f), wv, part[rt][0]);
                part[rt][1] = fmaf(fmaxf(acc[rt][j][2 + q] + cu, 0.f), wv, part[rt][1]);
            }
    #pragma unroll
    for (int rt = 0; rt < 2; rt++)
        #pragma unroll
        for (int h = 0; h < 2; h++) {
            part[rt][h] += __shfl_xor_sync(0xffffffffu, part[rt][h], 1);
            part[rt][h] += __shfl_xor_sync(0xffffffffu, part[rt][h], 2);
        }
    if (ql == 0) {
        #pragma unroll
        for (int rt = 0; rt < 2; rt++)
            #pragma unroll
            for (int h = 0; h < 2; h++)
                sP[cg * 64 + rl + rt * 16 + h * 8] = part[rt][h];
    }
    __syncthreads();
    if (tid < 64) {
        float s = ba2v;
        #pragma unroll
        for (int g = 0; g < 8; g++) s += sP[g * 64 + tid];
        sAtt[tid] = 1.f / (1.f + expf(-s));
    }
    __syncthreads();

    // GeGLU: x tiles 2,3 pair gate tiles 4,5 (same thread)
    float gvv[2][2][4];
    float s1[2][2] = {{0.f, 0.f}, {0.f, 0.f}};
    float s2[2][2] = {{0.f, 0.f}, {0.f, 0.f}};
    #pragma unroll
    for (int rt = 0; rt < 2; rt++)
        #pragma unroll
        for (int h = 0; h < 2; h++) {
            const float at = sAtt[rl + rt * 16 + h * 8];
            #pragma unroll
            for (int j = 0; j < 2; j++)
                #pragma unroll
                for (int q = 0; q < 2; q++) {
                    const int m = cg * 16 + j * 8 + ql * 2 + q;
                    const float zx = fmaf(at, acc[rt][2 + j][2 * h + q] + sC[128 + m], sBe[m]);
                    const float zg = fmaf(at, acc[rt][4 + j][2 * h + q] + sC[256 + m], sBe[128 + m]);
                    const float gel = 0.5f * zg * (1.f + erff(zg * 0.70710678118654752f));
                    const float v = zx * gel;
                    gvv[rt][h][j * 2 + q] = v;
                    s1[rt][h] += v;
                    s2[rt][h] = fmaf(v, v, s2[rt][h]);
                }
        }
    #pragma unroll
    for (int rt = 0; rt < 2; rt++)
        #pragma unroll
        for (int h = 0; h < 2; h++) {
            s1[rt][h] += __shfl_xor_sync(0xffffffffu, s1[rt][h], 1);
            s1[rt][h] += __shfl_xor_sync(0xffffffffu, s1[rt][h], 2);
            s2[rt][h] += __shfl_xor_sync(0xffffffffu, s2[rt][h], 1);
            s2[rt][h] += __shfl_xor_sync(0xffffffffu, s2[rt][h], 2);
        }
    if (ql == 0) {
        #pragma unroll
        for (int rt = 0; rt < 2; rt++)
            #pragma unroll
            for (int h = 0; h < 2; h++) {
                sS1[cg * 64 + rl + rt * 16 + h * 8] = s1[rt][h];
                sS2[cg * 64 + rl + rt * 16 + h * 8] = s2[rt][h];
            }
    }
    __syncthreads();
    if (tid < 64) {
        float S1 = 0.f, S2 = 0.f;
        #pragma unroll
        for (int g = 0; g < 8; g++) { S1 += sS1[g * 64 + tid]; S2 += sS2[g * 64 + tid]; }
        const float mu = S1 * (1.f / 128.f);
        const float var = S2 * (1.f / 128.f) - mu * mu;
        sMu[tid] = mu;
        sRs[tid] = rsqrtf(var + 1e-5f);
    }
    __syncthreads();

    #pragma unroll
    for (int rt = 0; rt < 2; rt++)
        #pragma unroll
        for (int h = 0; h < 2; h++) {
            const int r = rl + rt * 16 + h * 8;
            if (r < cnt) {
                const float mu = sMu[r], rs = sRs[r];
                float* orow = out + (size_t)(e0 + r) * CDIM;
                #pragma unroll
                for (int j = 0; j < 2; j++) {
                    const int m = cg * 16 + j * 8 + ql * 2;
                    float2 o;
                    o.x = (gvv[rt][h][j * 2]     - mu) * rs * sGa[m]     + sBt[m];
                    o.y = (gvv[rt][h][j * 2 + 1] - mu) * rs * sGa[m + 1] + sBt[m + 1];
                    *(float2*)(orow + m) = o;
                }
            }
        }
}

// ---------------------------------------------------------------------------
extern "C" void kernel_launch(void* const* d_in, const int* in_sizes, int n_in,
                              void* d_out, int out_size) {
    const float* emb   = (const float*)d_in[0];
    const void*  eidx  = d_in[1];
    const float* Ws    = (const float*)d_in[2];
    const float* bs    = (const float*)d_in[3];
    const float* Wt    = (const float*)d_in[4];
    const float* bt    = (const float*)d_in[5];
    const float* Wa1   = (const float*)d_in[6];
    const float* ba1   = (const float*)d_in[7];
    const float* Wa2   = (const float*)d_in[8];
    const float* ba2   = (const float*)d_in[9];
    const float* We    = (const float*)d_in[10];
    const float* be    = (const float*)d_in[11];
    const float* gamma = (const float*)d_in[12];
    const float* beta  = (const float*)d_in[13];
    float* out = (float*)d_out;

    cudaFuncSetAttribute(fused_kernel, cudaFuncAttributeMaxDynamicSharedMemorySize, SMEM_BYTES);

    detect_idx_kernel<<<1, 32>>>((const int*)eidx);
    precompute_W_kernel<<<(256 * NCOL + 255) / 256, 256>>>(Ws, Wt, Wa1, We);
    precompute_c_kernel<<<2, 256>>>(Wa1, We, bs, bt, ba1);
    convert_W_kernel<<<(8 * 384 * 32 + 255) / 256, 256>>>();
    fused_kernel<<<NTILES, 512, SMEM_BYTES>>>(emb, eidx, Wa2, ba2, be, gamma, beta, out);
}

// round 12
// speedup vs baseline: 3.8625x; 1.0862x over previous
#include <cuda_runtime.h>
#include <cuda_fp16.h>
#include <math.h>
#include <stdint.h>

#define E_TOTAL 500000
#define TM 64
#define NTILES ((E_TOTAL + TM - 1) / TM)   // 7813
#define NCOL 384
#define CDIM 128

// fused fp32 weights (logical cols: 0..127 attn-u, 128..255 GeGLU-x, 256..383 gate)
__device__ float g_W[256 * NCOL];
__device__ float g_c[NCOL];
__device__ int   g_idx64;
// f16 weights, reordered + pair-packed + swizzled, 8 K32 chunks of 40960 B:
//   [hi 24576 B: all 384 cols][lo 16384 B: 256 x/gate cols]
// hi col order: 8 groups of 48 = 16u|16x|16gate; lo: 8 groups of 32 = 16x|16gate.
// element (p,k): r=p>>1, h=p&1, off = r*128 + (((h<<6)|(k*2)) ^ ((r&7)<<4)).
__device__ __align__(16) char g_Wdb[8 * 40960];

// ---------------------------------------------------------------------------
__device__ __forceinline__ uint32_t smem_u32(const void* p) {
    uint32_t a;
    asm("{ .reg .u64 t; cvta.to.shared.u64 t, %1; cvt.u32.u64 %0, t; }" : "=r"(a) : "l"(p));
    return a;
}
#define LDMX4(arr, addr) \
    asm volatile("ldmatrix.sync.aligned.m8n8.x4.shared.b16 {%0,%1,%2,%3}, [%4];" \
        : "=r"((arr)[0]), "=r"((arr)[1]), "=r"((arr)[2]), "=r"((arr)[3]) : "r"(addr))
// NOTE: non-volatile — pure register op, lets ptxas software-pipeline the HMMA chain
#define MMA_F16(d, a, b0, b1) \
    asm("mma.sync.aligned.m16n8k16.row.col.f32.f16.f16.f32 " \
        "{%0,%1,%2,%3}, {%4,%5,%6,%7}, {%8,%9}, {%0,%1,%2,%3};" \
        : "+f"((d)[0]), "+f"((d)[1]), "+f"((d)[2]), "+f"((d)[3]) \
        : "r"((a)[0]), "r"((a)[1]), "r"((a)[2]), "r"((a)[3]), "r"(b0), "r"(b1))
#define CP_ASYNC16(dst, src) \
    asm volatile("cp.async.cg.shared.global [%0], [%1], 16;" :: "r"(dst), "l"(src) : "memory")
#define CP_COMMIT() asm volatile("cp.async.commit_group;" ::: "memory")
#define CP_WAIT1()  asm volatile("cp.async.wait_group 1;" ::: "memory")
#define CP_WAIT0()  asm volatile("cp.async.wait_group 0;" ::: "memory")

// smem byte offsets
#define OFF_A    0u        // 32768: [kc4] 64 rows x 128B swizzled (f16)
#define OFF_B    32768u    // 81920: 2 bufs x [hi 24576 | lo 16384]
#define OFF_C    114688u   // 384 f
#define OFF_WA2  116224u   // 128 f
#define OFF_BE   116736u   // 256 f
#define OFF_GA   117760u   // 128 f
#define OFF_BT   118272u   // 128 f
#define OFF_SRC  118784u   // 64 i
#define OFF_TGT  119040u   // 64 i
#define OFF_P    119296u   // 8x64 f
#define OFF_S1   121344u   // 8x64 f
#define OFF_S2   123392u   // 8x64 f
#define OFF_ATT  125440u   // 64 f
#define OFF_MU   125696u   // 64 f
#define OFF_RS   125952u   // 64 f
#define SMEM_BYTES 126208

// ---------------------------------------------------------------------------
__global__ void detect_idx_kernel(const int* __restrict__ idx32) {
    if (threadIdx.x == 0) {
        int nz = 0;
        for (int i = 0; i < 256; i++) nz |= idx32[2 * i + 1];
        g_idx64 = (nz == 0) ? 1 : 0;
    }
}

__global__ void precompute_W_kernel(const float* __restrict__ Ws, const float* __restrict__ Wt,
                                    const float* __restrict__ Wa1, const float* __restrict__ We) {
    int t = blockIdx.x * blockDim.x + threadIdx.x;
    if (t >= 256 * NCOL) return;
    int k = t / NCOL;
    int j = t % NCOL;
    const float* arow = (k < 128) ? (Ws + k * 128) : (Wt + (k - 128) * 128);
    const int off = (k < 128) ? 0 : 128;
    float sum = 0.f;
    if (j < 128) {
        const float* bcol = Wa1 + off * 128 + j;
        #pragma unroll 4
        for (int m = 0; m < 128; m++) sum = fmaf(arow[m], bcol[m * 128], sum);
    } else {
        const float* bcol = We + off * 256 + (j - 128);
        #pragma unroll 4
        for (int m = 0; m < 128; m++) sum = fmaf(arow[m], bcol[m * 256], sum);
    }
    g_W[k * NCOL + j] = sum;
}

__global__ void precompute_c_kernel(const float* __restrict__ Wa1, const float* __restrict__ We,
                                    const float* __restrict__ bs, const float* __restrict__ bt,
                                    const float* __restrict__ ba1) {
    int j = blockIdx.x * blockDim.x + threadIdx.x;
    if (j >= NCOL) return;
    float s;
    if (j < 128) {
        s = ba1[j];
        for (int m = 0; m < 128; m++)
            s += bs[m] * Wa1[m * 128 + j] + bt[m] * Wa1[(128 + m) * 128 + j];
    } else {
        const int jj = j - 128;
        s = 0.f;
        for (int m = 0; m < 128; m++)
            s += bs[m] * We[m * 256 + jj] + bt[m] * We[(128 + m) * 256 + jj];
    }
    g_c[j] = s;
}

// hi: 384 cols (8 groups of 48 = 16u|16x|16gate); lo: 256 cols (8 groups of 32 = 16x|16gate)
__global__ void convert_W_kernel() {
    int t = blockIdx.x * blockDim.x + threadIdx.x;
    if (t >= 8 * 640 * 32) return;
    const int c = t / (640 * 32);
    const int rem = t % (640 * 32);
    const int pp = rem / 32;     // 0..383 hi, 384..639 lo
    const int k = rem % 32;
    if (pp < 384) {
        const int p = pp;
        const int g = p / 48, q = p % 48;
        int L;
        if (q < 16)      L = 16 * g + q;
        else if (q < 32) L = 128 + 16 * g + (q - 16);
        else             L = 256 + 16 * g + (q - 32);
        const float v = g_W[(c * 32 + k) * NCOL + L];
        const int r = p >> 1, h = p & 1;
        const int off = r * 128 + ((((h << 6) | (k * 2))) ^ ((r & 7) << 4));
        *(__half*)(g_Wdb + c * 40960 + off) = __float2half_rn(v);
    } else {
        const int p = pp - 384;  // 0..255
        const int g = p / 32, q = p % 32;
        const int L = (q < 16) ? (128 + 16 * g + q) : (256 + 16 * g + (q - 16));
        const float v = g_W[(c * 32 + k) * NCOL + L];
        const __half hi = __float2half_rn(v);
        const __half lo = __float2half_rn(v - __half2float(hi));
        const int r = p >> 1, h = p & 1;
        const int off = r * 128 + ((((h << 6) | (k * 2))) ^ ((r & 7) << 4));
        *(__half*)(g_Wdb + c * 40960 + 24576 + off) = lo;
    }
}

// ---------------------------------------------------------------------------
__device__ __forceinline__ unsigned pack2(float a, float b) {
    const __half2 h = __floats2half2_rn(a, b);
    return *reinterpret_cast<const unsigned*>(&h);
}

// ---------------------------------------------------------------------------
// One CTA per 64-edge tile, 512 threads = 2 rowg x 8 cg warps; warp =
// 32 rows x 48 cols (2rt x 6 n8 tiles: 2u,2x,2gate). f16 split:
// full cols get Whi; x/gate also get Wlo (2-product); u hi-only.
// Weights cp.async double-buffered; A gathered once. Fused epilogue.
// ---------------------------------------------------------------------------
__global__ void __launch_bounds__(512, 1) fused_kernel(
    const float* __restrict__ emb, const void* __restrict__ eidx,
    const float* __restrict__ Wa2, const float* __restrict__ ba2,
    const float* __restrict__ be, const float* __restrict__ gamma,
    const float* __restrict__ beta, float* __restrict__ out)
{
    extern __shared__ char smem[];
    const uint32_t sbase = smem_u32(smem);
    const int tid = threadIdx.x;
    const int wid = tid >> 5;
    const int lane = tid & 31;
    const int rowg = wid >> 3;     // 0..1
    const int cg   = wid & 7;      // 0..7

    float* sC   = (float*)(smem + OFF_C);
    float* sWa2 = (float*)(smem + OFF_WA2);
    float* sBe  = (float*)(smem + OFF_BE);
    float* sGa  = (float*)(smem + OFF_GA);
    float* sBt  = (float*)(smem + OFF_BT);
    float* sP   = (float*)(smem + OFF_P);
    float* sS1  = (float*)(smem + OFF_S1);
    float* sS2  = (float*)(smem + OFF_S2);
    float* sAtt = (float*)(smem + OFF_ATT);
    float* sMu  = (float*)(smem + OFF_MU);
    float* sRs  = (float*)(smem + OFF_RS);
    int*   sSrc = (int*)(smem + OFF_SRC);
    int*   sTgt = (int*)(smem + OFF_TGT);

    if (tid < 128) { sWa2[tid] = Wa2[tid]; sGa[tid] = gamma[tid]; sBt[tid] = beta[tid]; }
    if (tid < 256) sBe[tid] = be[tid];
    if (tid < 384) sC[tid] = g_c[tid];

    const int e0 = blockIdx.x * TM;
    const int cnt = min(TM, E_TOTAL - e0);
    if (tid < TM) {
        int s = 0, t = 0;
        if (tid < cnt) {
            if (g_idx64) {
                const long long* p = (const long long*)eidx;
                s = (int)p[e0 + tid]; t = (int)p[E_TOTAL + e0 + tid];
            } else {
                const int* p = (const int*)eidx;
                s = p[e0 + tid]; t = p[E_TOTAL + e0 + tid];
            }
        }
        sSrc[tid] = s; sTgt[tid] = t;
    }

    // kick off weight chunk 0 while we gather A  (40960 B = 5 x 512 x 16B)
    {
        const char* src = g_Wdb;
        const uint32_t dst = sbase + OFF_B;
        #pragma unroll
        for (int it = 0; it < 5; it++)
            CP_ASYNC16(dst + tid * 16 + it * 8192, src + tid * 16 + it * 8192);
        CP_COMMIT();
    }
    __syncthreads();   // sSrc/sTgt visible

    // gather A: all 4 K64 chunks, single f16, swizzled 128B rows
    if (tid < 256) {
        const int r_g = tid >> 2, qt = tid & 3;
        const uint32_t rs = (uint32_t)(r_g & 7) << 4;
        #pragma unroll
        for (int kc = 0; kc < 4; kc++) {
            const int node = (kc < 2) ? sSrc[r_g] : sTgt[r_g];
            const float4* src = (const float4*)(emb + (size_t)node * CDIM + (kc & 1) * 64 + qt * 16);
            const float4 v0 = src[0], v1 = src[1], v2 = src[2], v3 = src[3];
            uint4 H0, H1;
            H0.x = pack2(v0.x, v0.y); H0.y = pack2(v0.z, v0.w);
            H0.z = pack2(v1.x, v1.y); H0.w = pack2(v1.z, v1.w);
            H1.x = pack2(v2.x, v2.y); H1.y = pack2(v2.z, v2.w);
            H1.z = pack2(v3.x, v3.y); H1.w = pack2(v3.z, v3.w);
            const uint32_t base = OFF_A + kc * 8192 + r_g * 128;
            *(uint4*)(smem + base + (((uint32_t)qt * 32) ^ rs)) = H0;
            *(uint4*)(smem + base + (((uint32_t)qt * 32 + 16) ^ rs)) = H1;
        }
    }

    // per-lane ldmatrix constants
    const uint32_t a_row = (uint32_t)rowg * 32 + ((lane >> 3) & 1) * 8 + (lane & 7);
    const uint32_t a_k   = (uint32_t)(lane >> 4) * 16;
    const uint32_t aconst = a_row * 128 + (a_k ^ (((uint32_t)(lane & 7)) << 4)); // +rt*2048
    const uint32_t b_k = ((lane >> 3) & 1) * 16;
    // hi fragment base: 48 cols/group
    const uint32_t p0  = (uint32_t)cg * 48 + (uint32_t)(lane >> 4) * 8 + (lane & 7); // +mi*16
    const uint32_t r0  = p0 >> 1;
    const uint32_t h0  = p0 & 1;
    const uint32_t bconst = r0 * 128 + (((h0 << 6) ^ ((r0 & 7) << 4)) ^ b_k);    // +mi*1024, ^s*32
    // lo fragment base: 32 cols/group (x|gate)
    const uint32_t p0l = (uint32_t)cg * 32 + (uint32_t)(lane >> 4) * 8 + (lane & 7);
    const uint32_t r0l = p0l >> 1;
    const uint32_t h0l = p0l & 1;
    const uint32_t bconstl = r0l * 128 + (((h0l << 6) ^ ((r0l & 7) << 4)) ^ b_k);
    const uint32_t aB = sbase + OFF_A;
    const uint32_t bB = sbase + OFF_B;

    float acc[2][6][4];
    #pragma unroll
    for (int rt = 0; rt < 2; rt++)
        #pragma unroll
        for (int j = 0; j < 6; j++)
            #pragma unroll
            for (int q = 0; q < 4; q++) acc[rt][j][q] = 0.f;

    #pragma unroll 1
    for (int c = 0; c < 8; c++) {
        const uint32_t bufB = bB + (uint32_t)(c & 1) * 40960;
        if (c < 7) {
            const char* src = g_Wdb + (c + 1) * 40960;
            const uint32_t dst = bB + (uint32_t)((c + 1) & 1) * 40960;
            #pragma unroll
            for (int it = 0; it < 5; it++)
                CP_ASYNC16(dst + tid * 16 + it * 8192, src + tid * 16 + it * 8192);
            CP_COMMIT();
            CP_WAIT1();
        } else {
            CP_WAIT0();
        }
        __syncthreads();

        const uint32_t kcA = aB + (uint32_t)(c >> 1) * 8192;
        const uint32_t kx0 = (uint32_t)(c & 1) * 64;
        #pragma unroll
        for (int s = 0; s < 2; s++) {
            const uint32_t akx = kx0 + (uint32_t)s * 32;
            uint32_t Ah[2][4];
            #pragma unroll
            for (int rt = 0; rt < 2; rt++)
                LDMX4(Ah[rt], kcA + (uint32_t)rt * 2048 + (aconst ^ akx));
            uint32_t Bh[3][4], Bl[2][4];
            #pragma unroll
            for (int mi = 0; mi < 3; mi++)
                LDMX4(Bh[mi], bufB + ((bconst + (uint32_t)mi * 1024) ^ ((uint32_t)s * 32)));
            #pragma unroll
            for (int mi = 0; mi < 2; mi++)
                LDMX4(Bl[mi], bufB + 24576 + ((bconstl + (uint32_t)mi * 1024) ^ ((uint32_t)s * 32)));
            // hi product: all 6 tiles, distinct accumulators (no RAW inside)
            #pragma unroll
            for (int rt = 0; rt < 2; rt++)
                #pragma unroll
                for (int mi = 0; mi < 3; mi++) {
                    MMA_F16(acc[rt][2 * mi],     Ah[rt], Bh[mi][0], Bh[mi][1]);
                    MMA_F16(acc[rt][2 * mi + 1], Ah[rt], Bh[mi][2], Bh[mi][3]);
                }
            // lo product: x (acc 2,3) and gate (acc 4,5) only
            #pragma unroll
            for (int rt = 0; rt < 2; rt++)
                #pragma unroll
                for (int mi = 0; mi < 2; mi++) {
                    MMA_F16(acc[rt][2 + 2 * mi], Ah[rt], Bl[mi][0], Bl[mi][1]);
                    MMA_F16(acc[rt][3 + 2 * mi], Ah[rt], Bl[mi][2], Bl[mi][3]);
                }
        }
        __syncthreads();
    }

    // ---- epilogue ----
    const int rl = rowg * 32 + (lane >> 2);   // + rt*16 + h*8
    const int ql = lane & 3;
    const float ba2v = ba2[0];

    // attention partials: u tiles 0,1 -> cols 16*cg + j*8 + ql*2 + q
    float part[2][2] = {{0.f, 0.f}, {0.f, 0.f}};
    #pragma unroll
    for (int rt = 0; rt < 2; rt++)
        #pragma unroll
        for (int j = 0; j < 2; j++)
            #pragma unroll
            for (int q = 0; q < 2; q++) {
                const int uc = cg * 16 + j * 8 + ql * 2 + q;
                const float cu = sC[uc], wv = sWa2[uc];
                part[rt][0] = fmaf(fmaxf(acc[rt][j][q]     + cu, 0.f), wv, part[rt][0]);
                part[rt][1] = fmaf(fmaxf(acc[rt][j][2 + q] + cu, 0.f), wv, part[rt][1]);
            }
    #pragma unroll
    for (int rt = 0; rt < 2; rt++)
        #pragma unroll
        for (int h = 0; h < 2; h++) {
            part[rt][h] += __shfl_xor_sync(0xffffffffu, part[rt][h], 1);
            part[rt][h] += __shfl_xor_sync(0xffffffffu, part[rt][h], 2);
        }
    if (ql == 0) {
        #pragma unroll
        for (int rt = 0; rt < 2; rt++)
            #pragma unroll
            for (int h = 0; h < 2; h++)
                sP[cg * 64 + rl + rt * 16 + h * 8] = part[rt][h];
    }
    __syncthreads();
    if (tid < 64) {
        float s = ba2v;
        #pragma unroll
        for (int g = 0; g < 8; g++) s += sP[g * 64 + tid];
        sAtt[tid] = 1.f / (1.f + expf(-s));
    }
    __syncthreads();

    // GeGLU: x tiles 2,3 pair gate tiles 4,5 (same thread)
    float gvv[2][2][4];
    float s1[2][2] = {{0.f, 0.f}, {0.f, 0.f}};
    float s2[2][2] = {{0.f, 0.f}, {0.f, 0.f}};
    #pragma unroll
    for (int rt = 0; rt < 2; rt++)
        #pragma unroll
        for (int h = 0; h < 2; h++) {
            const float at = sAtt[rl + rt * 16 + h * 8];
            #pragma unroll
            for (int j = 0; j < 2; j++)
                #pragma unroll
                for (int q = 0; q < 2; q++) {
                    const int m = cg * 16 + j * 8 + ql * 2 + q;
                    const float zx = fmaf(at, acc[rt][2 + j][2 * h + q] + sC[128 + m], sBe[m]);
                    const float zg = fmaf(at, acc[rt][4 + j][2 * h + q] + sC[256 + m], sBe[128 + m]);
                    const float gel = 0.5f * zg * (1.f + erff(zg * 0.70710678118654752f));
                    const float v = zx * gel;
                    gvv[rt][h][j * 2 + q] = v;
                    s1[rt][h] += v;
                    s2[rt][h] = fmaf(v, v, s2[rt][h]);
                }
        }
    #pragma unroll
    for (int rt = 0; rt < 2; rt++)
        #pragma unroll
        for (int h = 0; h < 2; h++) {
            s1[rt][h] += __shfl_xor_sync(0xffffffffu, s1[rt][h], 1);
            s1[rt][h] += __shfl_xor_sync(0xffffffffu, s1[rt][h], 2);
            s2[rt][h] += __shfl_xor_sync(0xffffffffu, s2[rt][h], 1);
            s2[rt][h] += __shfl_xor_sync(0xffffffffu, s2[rt][h], 2);
        }
    if (ql == 0) {
        #pragma unroll
        for (int rt = 0; rt < 2; rt++)
            #pragma unroll
            for (int h = 0; h < 2; h++) {
                sS1[cg * 64 + rl + rt * 16 + h * 8] = s1[rt][h];
                sS2[cg * 64 + rl + rt * 16 + h * 8] = s2[rt][h];
            }
    }
    __syncthreads();
    if (tid < 64) {
        float S1 = 0.f, S2 = 0.f;
        #pragma unroll
        for (int g = 0; g < 8; g++) { S1 += sS1[g * 64 + tid]; S2 += sS2[g * 64 + tid]; }
        const float mu = S1 * (1.f / 128.f);
        const float var = S2 * (1.f / 128.f) - mu * mu;
        sMu[tid] = mu;
        sRs[tid] = rsqrtf(var + 1e-5f);
    }
    __syncthreads();

    #pragma unroll
    for (int rt = 0; rt < 2; rt++)
        #pragma unroll
        for (int h = 0; h < 2; h++) {
            const int r = rl + rt * 16 + h * 8;
            if (r < cnt) {
                const float mu = sMu[r], rs = sRs[r];
                float* orow = out + (size_t)(e0 + r) * CDIM;
                #pragma unroll
                for (int j = 0; j < 2; j++) {
                    const int m = cg * 16 + j * 8 + ql * 2;
                    float2 o;
                    o.x = (gvv[rt][h][j * 2]     - mu) * rs * sGa[m]     + sBt[m];
                    o.y = (gvv[rt][h][j * 2 + 1] - mu) * rs * sGa[m + 1] + sBt[m + 1];
                    *(float2*)(orow + m) = o;
                }
            }
        }
}

// ---------------------------------------------------------------------------
extern "C" void kernel_launch(void* const* d_in, const int* in_sizes, int n_in,
                              void* d_out, int out_size) {
    const float* emb   = (const float*)d_in[0];
    const void*  eidx  = d_in[1];
    const float* Ws    = (const float*)d_in[2];
    const float* bs    = (const float*)d_in[3];
    const float* Wt    = (const float*)d_in[4];
    const float* bt    = (const float*)d_in[5];
    const float* Wa1   = (const float*)d_in[6];
    const float* ba1   = (const float*)d_in[7];
    const float* Wa2   = (const float*)d_in[8];
    const float* ba2   = (const float*)d_in[9];
    const float* We    = (const float*)d_in[10];
    const float* be    = (const float*)d_in[11];
    const float* gamma = (const float*)d_in[12];
    const float* beta  = (const float*)d_in[13];
    float* out = (float*)d_out;

    cudaFuncSetAttribute(fused_kernel, cudaFuncAttributeMaxDynamicSharedMemorySize, SMEM_BYTES);

    detect_idx_kernel<<<1, 32>>>((const int*)eidx);
    precompute_W_kernel<<<(256 * NCOL + 255) / 256, 256>>>(Ws, Wt, Wa1, We);
    precompute_c_kernel<<<2, 256>>>(Wa1, We, bs, bt, ba1);
    convert_W_kernel<<<(8 * 640 * 32 + 255) / 256, 256>>>();
    fused_kernel<<<NTILES, 512, SMEM_BYTES>>>(emb, eidx, Wa2, ba2, be, gamma, beta, out);
}

// round 13
// speedup vs baseline: 4.7927x; 1.2408x over previous
#include <cuda_runtime.h>
#include <cuda_fp16.h>
#include <math.h>
#include <stdint.h>

#define E_TOTAL 500000
#define TM 64
#define NTILES ((E_TOTAL + TM - 1) / TM)   // 7813
#define NCOL 384
#define CDIM 128

// fused fp32 weights (logical cols: 0..127 attn-u, 128..255 GeGLU-x, 256..383 gate)
__device__ float g_W[256 * NCOL];
__device__ float g_c[NCOL];
__device__ int   g_idx64;
// f16 weights (single precision product), reordered + pair-packed + swizzled,
// 8 K32 chunks of 24576 B. col order: 8 groups of 48 = 16u|16x|16gate.
// element (p,k): r=p>>1, h=p&1, off = r*128 + (((h<<6)|(k*2)) ^ ((r&7)<<4)).
__device__ __align__(16) char g_Wdb[8 * 24576];

// ---------------------------------------------------------------------------
__device__ __forceinline__ uint32_t smem_u32(const void* p) {
    uint32_t a;
    asm("{ .reg .u64 t; cvta.to.shared.u64 t, %1; cvt.u32.u64 %0, t; }" : "=r"(a) : "l"(p));
    return a;
}
#define LDMX4(arr, addr) \
    asm volatile("ldmatrix.sync.aligned.m8n8.x4.shared.b16 {%0,%1,%2,%3}, [%4];" \
        : "=r"((arr)[0]), "=r"((arr)[1]), "=r"((arr)[2]), "=r"((arr)[3]) : "r"(addr))
// non-volatile: pure register op, ptxas free to software-pipeline the HMMA chain
#define MMA_F16(d, a, b0, b1) \
    asm("mma.sync.aligned.m16n8k16.row.col.f32.f16.f16.f32 " \
        "{%0,%1,%2,%3}, {%4,%5,%6,%7}, {%8,%9}, {%0,%1,%2,%3};" \
        : "+f"((d)[0]), "+f"((d)[1]), "+f"((d)[2]), "+f"((d)[3]) \
        : "r"((a)[0]), "r"((a)[1]), "r"((a)[2]), "r"((a)[3]), "r"(b0), "r"(b1))
#define CP_ASYNC16(dst, src) \
    asm volatile("cp.async.cg.shared.global [%0], [%1], 16;" :: "r"(dst), "l"(src) : "memory")
#define CP_COMMIT() asm volatile("cp.async.commit_group;" ::: "memory")
#define CP_WAIT1()  asm volatile("cp.async.wait_group 1;" ::: "memory")
#define CP_WAIT0()  asm volatile("cp.async.wait_group 0;" ::: "memory")

// smem byte offsets
#define OFF_A    0u        // 32768: [kc4] 64 rows x 128B swizzled (f16)
#define OFF_B    32768u    // 49152: 2 bufs x 24576
#define OFF_C    81920u    // 384 f
#define OFF_WA2  83456u    // 128 f
#define OFF_BE   83968u    // 256 f
#define OFF_GA   84992u    // 128 f
#define OFF_BT   85504u    // 128 f
#define OFF_SRC  86016u    // 64 i
#define OFF_TGT  86272u    // 64 i
#define OFF_P    86528u    // 8x64 f
#define OFF_S1   88576u    // 8x64 f
#define OFF_S2   90624u    // 8x64 f
#define OFF_ATT  92672u    // 64 f
#define OFF_MU   92928u    // 64 f
#define OFF_RS   93184u    // 64 f
#define SMEM_BYTES 93440

// ---------------------------------------------------------------------------
__global__ void detect_idx_kernel(const int* __restrict__ idx32) {
    if (threadIdx.x == 0) {
        int nz = 0;
        for (int i = 0; i < 256; i++) nz |= idx32[2 * i + 1];
        g_idx64 = (nz == 0) ? 1 : 0;
    }
}

__global__ void precompute_W_kernel(const float* __restrict__ Ws, const float* __restrict__ Wt,
                                    const float* __restrict__ Wa1, const float* __restrict__ We) {
    int t = blockIdx.x * blockDim.x + threadIdx.x;
    if (t >= 256 * NCOL) return;
    int k = t / NCOL;
    int j = t % NCOL;
    const float* arow = (k < 128) ? (Ws + k * 128) : (Wt + (k - 128) * 128);
    const int off = (k < 128) ? 0 : 128;
    float sum = 0.f;
    if (j < 128) {
        const float* bcol = Wa1 + off * 128 + j;
        #pragma unroll 4
        for (int m = 0; m < 128; m++) sum = fmaf(arow[m], bcol[m * 128], sum);
    } else {
        const float* bcol = We + off * 256 + (j - 128);
        #pragma unroll 4
        for (int m = 0; m < 128; m++) sum = fmaf(arow[m], bcol[m * 256], sum);
    }
    g_W[k * NCOL + j] = sum;
}

__global__ void precompute_c_kernel(const float* __restrict__ Wa1, const float* __restrict__ We,
                                    const float* __restrict__ bs, const float* __restrict__ bt,
                                    const float* __restrict__ ba1) {
    int j = blockIdx.x * blockDim.x + threadIdx.x;
    if (j >= NCOL) return;
    float s;
    if (j < 128) {
        s = ba1[j];
        for (int m = 0; m < 128; m++)
            s += bs[m] * Wa1[m * 128 + j] + bt[m] * Wa1[(128 + m) * 128 + j];
    } else {
        const int jj = j - 128;
        s = 0.f;
        for (int m = 0; m < 128; m++)
            s += bs[m] * We[m * 256 + jj] + bt[m] * We[(128 + m) * 256 + jj];
    }
    g_c[j] = s;
}

// 384 cols (8 groups of 48 = 16u|16x|16gate), single f16, pair-pack + swizzle
__global__ void convert_W_kernel() {
    int t = blockIdx.x * blockDim.x + threadIdx.x;
    if (t >= 8 * 384 * 32) return;
    const int c = t / (384 * 32);
    const int rem = t % (384 * 32);
    const int p = rem / 32;
    const int k = rem % 32;
    const int g = p / 48, q = p % 48;
    int L;
    if (q < 16)      L = 16 * g + q;
    else if (q < 32) L = 128 + 16 * g + (q - 16);
    else             L = 256 + 16 * g + (q - 32);
    const float v = g_W[(c * 32 + k) * NCOL + L];
    const int r = p >> 1, h = p & 1;
    const int off = r * 128 + ((((h << 6) | (k * 2))) ^ ((r & 7) << 4));
    *(__half*)(g_Wdb + c * 24576 + off) = __float2half_rn(v);
}

// ---------------------------------------------------------------------------
__device__ __forceinline__ unsigned pack2(float a, float b) {
    const __half2 h = __floats2half2_rn(a, b);
    return *reinterpret_cast<const unsigned*>(&h);
}

// ---------------------------------------------------------------------------
// One CTA per 64-edge tile, 512 threads = 2 rowg x 8 cg warps; warp =
// 32 rows x 48 cols (2rt x 6 n8 tiles: 2u,2x,2gate). Single-product f16
// (A and W each one f16 value). Weights cp.async double-buffered (8 K32
// chunks); A gathered once. Fused attn + GeGLU + LayerNorm epilogue.
// ---------------------------------------------------------------------------
__global__ void __launch_bounds__(512, 1) fused_kernel(
    const float* __restrict__ emb, const void* __restrict__ eidx,
    const float* __restrict__ Wa2, const float* __restrict__ ba2,
    const float* __restrict__ be, const float* __restrict__ gamma,
    const float* __restrict__ beta, float* __restrict__ out)
{
    extern __shared__ char smem[];
    const uint32_t sbase = smem_u32(smem);
    const int tid = threadIdx.x;
    const int wid = tid >> 5;
    const int lane = tid & 31;
    const int rowg = wid >> 3;     // 0..1
    const int cg   = wid & 7;      // 0..7

    float* sC   = (float*)(smem + OFF_C);
    float* sWa2 = (float*)(smem + OFF_WA2);
    float* sBe  = (float*)(smem + OFF_BE);
    float* sGa  = (float*)(smem + OFF_GA);
    float* sBt  = (float*)(smem + OFF_BT);
    float* sP   = (float*)(smem + OFF_P);
    float* sS1  = (float*)(smem + OFF_S1);
    float* sS2  = (float*)(smem + OFF_S2);
    float* sAtt = (float*)(smem + OFF_ATT);
    float* sMu  = (float*)(smem + OFF_MU);
    float* sRs  = (float*)(smem + OFF_RS);
    int*   sSrc = (int*)(smem + OFF_SRC);
    int*   sTgt = (int*)(smem + OFF_TGT);

    if (tid < 128) { sWa2[tid] = Wa2[tid]; sGa[tid] = gamma[tid]; sBt[tid] = beta[tid]; }
    if (tid < 256) sBe[tid] = be[tid];
    if (tid < 384) sC[tid] = g_c[tid];

    const int e0 = blockIdx.x * TM;
    const int cnt = min(TM, E_TOTAL - e0);
    if (tid < TM) {
        int s = 0, t = 0;
        if (tid < cnt) {
            if (g_idx64) {
                const long long* p = (const long long*)eidx;
                s = (int)p[e0 + tid]; t = (int)p[E_TOTAL + e0 + tid];
            } else {
                const int* p = (const int*)eidx;
                s = p[e0 + tid]; t = p[E_TOTAL + e0 + tid];
            }
        }
        sSrc[tid] = s; sTgt[tid] = t;
    }

    // kick off weight chunk 0 while we gather A  (24576 B = 3 x 512 x 16B)
    {
        const char* src = g_Wdb;
        const uint32_t dst = sbase + OFF_B;
        #pragma unroll
        for (int it = 0; it < 3; it++)
            CP_ASYNC16(dst + tid * 16 + it * 8192, src + tid * 16 + it * 8192);
        CP_COMMIT();
    }
    __syncthreads();   // sSrc/sTgt visible

    // gather A: all 4 K64 chunks, single f16, swizzled 128B rows
    if (tid < 256) {
        const int r_g = tid >> 2, qt = tid & 3;
        const uint32_t rs = (uint32_t)(r_g & 7) << 4;
        #pragma unroll
        for (int kc = 0; kc < 4; kc++) {
            const int node = (kc < 2) ? sSrc[r_g] : sTgt[r_g];
            const float4* src = (const float4*)(emb + (size_t)node * CDIM + (kc & 1) * 64 + qt * 16);
            const float4 v0 = src[0], v1 = src[1], v2 = src[2], v3 = src[3];
            uint4 H0, H1;
            H0.x = pack2(v0.x, v0.y); H0.y = pack2(v0.z, v0.w);
            H0.z = pack2(v1.x, v1.y); H0.w = pack2(v1.z, v1.w);
            H1.x = pack2(v2.x, v2.y); H1.y = pack2(v2.z, v2.w);
            H1.z = pack2(v3.x, v3.y); H1.w = pack2(v3.z, v3.w);
            const uint32_t base = OFF_A + kc * 8192 + r_g * 128;
            *(uint4*)(smem + base + (((uint32_t)qt * 32) ^ rs)) = H0;
            *(uint4*)(smem + base + (((uint32_t)qt * 32 + 16) ^ rs)) = H1;
        }
    }

    // per-lane ldmatrix constants
    const uint32_t a_row = (uint32_t)rowg * 32 + ((lane >> 3) & 1) * 8 + (lane & 7);
    const uint32_t a_k   = (uint32_t)(lane >> 4) * 16;
    const uint32_t aconst = a_row * 128 + (a_k ^ (((uint32_t)(lane & 7)) << 4)); // +rt*2048
    const uint32_t b_k = ((lane >> 3) & 1) * 16;
    const uint32_t p0  = (uint32_t)cg * 48 + (uint32_t)(lane >> 4) * 8 + (lane & 7); // +mi*16
    const uint32_t r0  = p0 >> 1;
    const uint32_t h0  = p0 & 1;
    const uint32_t bconst = r0 * 128 + (((h0 << 6) ^ ((r0 & 7) << 4)) ^ b_k);    // +mi*1024, ^s*32
    const uint32_t aB = sbase + OFF_A;
    const uint32_t bB = sbase + OFF_B;

    float acc[2][6][4];
    #pragma unroll
    for (int rt = 0; rt < 2; rt++)
        #pragma unroll
        for (int j = 0; j < 6; j++)
            #pragma unroll
            for (int q = 0; q < 4; q++) acc[rt][j][q] = 0.f;

    #pragma unroll 1
    for (int c = 0; c < 8; c++) {
        const uint32_t bufB = bB + (uint32_t)(c & 1) * 24576;
        if (c < 7) {
            const char* src = g_Wdb + (c + 1) * 24576;
            const uint32_t dst = bB + (uint32_t)((c + 1) & 1) * 24576;
            #pragma unroll
            for (int it = 0; it < 3; it++)
                CP_ASYNC16(dst + tid * 16 + it * 8192, src + tid * 16 + it * 8192);
            CP_COMMIT();
            CP_WAIT1();
        } else {
            CP_WAIT0();
        }
        __syncthreads();

        const uint32_t kcA = aB + (uint32_t)(c >> 1) * 8192;
        const uint32_t kx0 = (uint32_t)(c & 1) * 64;
        #pragma unroll
        for (int s = 0; s < 2; s++) {
            const uint32_t akx = kx0 + (uint32_t)s * 32;
            uint32_t Ah[2][4];
            #pragma unroll
            for (int rt = 0; rt < 2; rt++)
                LDMX4(Ah[rt], kcA + (uint32_t)rt * 2048 + (aconst ^ akx));
            uint32_t Bh[3][4];
            #pragma unroll
            for (int mi = 0; mi < 3; mi++)
                LDMX4(Bh[mi], bufB + ((bconst + (uint32_t)mi * 1024) ^ ((uint32_t)s * 32)));
            #pragma unroll
            for (int rt = 0; rt < 2; rt++)
                #pragma unroll
                for (int mi = 0; mi < 3; mi++) {
                    MMA_F16(acc[rt][2 * mi],     Ah[rt], Bh[mi][0], Bh[mi][1]);
                    MMA_F16(acc[rt][2 * mi + 1], Ah[rt], Bh[mi][2], Bh[mi][3]);
                }
        }
        __syncthreads();
    }

    // ---- epilogue ----
    const int rl = rowg * 32 + (lane >> 2);   // + rt*16 + h*8
    const int ql = lane & 3;
    const float ba2v = ba2[0];

    // attention partials: u tiles 0,1 -> cols 16*cg + j*8 + ql*2 + q
    float part[2][2] = {{0.f, 0.f}, {0.f, 0.f}};
    #pragma unroll
    for (int rt = 0; rt < 2; rt++)
        #pragma unroll
        for (int j = 0; j < 2; j++)
            #pragma unroll
            for (int q = 0; q < 2; q++) {
                const int uc = cg * 16 + j * 8 + ql * 2 + q;
                const float cu = sC[uc], wv = sWa2[uc];
                part[rt][0] = fmaf(fmaxf(acc[rt][j][q]     + cu, 0.f), wv, part[rt][0]);
                part[rt][1] = fmaf(fmaxf(acc[rt][j][2 + q] + cu, 0.f), wv, part[rt][1]);
            }
    #pragma unroll
    for (int rt = 0; rt < 2; rt++)
        #pragma unroll
        for (int h = 0; h < 2; h++) {
            part[rt][h] += __shfl_xor_sync(0xffffffffu, part[rt][h], 1);
            part[rt][h] += __shfl_xor_sync(0xffffffffu, part[rt][h], 2);
        }
    if (ql == 0) {
        #pragma unroll
        for (int rt = 0; rt < 2; rt++)
            #pragma unroll
            for (int h = 0; h < 2; h++)
                sP[cg * 64 + rl + rt * 16 + h * 8] = part[rt][h];
    }
    __syncthreads();
    if (tid < 64) {
        float s = ba2v;
        #pragma unroll
        for (int g = 0; g < 8; g++) s += sP[g * 64 + tid];
        sAtt[tid] = 1.f / (1.f + expf(-s));
    }
    __syncthreads();

    // GeGLU: x tiles 2,3 pair gate tiles 4,5 (same thread)
    float gvv[2][2][4];
    float s1[2][2] = {{0.f, 0.f}, {0.f, 0.f}};
    float s2[2][2] = {{0.f, 0.f}, {0.f, 0.f}};
    #pragma unroll
    for (int rt = 0; rt < 2; rt++)
        #pragma unroll
        for (int h = 0; h < 2; h++) {
            const float at = sAtt[rl + rt * 16 + h * 8];
            #pragma unroll
            for (int j = 0; j < 2; j++)
                #pragma unroll
                for (int q = 0; q < 2; q++) {
                    const int m = cg * 16 + j * 8 + ql * 2 + q;
                    const float zx = fmaf(at, acc[rt][2 + j][2 * h + q] + sC[128 + m], sBe[m]);
                    const float zg = fmaf(at, acc[rt][4 + j][2 * h + q] + sC[256 + m], sBe[128 + m]);
                    const float gel = 0.5f * zg * (1.f + erff(zg * 0.70710678118654752f));
                    const float v = zx * gel;
                    gvv[rt][h][j * 2 + q] = v;
                    s1[rt][h] += v;
                    s2[rt][h] = fmaf(v, v, s2[rt][h]);
                }
        }
    #pragma unroll
    for (int rt = 0; rt < 2; rt++)
        #pragma unroll
        for (int h = 0; h < 2; h++) {
            s1[rt][h] += __shfl_xor_sync(0xffffffffu, s1[rt][h], 1);
            s1[rt][h] += __shfl_xor_sync(0xffffffffu, s1[rt][h], 2);
            s2[rt][h] += __shfl_xor_sync(0xffffffffu, s2[rt][h], 1);
            s2[rt][h] += __shfl_xor_sync(0xffffffffu, s2[rt][h], 2);
        }
    if (ql == 0) {
        #pragma unroll
        for (int rt = 0; rt < 2; rt++)
            #pragma unroll
            for (int h = 0; h < 2; h++) {
                sS1[cg * 64 + rl + rt * 16 + h * 8] = s1[rt][h];
                sS2[cg * 64 + rl + rt * 16 + h * 8] = s2[rt][h];
            }
    }
    __syncthreads();
    if (tid < 64) {
        float S1 = 0.f, S2 = 0.f;
        #pragma unroll
        for (int g = 0; g < 8; g++) { S1 += sS1[g * 64 + tid]; S2 += sS2[g * 64 + tid]; }
        const float mu = S1 * (1.f / 128.f);
        const float var = S2 * (1.f / 128.f) - mu * mu;
        sMu[tid] = mu;
        sRs[tid] = rsqrtf(var + 1e-5f);
    }
    __syncthreads();

    #pragma unroll
    for (int rt = 0; rt < 2; rt++)
        #pragma unroll
        for (int h = 0; h < 2; h++) {
            const int r = rl + rt * 16 + h * 8;
            if (r < cnt) {
                const float mu = sMu[r], rs = sRs[r];
                float* orow = out + (size_t)(e0 + r) * CDIM;
                #pragma unroll
                for (int j = 0; j < 2; j++) {
                    const int m = cg * 16 + j * 8 + ql * 2;
                    float2 o;
                    o.x = (gvv[rt][h][j * 2]     - mu) * rs * sGa[m]     + sBt[m];
                    o.y = (gvv[rt][h][j * 2 + 1] - mu) * rs * sGa[m + 1] + sBt[m + 1];
                    *(float2*)(orow + m) = o;
                }
            }
        }
}

// ---------------------------------------------------------------------------
extern "C" void kernel_launch(void* const* d_in, const int* in_sizes, int n_in,
                              void* d_out, int out_size) {
    const float* emb   = (const float*)d_in[0];
    const void*  eidx  = d_in[1];
    const float* Ws    = (const float*)d_in[2];
    const float* bs    = (const float*)d_in[3];
    const float* Wt    = (const float*)d_in[4];
    const float* bt    = (const float*)d_in[5];
    const float* Wa1   = (const float*)d_in[6];
    const float* ba1   = (const float*)d_in[7];
    const float* Wa2   = (const float*)d_in[8];
    const float* ba2   = (const float*)d_in[9];
    const float* We    = (const float*)d_in[10];
    const float* be    = (const float*)d_in[11];
    const float* gamma = (const float*)d_in[12];
    const float* beta  = (const float*)d_in[13];
    float* out = (float*)d_out;

    cudaFuncSetAttribute(fused_kernel, cudaFuncAttributeMaxDynamicSharedMemorySize, SMEM_BYTES);

    detect_idx_kernel<<<1, 32>>>((const int*)eidx);
    precompute_W_kernel<<<(256 * NCOL + 255) / 256, 256>>>(Ws, Wt, Wa1, We);
    precompute_c_kernel<<<2, 256>>>(Wa1, We, bs, bt, ba1);
    convert_W_kernel<<<(8 * 384 * 32 + 255) / 256, 256>>>();
    fused_kernel<<<NTILES, 512, SMEM_BYTES>>>(emb, eidx, Wa2, ba2, be, gamma, beta, out);
}

// round 14
// speedup vs baseline: 5.0248x; 1.0484x over previous
#include <cuda_runtime.h>
#include <cuda_fp16.h>
#include <math.h>
#include <stdint.h>

#define E_TOTAL 500000
#define TM 64
#define NTILES ((E_TOTAL + TM - 1) / TM)   // 7813
#define NCOL 384
#define CDIM 128

// fused fp32 weights (logical cols: 0..127 attn-u, 128..255 GeGLU-x, 256..383 gate)
__device__ float g_W[256 * NCOL];
__device__ float g_c[NCOL];
__device__ int   g_idx64;
// f16 weights, reordered + pair-packed + swizzled, 8 K32 sub-chunks of 24576 B
// (consumed as 4 K64 chunks of 49152 B). col order: 8 groups of 48 = 16u|16x|16gate.
// element (p,k): r=p>>1, h=p&1, off = r*128 + (((h<<6)|(k*2)) ^ ((r&7)<<4)).
__device__ __align__(16) char g_Wdb[8 * 24576];

// ---------------------------------------------------------------------------
__device__ __forceinline__ uint32_t smem_u32(const void* p) {
    uint32_t a;
    asm("{ .reg .u64 t; cvta.to.shared.u64 t, %1; cvt.u32.u64 %0, t; }" : "=r"(a) : "l"(p));
    return a;
}
#define LDMX4(arr, addr) \
    asm volatile("ldmatrix.sync.aligned.m8n8.x4.shared.b16 {%0,%1,%2,%3}, [%4];" \
        : "=r"((arr)[0]), "=r"((arr)[1]), "=r"((arr)[2]), "=r"((arr)[3]) : "r"(addr))
// non-volatile: pure register op, ptxas free to software-pipeline the HMMA chain
#define MMA_F16(d, a, b0, b1) \
    asm("mma.sync.aligned.m16n8k16.row.col.f32.f16.f16.f32 " \
        "{%0,%1,%2,%3}, {%4,%5,%6,%7}, {%8,%9}, {%0,%1,%2,%3};" \
        : "+f"((d)[0]), "+f"((d)[1]), "+f"((d)[2]), "+f"((d)[3]) \
        : "r"((a)[0]), "r"((a)[1]), "r"((a)[2]), "r"((a)[3]), "r"(b0), "r"(b1))
#define CP_ASYNC16(dst, src) \
    asm volatile("cp.async.cg.shared.global [%0], [%1], 16;" :: "r"(dst), "l"(src) : "memory")
#define CP_COMMIT() asm volatile("cp.async.commit_group;" ::: "memory")
#define CP_WAIT1()  asm volatile("cp.async.wait_group 1;" ::: "memory")
#define CP_WAIT0()  asm volatile("cp.async.wait_group 0;" ::: "memory")

// smem byte offsets
#define OFF_A    0u        // 32768: [kc4] 64 rows x 128B swizzled (f16)
#define OFF_B    32768u    // 98304: 2 bufs x 49152 (K64 chunk = 2 K32 sub-chunks)
#define OFF_C    131072u   // 384 f
#define OFF_WA2  132608u   // 128 f
#define OFF_BE   133120u   // 256 f
#define OFF_GA   134144u   // 128 f
#define OFF_BT   134656u   // 128 f
#define OFF_SRC  135168u   // 64 i
#define OFF_TGT  135424u   // 64 i
#define OFF_P    135680u   // 8x64 f
#define OFF_S1   137728u   // 8x64 f
#define OFF_S2   139776u   // 8x64 f
#define OFF_ATT  141824u   // 64 f
#define OFF_MU   142080u   // 64 f
#define OFF_RS   142336u   // 64 f
#define SMEM_BYTES 142592

// ---------------------------------------------------------------------------
__global__ void detect_idx_kernel(const int* __restrict__ idx32) {
    if (threadIdx.x == 0) {
        int nz = 0;
        for (int i = 0; i < 256; i++) nz |= idx32[2 * i + 1];
        g_idx64 = (nz == 0) ? 1 : 0;
    }
}

__global__ void precompute_W_kernel(const float* __restrict__ Ws, const float* __restrict__ Wt,
                                    const float* __restrict__ Wa1, const float* __restrict__ We) {
    int t = blockIdx.x * blockDim.x + threadIdx.x;
    if (t >= 256 * NCOL) return;
    int k = t / NCOL;
    int j = t % NCOL;
    const float* arow = (k < 128) ? (Ws + k * 128) : (Wt + (k - 128) * 128);
    const int off = (k < 128) ? 0 : 128;
    float sum = 0.f;
    if (j < 128) {
        const float* bcol = Wa1 + off * 128 + j;
        #pragma unroll 4
        for (int m = 0; m < 128; m++) sum = fmaf(arow[m], bcol[m * 128], sum);
    } else {
        const float* bcol = We + off * 256 + (j - 128);
        #pragma unroll 4
        for (int m = 0; m < 128; m++) sum = fmaf(arow[m], bcol[m * 256], sum);
    }
    g_W[k * NCOL + j] = sum;
}

__global__ void precompute_c_kernel(const float* __restrict__ Wa1, const float* __restrict__ We,
                                    const float* __restrict__ bs, const float* __restrict__ bt,
                                    const float* __restrict__ ba1) {
    int j = blockIdx.x * blockDim.x + threadIdx.x;
    if (j >= NCOL) return;
    float s;
    if (j < 128) {
        s = ba1[j];
        for (int m = 0; m < 128; m++)
            s += bs[m] * Wa1[m * 128 + j] + bt[m] * Wa1[(128 + m) * 128 + j];
    } else {
        const int jj = j - 128;
        s = 0.f;
        for (int m = 0; m < 128; m++)
            s += bs[m] * We[m * 256 + jj] + bt[m] * We[(128 + m) * 256 + jj];
    }
    g_c[j] = s;
}

// 384 cols (8 groups of 48 = 16u|16x|16gate), single f16, pair-pack + swizzle
__global__ void convert_W_kernel() {
    int t = blockIdx.x * blockDim.x + threadIdx.x;
    if (t >= 8 * 384 * 32) return;
    const int c = t / (384 * 32);
    const int rem = t % (384 * 32);
    const int p = rem / 32;
    const int k = rem % 32;
    const int g = p / 48, q = p % 48;
    int L;
    if (q < 16)      L = 16 * g + q;
    else if (q < 32) L = 128 + 16 * g + (q - 16);
    else             L = 256 + 16 * g + (q - 32);
    const float v = g_W[(c * 32 + k) * NCOL + L];
    const int r = p >> 1, h = p & 1;
    const int off = r * 128 + ((((h << 6) | (k * 2))) ^ ((r & 7) << 4));
    *(__half*)(g_Wdb + c * 24576 + off) = __float2half_rn(v);
}

// ---------------------------------------------------------------------------
__device__ __forceinline__ unsigned pack2(float a, float b) {
    const __half2 h = __floats2half2_rn(a, b);
    return *reinterpret_cast<const unsigned*>(&h);
}

// ---------------------------------------------------------------------------
// One CTA per 64-edge tile, 512 threads = 2 rowg x 8 cg warps; warp =
// 32 rows x 48 cols (2rt x 6 n8 tiles: 2u,2x,2gate). Single-product f16.
// Weights cp.async double-buffered in 4 K64 chunks (8 main-loop barriers);
// A gathered once by ALL 512 threads. Fused attn + GeGLU + LN epilogue.
// ---------------------------------------------------------------------------
__global__ void __launch_bounds__(512, 1) fused_kernel(
    const float* __restrict__ emb, const void* __restrict__ eidx,
    const float* __restrict__ Wa2, const float* __restrict__ ba2,
    const float* __restrict__ be, const float* __restrict__ gamma,
    const float* __restrict__ beta, float* __restrict__ out)
{
    extern __shared__ char smem[];
    const uint32_t sbase = smem_u32(smem);
    const int tid = threadIdx.x;
    const int wid = tid >> 5;
    const int lane = tid & 31;
    const int rowg = wid >> 3;     // 0..1
    const int cg   = wid & 7;      // 0..7

    float* sC   = (float*)(smem + OFF_C);
    float* sWa2 = (float*)(smem + OFF_WA2);
    float* sBe  = (float*)(smem + OFF_BE);
    float* sGa  = (float*)(smem + OFF_GA);
    float* sBt  = (float*)(smem + OFF_BT);
    float* sP   = (float*)(smem + OFF_P);
    float* sS1  = (float*)(smem + OFF_S1);
    float* sS2  = (float*)(smem + OFF_S2);
    float* sAtt = (float*)(smem + OFF_ATT);
    float* sMu  = (float*)(smem + OFF_MU);
    float* sRs  = (float*)(smem + OFF_RS);
    int*   sSrc = (int*)(smem + OFF_SRC);
    int*   sTgt = (int*)(smem + OFF_TGT);

    if (tid < 128) { sWa2[tid] = Wa2[tid]; sGa[tid] = gamma[tid]; sBt[tid] = beta[tid]; }
    if (tid < 256) sBe[tid] = be[tid];
    if (tid < 384) sC[tid] = g_c[tid];

    const int e0 = blockIdx.x * TM;
    const int cnt = min(TM, E_TOTAL - e0);
    if (tid < TM) {
        int s = 0, t = 0;
        if (tid < cnt) {
            if (g_idx64) {
                const long long* p = (const long long*)eidx;
                s = (int)p[e0 + tid]; t = (int)p[E_TOTAL + e0 + tid];
            } else {
                const int* p = (const int*)eidx;
                s = p[e0 + tid]; t = p[E_TOTAL + e0 + tid];
            }
        }
        sSrc[tid] = s; sTgt[tid] = t;
    }

    // kick off weight chunk 0 while we gather A  (49152 B = 6 x 512 x 16B)
    {
        const char* src = g_Wdb;
        const uint32_t dst = sbase + OFF_B;
        #pragma unroll
        for (int it = 0; it < 6; it++)
            CP_ASYNC16(dst + tid * 16 + it * 8192, src + tid * 16 + it * 8192);
        CP_COMMIT();
    }
    __syncthreads();   // sSrc/sTgt visible

    // gather A: all 512 threads, 2 K64 chunks each, swizzled 128B rows
    {
        const int r_g = (tid & 255) >> 2, qt = tid & 3;
        const int kc0 = (tid >> 8) * 2;
        const uint32_t rs = (uint32_t)(r_g & 7) << 4;
        #pragma unroll
        for (int kk = 0; kk < 2; kk++) {
            const int kc = kc0 + kk;
            const int node = (kc < 2) ? sSrc[r_g] : sTgt[r_g];
            const float4* src = (const float4*)(emb + (size_t)node * CDIM + (kc & 1) * 64 + qt * 16);
            const float4 v0 = src[0], v1 = src[1], v2 = src[2], v3 = src[3];
            uint4 H0, H1;
            H0.x = pack2(v0.x, v0.y); H0.y = pack2(v0.z, v0.w);
            H0.z = pack2(v1.x, v1.y); H0.w = pack2(v1.z, v1.w);
            H1.x = pack2(v2.x, v2.y); H1.y = pack2(v2.z, v2.w);
            H1.z = pack2(v3.x, v3.y); H1.w = pack2(v3.z, v3.w);
            const uint32_t base = OFF_A + kc * 8192 + r_g * 128;
            *(uint4*)(smem + base + (((uint32_t)qt * 32) ^ rs)) = H0;
            *(uint4*)(smem + base + (((uint32_t)qt * 32 + 16) ^ rs)) = H1;
        }
    }

    // per-lane ldmatrix constants
    const uint32_t a_row = (uint32_t)rowg * 32 + ((lane >> 3) & 1) * 8 + (lane & 7);
    const uint32_t a_k   = (uint32_t)(lane >> 4) * 16;
    const uint32_t aconst = a_row * 128 + (a_k ^ (((uint32_t)(lane & 7)) << 4)); // +rt*2048, ^ss*32
    const uint32_t b_k = ((lane >> 3) & 1) * 16;
    const uint32_t p0  = (uint32_t)cg * 48 + (uint32_t)(lane >> 4) * 8 + (lane & 7); // +mi*16
    const uint32_t r0  = p0 >> 1;
    const uint32_t h0  = p0 & 1;
    const uint32_t bconst = r0 * 128 + (((h0 << 6) ^ ((r0 & 7) << 4)) ^ b_k);    // +mi*1024, ^(ss&1)*32
    const uint32_t aB = sbase + OFF_A;
    const uint32_t bB = sbase + OFF_B;

    float acc[2][6][4];
    #pragma unroll
    for (int rt = 0; rt < 2; rt++)
        #pragma unroll
        for (int j = 0; j < 6; j++)
            #pragma unroll
            for (int q = 0; q < 4; q++) acc[rt][j][q] = 0.f;

    #pragma unroll 1
    for (int c = 0; c < 4; c++) {
        const uint32_t bufB = bB + (uint32_t)(c & 1) * 49152;
        if (c < 3) {
            const char* src = g_Wdb + (c + 1) * 49152;
            const uint32_t dst = bB + (uint32_t)((c + 1) & 1) * 49152;
            #pragma unroll
            for (int it = 0; it < 6; it++)
                CP_ASYNC16(dst + tid * 16 + it * 8192, src + tid * 16 + it * 8192);
            CP_COMMIT();
            CP_WAIT1();
        } else {
            CP_WAIT0();
        }
        __syncthreads();

        const uint32_t kcA = aB + (uint32_t)c * 8192;
        #pragma unroll
        for (int ss = 0; ss < 4; ss++) {
            const uint32_t akx = (uint32_t)ss * 32;
            uint32_t Ah[2][4];
            #pragma unroll
            for (int rt = 0; rt < 2; rt++)
                LDMX4(Ah[rt], kcA + (uint32_t)rt * 2048 + (aconst ^ akx));
            const uint32_t bsub = bufB + (uint32_t)(ss >> 1) * 24576;
            const uint32_t bxor = (uint32_t)(ss & 1) * 32;
            uint32_t Bh[3][4];
            #pragma unroll
            for (int mi = 0; mi < 3; mi++)
                LDMX4(Bh[mi], bsub + ((bconst + (uint32_t)mi * 1024) ^ bxor));
            #pragma unroll
            for (int rt = 0; rt < 2; rt++)
                #pragma unroll
                for (int mi = 0; mi < 3; mi++) {
                    MMA_F16(acc[rt][2 * mi],     Ah[rt], Bh[mi][0], Bh[mi][1]);
                    MMA_F16(acc[rt][2 * mi + 1], Ah[rt], Bh[mi][2], Bh[mi][3]);
                }
        }
        __syncthreads();
    }

    // ---- epilogue ----
    const int rl = rowg * 32 + (lane >> 2);   // + rt*16 + h*8
    const int ql = lane & 3;
    const float ba2v = ba2[0];

    // attention partials: u tiles 0,1 -> cols 16*cg + j*8 + ql*2 + q
    float part[2][2] = {{0.f, 0.f}, {0.f, 0.f}};
    #pragma unroll
    for (int rt = 0; rt < 2; rt++)
        #pragma unroll
        for (int j = 0; j < 2; j++)
            #pragma unroll
            for (int q = 0; q < 2; q++) {
                const int uc = cg * 16 + j * 8 + ql * 2 + q;
                const float cu = sC[uc], wv = sWa2[uc];
                part[rt][0] = fmaf(fmaxf(acc[rt][j][q]     + cu, 0.f), wv, part[rt][0]);
                part[rt][1] = fmaf(fmaxf(acc[rt][j][2 + q] + cu, 0.f), wv, part[rt][1]);
            }
    #pragma unroll
    for (int rt = 0; rt < 2; rt++)
        #pragma unroll
        for (int h = 0; h < 2; h++) {
            part[rt][h] += __shfl_xor_sync(0xffffffffu, part[rt][h], 1);
            part[rt][h] += __shfl_xor_sync(0xffffffffu, part[rt][h], 2);
        }
    if (ql == 0) {
        #pragma unroll
        for (int rt = 0; rt < 2; rt++)
            #pragma unroll
            for (int h = 0; h < 2; h++)
                sP[cg * 64 + rl + rt * 16 + h * 8] = part[rt][h];
    }
    __syncthreads();
    if (tid < 64) {
        float s = ba2v;
        #pragma unroll
        for (int g = 0; g < 8; g++) s += sP[g * 64 + tid];
        sAtt[tid] = 1.f / (1.f + expf(-s));
    }
    __syncthreads();

    // GeGLU: x tiles 2,3 pair gate tiles 4,5 (same thread)
    float gvv[2][2][4];
    float s1[2][2] = {{0.f, 0.f}, {0.f, 0.f}};
    float s2[2][2] = {{0.f, 0.f}, {0.f, 0.f}};
    #pragma unroll
    for (int rt = 0; rt < 2; rt++)
        #pragma unroll
        for (int h = 0; h < 2; h++) {
            const float at = sAtt[rl + rt * 16 + h * 8];
            #pragma unroll
            for (int j = 0; j < 2; j++)
                #pragma unroll
                for (int q = 0; q < 2; q++) {
                    const int m = cg * 16 + j * 8 + ql * 2 + q;
                    const float zx = fmaf(at, acc[rt][2 + j][2 * h + q] + sC[128 + m], sBe[m]);
                    const float zg = fmaf(at, acc[rt][4 + j][2 * h + q] + sC[256 + m], sBe[128 + m]);
                    const float gel = 0.5f * zg * (1.f + erff(zg * 0.70710678118654752f));
                    const float v = zx * gel;
                    gvv[rt][h][j * 2 + q] = v;
                    s1[rt][h] += v;
                    s2[rt][h] = fmaf(v, v, s2[rt][h]);
                }
        }
    #pragma unroll
    for (int rt = 0; rt < 2; rt++)
        #pragma unroll
        for (int h = 0; h < 2; h++) {
            s1[rt][h] += __shfl_xor_sync(0xffffffffu, s1[rt][h], 1);
            s1[rt][h] += __shfl_xor_sync(0xffffffffu, s1[rt][h], 2);
            s2[rt][h] += __shfl_xor_sync(0xffffffffu, s2[rt][h], 1);
            s2[rt][h] += __shfl_xor_sync(0xffffffffu, s2[rt][h], 2);
        }
    if (ql == 0) {
        #pragma unroll
        for (int rt = 0; rt < 2; rt++)
            #pragma unroll
            for (int h = 0; h < 2; h++) {
                sS1[cg * 64 + rl + rt * 16 + h * 8] = s1[rt][h];
                sS2[cg * 64 + rl + rt * 16 + h * 8] = s2[rt][h];
            }
    }
    __syncthreads();
    if (tid < 64) {
        float S1 = 0.f, S2 = 0.f;
        #pragma unroll
        for (int g = 0; g < 8; g++) { S1 += sS1[g * 64 + tid]; S2 += sS2[g * 64 + tid]; }
        const float mu = S1 * (1.f / 128.f);
        const float var = S2 * (1.f / 128.f) - mu * mu;
        sMu[tid] = mu;
        sRs[tid] = rsqrtf(var + 1e-5f);
    }
    __syncthreads();

    #pragma unroll
    for (int rt = 0; rt < 2; rt++)
        #pragma unroll
        for (int h = 0; h < 2; h++) {
            const int r = rl + rt * 16 + h * 8;
            if (r < cnt) {
                const float mu = sMu[r], rs = sRs[r];
                float* orow = out + (size_t)(e0 + r) * CDIM;
                #pragma unroll
                for (int j = 0; j < 2; j++) {
                    const int m = cg * 16 + j * 8 + ql * 2;
                    float2 o;
                    o.x = (gvv[rt][h][j * 2]     - mu) * rs * sGa[m]     + sBt[m];
                    o.y = (gvv[rt][h][j * 2 + 1] - mu) * rs * sGa[m + 1] + sBt[m + 1];
                    *(float2*)(orow + m) = o;
                }
            }
        }
}

// ---------------------------------------------------------------------------
extern "C" void kernel_launch(void* const* d_in, const int* in_sizes, int n_in,
                              void* d_out, int out_size) {
    const float* emb   = (const float*)d_in[0];
    const void*  eidx  = d_in[1];
    const float* Ws    = (const float*)d_in[2];
    const float* bs    = (const float*)d_in[3];
    const float* Wt    = (const float*)d_in[4];
    const float* bt    = (const float*)d_in[5];
    const float* Wa1   = (const float*)d_in[6];
    const float* ba1   = (const float*)d_in[7];
    const float* Wa2   = (const float*)d_in[8];
    const float* ba2   = (const float*)d_in[9];
    const float* We    = (const float*)d_in[10];
    const float* be    = (const float*)d_in[11];
    const float* gamma = (const float*)d_in[12];
    const float* beta  = (const float*)d_in[13];
    float* out = (float*)d_out;

    cudaFuncSetAttribute(fused_kernel, cudaFuncAttributeMaxDynamicSharedMemorySize, SMEM_BYTES);

    detect_idx_kernel<<<1, 32>>>((const int*)eidx);
    precompute_W_kernel<<<(256 * NCOL + 255) / 256, 256>>>(Ws, Wt, Wa1, We);
    precompute_c_kernel<<<2, 256>>>(Wa1, We, bs, bt, ba1);
    convert_W_kernel<<<(8 * 384 * 32 + 255) / 256, 256>>>();
    fused_kernel<<<NTILES, 512, SMEM_BYTES>>>(emb, eidx, Wa2, ba2, be, gamma, beta, out);
}

// round 15
// speedup vs baseline: 5.7165x; 1.1377x over previous
#include <cuda_runtime.h>
#include <cuda_fp16.h>
#include <math.h>
#include <stdint.h>

#define E_TOTAL 500000
#define TM 64
#define NTILES ((E_TOTAL + TM - 1) / TM)   // 7813
#define NCOL 384
#define CDIM 128
#define GRID_P 152

// fused fp32 weights (logical cols: 0..127 attn-u, 128..255 GeGLU-x, 256..383 gate)
__device__ float g_W[256 * NCOL];
__device__ float g_c[NCOL];
__device__ int   g_idx64;
// f16 weights, reordered + pair-packed + swizzled, 8 K32 sub-chunks of 24576 B
// (consumed as 4 K64 chunks of 49152 B). col order: 8 groups of 48 = 16u|16x|16gate.
// element (p,k): r=p>>1, h=p&1, off = r*128 + (((h<<6)|(k*2)) ^ ((r&7)<<4)).
__device__ __align__(16) char g_Wdb[8 * 24576];

// ---------------------------------------------------------------------------
__device__ __forceinline__ uint32_t smem_u32(const void* p) {
    uint32_t a;
    asm("{ .reg .u64 t; cvta.to.shared.u64 t, %1; cvt.u32.u64 %0, t; }" : "=r"(a) : "l"(p));
    return a;
}
#define LDMX4(arr, addr) \
    asm volatile("ldmatrix.sync.aligned.m8n8.x4.shared.b16 {%0,%1,%2,%3}, [%4];" \
        : "=r"((arr)[0]), "=r"((arr)[1]), "=r"((arr)[2]), "=r"((arr)[3]) : "r"(addr))
// non-volatile: pure register op, ptxas free to software-pipeline the HMMA chain
#define MMA_F16(d, a, b0, b1) \
    asm("mma.sync.aligned.m16n8k16.row.col.f32.f16.f16.f32 " \
        "{%0,%1,%2,%3}, {%4,%5,%6,%7}, {%8,%9}, {%0,%1,%2,%3};" \
        : "+f"((d)[0]), "+f"((d)[1]), "+f"((d)[2]), "+f"((d)[3]) \
        : "r"((a)[0]), "r"((a)[1]), "r"((a)[2]), "r"((a)[3]), "r"(b0), "r"(b1))
#define CP_ASYNC16(dst, src) \
    asm volatile("cp.async.cg.shared.global [%0], [%1], 16;" :: "r"(dst), "l"(src) : "memory")
#define CP_COMMIT() asm volatile("cp.async.commit_group;" ::: "memory")
#define CP_WAIT0()  asm volatile("cp.async.wait_group 0;" ::: "memory")

// smem layout (persistent kernel):
//   [0, 196608)           resident f16 weights (4 K64 chunks of 49152)
//   [196608, 229376)      A tile (4 chunks x 8192) — epilogue scratch overlays it
//   [229376, 231424)      gamma | beta | be
#define OFF_W    0u
#define OFF_A    196608u
#define OFF_P    196608u     // 8x64 f   (overlay: A dead during epilogue)
#define OFF_S1   198656u     // 8x64 f
#define OFF_S2   200704u     // 8x64 f
#define OFF_ATT  202752u     // 64 f
#define OFF_MU   203008u     // 64 f
#define OFF_RS   203264u     // 64 f
#define OFF_GA   229376u     // 128 f
#define OFF_BT   229888u     // 128 f
#define OFF_BE   230400u     // 256 f
#define SMEM_BYTES 231424

// ---------------------------------------------------------------------------
__global__ void detect_idx_kernel(const int* __restrict__ idx32) {
    if (threadIdx.x == 0) {
        int nz = 0;
        for (int i = 0; i < 256; i++) nz |= idx32[2 * i + 1];
        g_idx64 = (nz == 0) ? 1 : 0;
    }
}

__global__ void precompute_W_kernel(const float* __restrict__ Ws, const float* __restrict__ Wt,
                                    const float* __restrict__ Wa1, const float* __restrict__ We) {
    int t = blockIdx.x * blockDim.x + threadIdx.x;
    if (t >= 256 * NCOL) return;
    int k = t / NCOL;
    int j = t % NCOL;
    const float* arow = (k < 128) ? (Ws + k * 128) : (Wt + (k - 128) * 128);
    const int off = (k < 128) ? 0 : 128;
    float sum = 0.f;
    if (j < 128) {
        const float* bcol = Wa1 + off * 128 + j;
        #pragma unroll 4
        for (int m = 0; m < 128; m++) sum = fmaf(arow[m], bcol[m * 128], sum);
    } else {
        const float* bcol = We + off * 256 + (j - 128);
        #pragma unroll 4
        for (int m = 0; m < 128; m++) sum = fmaf(arow[m], bcol[m * 256], sum);
    }
    g_W[k * NCOL + j] = sum;
}

__global__ void precompute_c_kernel(const float* __restrict__ Wa1, const float* __restrict__ We,
                                    const float* __restrict__ bs, const float* __restrict__ bt,
                                    const float* __restrict__ ba1) {
    int j = blockIdx.x * blockDim.x + threadIdx.x;
    if (j >= NCOL) return;
    float s;
    if (j < 128) {
        s = ba1[j];
        for (int m = 0; m < 128; m++)
            s += bs[m] * Wa1[m * 128 + j] + bt[m] * Wa1[(128 + m) * 128 + j];
    } else {
        const int jj = j - 128;
        s = 0.f;
        for (int m = 0; m < 128; m++)
            s += bs[m] * We[m * 256 + jj] + bt[m] * We[(128 + m) * 256 + jj];
    }
    g_c[j] = s;
}

// 384 cols (8 groups of 48 = 16u|16x|16gate), single f16, pair-pack + swizzle
__global__ void convert_W_kernel() {
    int t = blockIdx.x * blockDim.x + threadIdx.x;
    if (t >= 8 * 384 * 32) return;
    const int c = t / (384 * 32);
    const int rem = t % (384 * 32);
    const int p = rem / 32;
    const int k = rem % 32;
    const int g = p / 48, q = p % 48;
    int L;
    if (q < 16)      L = 16 * g + q;
    else if (q < 32) L = 128 + 16 * g + (q - 16);
    else             L = 256 + 16 * g + (q - 32);
    const float v = g_W[(c * 32 + k) * NCOL + L];
    const int r = p >> 1, h = p & 1;
    const int off = r * 128 + ((((h << 6) | (k * 2))) ^ ((r & 7) << 4));
    *(__half*)(g_Wdb + c * 24576 + off) = __float2half_rn(v);
}

// ---------------------------------------------------------------------------
__device__ __forceinline__ unsigned pack2(float a, float b) {
    const __half2 h = __floats2half2_rn(a, b);
    return *reinterpret_cast<const unsigned*>(&h);
}

// ---------------------------------------------------------------------------
// PERSISTENT kernel: 152 CTAs x 512 threads (2 rowg x 8 cg warps; warp =
// 32 rows x 48 cols = 2rt x 6 n8 tiles: 2u,2x,2gate). Full f16 weight matrix
// resident in smem; grid-stride over 64-edge tiles with zero weight traffic.
// Single-product f16 math (identical to R13/R14). Fused attn+GeGLU+LN.
// ---------------------------------------------------------------------------
__global__ void __launch_bounds__(512, 1) fused_kernel(
    const float* __restrict__ emb, const void* __restrict__ eidx,
    const float* __restrict__ Wa2, const float* __restrict__ ba2,
    const float* __restrict__ be, const float* __restrict__ gamma,
    const float* __restrict__ beta, float* __restrict__ out)
{
    extern __shared__ char smem[];
    const uint32_t sbase = smem_u32(smem);
    const int tid = threadIdx.x;
    const int wid = tid >> 5;
    const int lane = tid & 31;
    const int rowg = wid >> 3;     // 0..1
    const int cg   = wid & 7;      // 0..7
    const int ql   = lane & 3;

    float* sBe  = (float*)(smem + OFF_BE);
    float* sGa  = (float*)(smem + OFF_GA);
    float* sBt  = (float*)(smem + OFF_BT);
    float* sP   = (float*)(smem + OFF_P);
    float* sS1  = (float*)(smem + OFF_S1);
    float* sS2  = (float*)(smem + OFF_S2);
    float* sAtt = (float*)(smem + OFF_ATT);
    float* sMu  = (float*)(smem + OFF_MU);
    float* sRs  = (float*)(smem + OFF_RS);

    // one-time: stream full weight matrix into smem (196608 B = 24 x 512 x 16B)
    {
        const char* src = g_Wdb;
        const uint32_t dst = sbase + OFF_W;
        #pragma unroll
        for (int it = 0; it < 24; it++)
            CP_ASYNC16(dst + tid * 16 + it * 8192, src + tid * 16 + it * 8192);
        CP_COMMIT();
    }
    if (tid < 256) sBe[tid] = be[tid];
    if (tid < 128) { sGa[tid] = gamma[tid]; sBt[tid] = beta[tid]; }

    // per-thread epilogue constants (uniform across tiles) -> registers
    float cu[4], wv[4], cx[4], cgt[4];
    #pragma unroll
    for (int j = 0; j < 2; j++)
        #pragma unroll
        for (int q = 0; q < 2; q++) {
            const int uc = cg * 16 + j * 8 + ql * 2 + q;
            cu[j * 2 + q]  = g_c[uc];
            wv[j * 2 + q]  = Wa2[uc];
            cx[j * 2 + q]  = g_c[128 + uc];
            cgt[j * 2 + q] = g_c[256 + uc];
        }
    const float ba2v = ba2[0];
    const int is64 = g_idx64;

    // per-lane ldmatrix constants
    const uint32_t a_row = (uint32_t)rowg * 32 + ((lane >> 3) & 1) * 8 + (lane & 7);
    const uint32_t a_k   = (uint32_t)(lane >> 4) * 16;
    const uint32_t aconst = a_row * 128 + (a_k ^ (((uint32_t)(lane & 7)) << 4)); // +rt*2048, ^ss*32
    const uint32_t b_k = ((lane >> 3) & 1) * 16;
    const uint32_t p0  = (uint32_t)cg * 48 + (uint32_t)(lane >> 4) * 8 + (lane & 7); // +mi*16
    const uint32_t r0  = p0 >> 1;
    const uint32_t h0  = p0 & 1;
    const uint32_t bconst = r0 * 128 + (((h0 << 6) ^ ((r0 & 7) << 4)) ^ b_k);    // +mi*1024, ^(ss&1)*32
    const uint32_t aB = sbase + OFF_A;
    const uint32_t wB = sbase + OFF_W;

    // gather-thread constants: 2 K64 chunks per thread, same node both
    const int r_g = (tid & 255) >> 2, qt = tid & 3;
    const int kc0 = (tid >> 8) * 2;                 // 0 -> src chunks, 2 -> tgt chunks
    const uint32_t rs = (uint32_t)(r_g & 7) << 4;

    CP_WAIT0();
    __syncthreads();   // weights + consts resident

    const int rl = rowg * 32 + (lane >> 2);   // + rt*16 + h*8

    for (int tile = blockIdx.x; tile < NTILES; tile += GRID_P) {
        const int e0 = tile * TM;
        const int cnt = min(TM, E_TOTAL - e0);

        // node index straight from gmem (4 adjacent threads share one address)
        int node = 0;
        if (r_g < cnt) {
            const int base = kc0 ? E_TOTAL : 0;
            node = is64 ? (int)((const long long*)eidx)[base + e0 + r_g]
                        : ((const int*)eidx)[base + e0 + r_g];
        }

        __syncthreads();   // previous epilogue's scratch reads done before overwrite

        // gather A: 2 chunks per thread, f16, swizzled 128B rows
        #pragma unroll
        for (int kk = 0; kk < 2; kk++) {
            const int kc = kc0 + kk;
            const float4* src = (const float4*)(emb + (size_t)node * CDIM + (kc & 1) * 64 + qt * 16);
            const float4 v0 = src[0], v1 = src[1], v2 = src[2], v3 = src[3];
            uint4 H0, H1;
            H0.x = pack2(v0.x, v0.y); H0.y = pack2(v0.z, v0.w);
            H0.z = pack2(v1.x, v1.y); H0.w = pack2(v1.z, v1.w);
            H1.x = pack2(v2.x, v2.y); H1.y = pack2(v2.z, v2.w);
            H1.z = pack2(v3.x, v3.y); H1.w = pack2(v3.z, v3.w);
            const uint32_t base = OFF_A + kc * 8192 + r_g * 128;
            *(uint4*)(smem + base + (((uint32_t)qt * 32) ^ rs)) = H0;
            *(uint4*)(smem + base + (((uint32_t)qt * 32 + 16) ^ rs)) = H1;
        }
        __syncthreads();

        // GEMM: 4 K64 chunks x 4 k16-steps, weights already resident
        float acc[2][6][4];
        #pragma unroll
        for (int rt = 0; rt < 2; rt++)
            #pragma unroll
            for (int j = 0; j < 6; j++)
                #pragma unroll
                for (int q = 0; q < 4; q++) acc[rt][j][q] = 0.f;

        #pragma unroll
        for (int c = 0; c < 4; c++) {
            const uint32_t kcA = aB + (uint32_t)c * 8192;
            const uint32_t cW  = wB + (uint32_t)c * 49152;
            #pragma unroll
            for (int ss = 0; ss < 4; ss++) {
                const uint32_t akx = (uint32_t)ss * 32;
                uint32_t Ah[2][4];
                #pragma unroll
                for (int rt = 0; rt < 2; rt++)
                    LDMX4(Ah[rt], kcA + (uint32_t)rt * 2048 + (aconst ^ akx));
                const uint32_t bsub = cW + (uint32_t)(ss >> 1) * 24576;
                const uint32_t bxor = (uint32_t)(ss & 1) * 32;
                uint32_t Bh[3][4];
                #pragma unroll
                for (int mi = 0; mi < 3; mi++)
                    LDMX4(Bh[mi], bsub + ((bconst + (uint32_t)mi * 1024) ^ bxor));
                #pragma unroll
                for (int rt = 0; rt < 2; rt++)
                    #pragma unroll
                    for (int mi = 0; mi < 3; mi++) {
                        MMA_F16(acc[rt][2 * mi],     Ah[rt], Bh[mi][0], Bh[mi][1]);
                        MMA_F16(acc[rt][2 * mi + 1], Ah[rt], Bh[mi][2], Bh[mi][3]);
                    }
            }
        }
        __syncthreads();   // all LDSM of A done before scratch overlays it

        // ---- epilogue ----
        // attention partials: u tiles 0,1
        float part[2][2] = {{0.f, 0.f}, {0.f, 0.f}};
        #pragma unroll
        for (int rt = 0; rt < 2; rt++)
            #pragma unroll
            for (int j = 0; j < 2; j++)
                #pragma unroll
                for (int q = 0; q < 2; q++) {
                    const int id = j * 2 + q;
                    part[rt][0] = fmaf(fmaxf(acc[rt][j][q]     + cu[id], 0.f), wv[id], part[rt][0]);
                    part[rt][1] = fmaf(fmaxf(acc[rt][j][2 + q] + cu[id], 0.f), wv[id], part[rt][1]);
                }
        #pragma unroll
        for (int rt = 0; rt < 2; rt++)
            #pragma unroll
            for (int h = 0; h < 2; h++) {
                part[rt][h] += __shfl_xor_sync(0xffffffffu, part[rt][h], 1);
                part[rt][h] += __shfl_xor_sync(0xffffffffu, part[rt][h], 2);
            }
        if (ql == 0) {
            #pragma unroll
            for (int rt = 0; rt < 2; rt++)
                #pragma unroll
                for (int h = 0; h < 2; h++)
                    sP[cg * 64 + rl + rt * 16 + h * 8] = part[rt][h];
        }
        __syncthreads();
        if (tid < 64) {
            float s = ba2v;
            #pragma unroll
            for (int g = 0; g < 8; g++) s += sP[g * 64 + tid];
            sAtt[tid] = 1.f / (1.f + expf(-s));
        }
        __syncthreads();

        // GeGLU: x tiles 2,3 pair gate tiles 4,5 (same thread)
        float gvv[2][2][4];
        float s1[2][2] = {{0.f, 0.f}, {0.f, 0.f}};
        float s2[2][2] = {{0.f, 0.f}, {0.f, 0.f}};
        #pragma unroll
        for (int rt = 0; rt < 2; rt++)
            #pragma unroll
            for (int h = 0; h < 2; h++) {
                const float at = sAtt[rl + rt * 16 + h * 8];
                #pragma unroll
                for (int j = 0; j < 2; j++)
                    #pragma unroll
                    for (int q = 0; q < 2; q++) {
                        const int id = j * 2 + q;
                        const int m = cg * 16 + j * 8 + ql * 2 + q;
                        const float zx = fmaf(at, acc[rt][2 + j][2 * h + q] + cx[id],  sBe[m]);
                        const float zg = fmaf(at, acc[rt][4 + j][2 * h + q] + cgt[id], sBe[128 + m]);
                        const float gel = 0.5f * zg * (1.f + erff(zg * 0.70710678118654752f));
                        const float v = zx * gel;
                        gvv[rt][h][id] = v;
                        s1[rt][h] += v;
                        s2[rt][h] = fmaf(v, v, s2[rt][h]);
                    }
            }
        #pragma unroll
        for (int rt = 0; rt < 2; rt++)
            #pragma unroll
            for (int h = 0; h < 2; h++) {
                s1[rt][h] += __shfl_xor_sync(0xffffffffu, s1[rt][h], 1);
                s1[rt][h] += __shfl_xor_sync(0xffffffffu, s1[rt][h], 2);
                s2[rt][h] += __shfl_xor_sync(0xffffffffu, s2[rt][h], 1);
                s2[rt][h] += __shfl_xor_sync(0xffffffffu, s2[rt][h], 2);
            }
        if (ql == 0) {
            #pragma unroll
            for (int rt = 0; rt < 2; rt++)
                #pragma unroll
                for (int h = 0; h < 2; h++) {
                    sS1[cg * 64 + rl + rt * 16 + h * 8] = s1[rt][h];
                    sS2[cg * 64 + rl + rt * 16 + h * 8] = s2[rt][h];
                }
        }
        __syncthreads();
        if (tid < 64) {
            float S1 = 0.f, S2 = 0.f;
            #pragma unroll
            for (int g = 0; g < 8; g++) { S1 += sS1[g * 64 + tid]; S2 += sS2[g * 64 + tid]; }
            const float mu = S1 * (1.f / 128.f);
            const float var = S2 * (1.f / 128.f) - mu * mu;
            sMu[tid] = mu;
            sRs[tid] = rsqrtf(var + 1e-5f);
        }
        __syncthreads();

        #pragma unroll
        for (int rt = 0; rt < 2; rt++)
            #pragma unroll
            for (int h = 0; h < 2; h++) {
                const int r = rl + rt * 16 + h * 8;
                if (r < cnt) {
                    const float mu = sMu[r], rsd = sRs[r];
                    float* orow = out + (size_t)(e0 + r) * CDIM;
                    #pragma unroll
                    for (int j = 0; j < 2; j++) {
                        const int m = cg * 16 + j * 8 + ql * 2;
                        float2 o;
                        o.x = (gvv[rt][h][j * 2]     - mu) * rsd * sGa[m]     + sBt[m];
                        o.y = (gvv[rt][h][j * 2 + 1] - mu) * rsd * sGa[m + 1] + sBt[m + 1];
                        *(float2*)(orow + m) = o;
                    }
                }
            }
    }
}

// ---------------------------------------------------------------------------
extern "C" void kernel_launch(void* const* d_in, const int* in_sizes, int n_in,
                              void* d_out, int out_size) {
    const float* emb   = (const float*)d_in[0];
    const void*  eidx  = d_in[1];
    const float* Ws    = (const float*)d_in[2];
    const float* bs    = (const float*)d_in[3];
    const float* Wt    = (const float*)d_in[4];
    const float* bt    = (const float*)d_in[5];
    const float* Wa1   = (const float*)d_in[6];
    const float* ba1   = (const float*)d_in[7];
    const float* Wa2   = (const float*)d_in[8];
    const float* ba2   = (const float*)d_in[9];
    const float* We    = (const float*)d_in[10];
    const float* be    = (const float*)d_in[11];
    const float* gamma = (const float*)d_in[12];
    const float* beta  = (const float*)d_in[13];
    float* out = (float*)d_out;

    cudaFuncSetAttribute(fused_kernel, cudaFuncAttributeMaxDynamicSharedMemorySize, SMEM_BYTES);

    detect_idx_kernel<<<1, 32>>>((const int*)eidx);
    precompute_W_kernel<<<(256 * NCOL + 255) / 256, 256>>>(Ws, Wt, Wa1, We);
    precompute_c_kernel<<<2, 256>>>(Wa1, We, bs, bt, ba1);
    convert_W_kernel<<<(8 * 384 * 32 + 255) / 256, 256>>>();
    fused_kernel<<<GRID_P, 512, SMEM_BYTES>>>(emb, eidx, Wa2, ba2, be, gamma, beta, out);
}

// round 16
// speedup vs baseline: 6.9229x; 1.2110x over previous
#include <cuda_runtime.h>
#include <cuda_fp16.h>
#include <math.h>
#include <stdint.h>

#define E_TOTAL 500000
#define TM 32
#define NTILES (E_TOTAL / TM)     // 15625 exactly (no partial tile)
#define NCOL 384
#define CDIM 128
#define GRID_P 152
#define NGROUPS (GRID_P * 2)      // 304 tile pipelines

// fused fp32 weights (logical cols: 0..127 attn-u, 128..255 GeGLU-x, 256..383 gate)
__device__ float g_W[256 * NCOL];
__device__ float g_c[NCOL];
__device__ int   g_idx64;
// f16 weights, reordered + pair-packed + swizzled, 8 K32 sub-chunks of 24576 B
// (consumed as 4 K64 chunks of 49152 B). col order: 8 groups of 48 = 16u|16x|16gate.
// element (p,k): r=p>>1, h=p&1, off = r*128 + (((h<<6)|(k*2)) ^ ((r&7)<<4)).
__device__ __align__(16) char g_Wdb[8 * 24576];

// ---------------------------------------------------------------------------
__device__ __forceinline__ uint32_t smem_u32(const void* p) {
    uint32_t a;
    asm("{ .reg .u64 t; cvta.to.shared.u64 t, %1; cvt.u32.u64 %0, t; }" : "=r"(a) : "l"(p));
    return a;
}
#define LDMX4(arr, addr) \
    asm volatile("ldmatrix.sync.aligned.m8n8.x4.shared.b16 {%0,%1,%2,%3}, [%4];" \
        : "=r"((arr)[0]), "=r"((arr)[1]), "=r"((arr)[2]), "=r"((arr)[3]) : "r"(addr))
// non-volatile: pure register op, ptxas free to software-pipeline the HMMA chain
#define MMA_F16(d, a, b0, b1) \
    asm("mma.sync.aligned.m16n8k16.row.col.f32.f16.f16.f32 " \
        "{%0,%1,%2,%3}, {%4,%5,%6,%7}, {%8,%9}, {%0,%1,%2,%3};" \
        : "+f"((d)[0]), "+f"((d)[1]), "+f"((d)[2]), "+f"((d)[3]) \
        : "r"((a)[0]), "r"((a)[1]), "r"((a)[2]), "r"((a)[3]), "r"(b0), "r"(b1))
#define CP_ASYNC16(dst, src) \
    asm volatile("cp.async.cg.shared.global [%0], [%1], 16;" :: "r"(dst), "l"(src) : "memory")
#define CP_COMMIT() asm volatile("cp.async.commit_group;" ::: "memory")
#define CP_WAIT0()  asm volatile("cp.async.wait_group 0;" ::: "memory")
// group barrier: 256 threads, named barrier id 1+g
#define BARG(id) asm volatile("bar.sync %0, 256;" :: "r"(id) : "memory")

// smem layout (persistent kernel, two tile pipelines):
//   [0, 196608)           resident f16 weights (4 K64 chunks of 49152)
//   [196608, 212992)      group 0: A tile (4 chunks x 4096) / epilogue scratch overlay
//   [212992, 229376)      group 1: same
//   [229376, 231424)      gamma | beta | be
#define OFF_W    0u
#define OFF_A    196608u
#define AGRP_SZ  16384u
// scratch offsets within a group's A region (A dead during epilogue)
#define SC_P     0u          // 8x32 f = 1024
#define SC_S1    1024u
#define SC_S2    2048u
#define SC_ATT   3072u       // 32 f
#define SC_MU    3200u
#define SC_RS    3328u
#define OFF_GA   229376u     // 128 f
#define OFF_BT   229888u     // 128 f
#define OFF_BE   230400u     // 256 f
#define SMEM_BYTES 231424

// ---------------------------------------------------------------------------
__global__ void detect_idx_kernel(const int* __restrict__ idx32) {
    if (threadIdx.x == 0) {
        int nz = 0;
        for (int i = 0; i < 256; i++) nz |= idx32[2 * i + 1];
        g_idx64 = (nz == 0) ? 1 : 0;
    }
}

__global__ void precompute_W_kernel(const float* __restrict__ Ws, const float* __restrict__ Wt,
                                    const float* __restrict__ Wa1, const float* __restrict__ We) {
    int t = blockIdx.x * blockDim.x + threadIdx.x;
    if (t >= 256 * NCOL) return;
    int k = t / NCOL;
    int j = t % NCOL;
    const float* arow = (k < 128) ? (Ws + k * 128) : (Wt + (k - 128) * 128);
    const int off = (k < 128) ? 0 : 128;
    float sum = 0.f;
    if (j < 128) {
        const float* bcol = Wa1 + off * 128 + j;
        #pragma unroll 4
        for (int m = 0; m < 128; m++) sum = fmaf(arow[m], bcol[m * 128], sum);
    } else {
        const float* bcol = We + off * 256 + (j - 128);
        #pragma unroll 4
        for (int m = 0; m < 128; m++) sum = fmaf(arow[m], bcol[m * 256], sum);
    }
    g_W[k * NCOL + j] = sum;
}

__global__ void precompute_c_kernel(const float* __restrict__ Wa1, const float* __restrict__ We,
                                    const float* __restrict__ bs, const float* __restrict__ bt,
                                    const float* __restrict__ ba1) {
    int j = blockIdx.x * blockDim.x + threadIdx.x;
    if (j >= NCOL) return;
    float s;
    if (j < 128) {
        s = ba1[j];
        for (int m = 0; m < 128; m++)
            s += bs[m] * Wa1[m * 128 + j] + bt[m] * Wa1[(128 + m) * 128 + j];
    } else {
        const int jj = j - 128;
        s = 0.f;
        for (int m = 0; m < 128; m++)
            s += bs[m] * We[m * 256 + jj] + bt[m] * We[(128 + m) * 256 + jj];
    }
    g_c[j] = s;
}

// 384 cols (8 groups of 48 = 16u|16x|16gate), single f16, pair-pack + swizzle
__global__ void convert_W_kernel() {
    int t = blockIdx.x * blockDim.x + threadIdx.x;
    if (t >= 8 * 384 * 32) return;
    const int c = t / (384 * 32);
    const int rem = t % (384 * 32);
    const int p = rem / 32;
    const int k = rem % 32;
    const int g = p / 48, q = p % 48;
    int L;
    if (q < 16)      L = 16 * g + q;
    else if (q < 32) L = 128 + 16 * g + (q - 16);
    else             L = 256 + 16 * g + (q - 32);
    const float v = g_W[(c * 32 + k) * NCOL + L];
    const int r = p >> 1, h = p & 1;
    const int off = r * 128 + ((((h << 6) | (k * 2))) ^ ((r & 7) << 4));
    *(__half*)(g_Wdb + c * 24576 + off) = __float2half_rn(v);
}

// ---------------------------------------------------------------------------
__device__ __forceinline__ unsigned pack2(float a, float b) {
    const __half2 h = __floats2half2_rn(a, b);
    return *reinterpret_cast<const unsigned*>(&h);
}

// ---------------------------------------------------------------------------
// PERSISTENT kernel, TWO tile pipelines per CTA: 512 threads = 2 groups x
// 8 warps. Each group owns a 32-edge tile stream (TM=32), its own A buffer
// and scratch, synced by named barriers — group 0's FMA epilogue overlaps
// group 1's tensor GEMM. Weights resident in smem (shared, read-only).
// Warp = 32 rows x 48 cols (2rt x 6 n8 tiles: 2u,2x,2gate), f16 single-
// product math (identical numerics to R13-R15).
// ---------------------------------------------------------------------------
__global__ void __launch_bounds__(512, 1) fused_kernel(
    const float* __restrict__ emb, const void* __restrict__ eidx,
    const float* __restrict__ Wa2, const float* __restrict__ ba2,
    const float* __restrict__ be, const float* __restrict__ gamma,
    const float* __restrict__ beta, float* __restrict__ out)
{
    extern __shared__ char smem[];
    const uint32_t sbase = smem_u32(smem);
    const int tid = threadIdx.x;
    const int grp = tid >> 8;          // 0..1
    const int lt  = tid & 255;         // group-local tid
    const int wid = lt >> 5;           // 0..7 within group
    const int lane = tid & 31;
    const int cg   = wid;              // 8 col groups of 48
    const int ql   = lane & 3;
    const int barid = 1 + grp;

    float* sBe  = (float*)(smem + OFF_BE);
    float* sGa  = (float*)(smem + OFF_GA);
    float* sBt  = (float*)(smem + OFF_BT);
    const uint32_t Ag = OFF_A + (uint32_t)grp * AGRP_SZ;
    float* sP   = (float*)(smem + Ag + SC_P);
    float* sS1  = (float*)(smem + Ag + SC_S1);
    float* sS2  = (float*)(smem + Ag + SC_S2);
    float* sAtt = (float*)(smem + Ag + SC_ATT);
    float* sMu  = (float*)(smem + Ag + SC_MU);
    float* sRs  = (float*)(smem + Ag + SC_RS);

    // one-time: stream full weight matrix into smem (196608 B = 24 x 512 x 16B)
    {
        const char* src = g_Wdb;
        const uint32_t dst = sbase + OFF_W;
        #pragma unroll
        for (int it = 0; it < 24; it++)
            CP_ASYNC16(dst + tid * 16 + it * 8192, src + tid * 16 + it * 8192);
        CP_COMMIT();
    }
    if (tid < 256) sBe[tid] = be[tid];
    if (tid < 128) { sGa[tid] = gamma[tid]; sBt[tid] = beta[tid]; }

    // per-thread epilogue constants (uniform across tiles) -> registers
    float cu[4], wv[4], cx[4], cgt[4];
    #pragma unroll
    for (int j = 0; j < 2; j++)
        #pragma unroll
        for (int q = 0; q < 2; q++) {
            const int uc = cg * 16 + j * 8 + ql * 2 + q;
            cu[j * 2 + q]  = g_c[uc];
            wv[j * 2 + q]  = Wa2[uc];
            cx[j * 2 + q]  = g_c[128 + uc];
            cgt[j * 2 + q] = g_c[256 + uc];
        }
    const float ba2v = ba2[0];
    const int is64 = g_idx64;

    // per-lane ldmatrix constants (A tile: 32 rows x 128B/chunk, 4 chunks of 4096)
    const uint32_t a_row = ((lane >> 3) & 1) * 8 + (lane & 7);    // + rt*16
    const uint32_t a_k   = (uint32_t)(lane >> 4) * 16;
    const uint32_t aconst = a_row * 128 + (a_k ^ (((uint32_t)(lane & 7)) << 4)); // +rt*2048, ^ss*32
    const uint32_t b_k = ((lane >> 3) & 1) * 16;
    const uint32_t p0  = (uint32_t)cg * 48 + (uint32_t)(lane >> 4) * 8 + (lane & 7); // +mi*16
    const uint32_t r0  = p0 >> 1;
    const uint32_t h0  = p0 & 1;
    const uint32_t bconst = r0 * 128 + (((h0 << 6) ^ ((r0 & 7) << 4)) ^ b_k);    // +mi*1024, ^(ss&1)*32
    const uint32_t aB = sbase + Ag;
    const uint32_t wB = sbase + OFF_W;

    // gather constants: 32 rows x 4 threads; each thread 2 K64 chunks (src or tgt)
    const int r_g = (lt & 127) >> 2, qt = lt & 3;
    const int kc0 = (lt >> 7) * 2;                 // 0 -> src chunks, 2 -> tgt chunks
    const uint32_t rs = (uint32_t)(r_g & 7) << 4;
    const int idx_base = kc0 ? E_TOTAL : 0;

    CP_WAIT0();
    __syncthreads();   // weights + consts resident; groups diverge after this

    const int rl = lane >> 2;   // + rt*16 + h*8

    const int gid = blockIdx.x * 2 + grp;
    for (int tile = gid; tile < NTILES; tile += NGROUPS) {
        const int e0 = tile * TM;

        // node index straight from gmem (4 adjacent threads share one address)
        const int node = is64 ? (int)((const long long*)eidx)[idx_base + e0 + r_g]
                              : ((const int*)eidx)[idx_base + e0 + r_g];

        BARG(barid);   // previous epilogue's scratch reads done before overwrite

        // gather A: 2 chunks per thread, f16, swizzled 128B rows
        #pragma unroll
        for (int kk = 0; kk < 2; kk++) {
            const int kc = kc0 + kk;
            const float4* src = (const float4*)(emb + (size_t)node * CDIM + (kc & 1) * 64 + qt * 16);
            const float4 v0 = src[0], v1 = src[1], v2 = src[2], v3 = src[3];
            uint4 H0, H1;
            H0.x = pack2(v0.x, v0.y); H0.y = pack2(v0.z, v0.w);
            H0.z = pack2(v1.x, v1.y); H0.w = pack2(v1.z, v1.w);
            H1.x = pack2(v2.x, v2.y); H1.y = pack2(v2.z, v2.w);
            H1.z = pack2(v3.x, v3.y); H1.w = pack2(v3.z, v3.w);
            const uint32_t base = Ag + kc * 4096 + r_g * 128;
            *(uint4*)(smem + base + (((uint32_t)qt * 32) ^ rs)) = H0;
            *(uint4*)(smem + base + (((uint32_t)qt * 32 + 16) ^ rs)) = H1;
        }
        BARG(barid);

        // GEMM: 4 K64 chunks x 4 k16-steps, weights resident
        float acc[2][6][4];
        #pragma unroll
        for (int rt = 0; rt < 2; rt++)
            #pragma unroll
            for (int j = 0; j < 6; j++)
                #pragma unroll
                for (int q = 0; q < 4; q++) acc[rt][j][q] = 0.f;

        #pragma unroll
        for (int c = 0; c < 4; c++) {
            const uint32_t kcA = aB + (uint32_t)c * 4096;
            const uint32_t cW  = wB + (uint32_t)c * 49152;
            #pragma unroll
            for (int ss = 0; ss < 4; ss++) {
                const uint32_t akx = (uint32_t)ss * 32;
                uint32_t Ah[2][4];
                #pragma unroll
                for (int rt = 0; rt < 2; rt++)
                    LDMX4(Ah[rt], kcA + (uint32_t)rt * 2048 + (aconst ^ akx));
                const uint32_t bsub = cW + (uint32_t)(ss >> 1) * 24576;
                const uint32_t bxor = (uint32_t)(ss & 1) * 32;
                uint32_t Bh[3][4];
                #pragma unroll
                for (int mi = 0; mi < 3; mi++)
                    LDMX4(Bh[mi], bsub + ((bconst + (uint32_t)mi * 1024) ^ bxor));
                #pragma unroll
                for (int rt = 0; rt < 2; rt++)
                    #pragma unroll
                    for (int mi = 0; mi < 3; mi++) {
                        MMA_F16(acc[rt][2 * mi],     Ah[rt], Bh[mi][0], Bh[mi][1]);
                        MMA_F16(acc[rt][2 * mi + 1], Ah[rt], Bh[mi][2], Bh[mi][3]);
                    }
            }
        }
        BARG(barid);   // all LDSM of A done before scratch overlays it

        // ---- epilogue ----
        // attention partials: u tiles 0,1
        float part[2][2] = {{0.f, 0.f}, {0.f, 0.f}};
        #pragma unroll
        for (int rt = 0; rt < 2; rt++)
            #pragma unroll
            for (int j = 0; j < 2; j++)
                #pragma unroll
                for (int q = 0; q < 2; q++) {
                    const int id = j * 2 + q;
                    part[rt][0] = fmaf(fmaxf(acc[rt][j][q]     + cu[id], 0.f), wv[id], part[rt][0]);
                    part[rt][1] = fmaf(fmaxf(acc[rt][j][2 + q] + cu[id], 0.f), wv[id], part[rt][1]);
                }
        #pragma unroll
        for (int rt = 0; rt < 2; rt++)
            #pragma unroll
            for (int h = 0; h < 2; h++) {
                part[rt][h] += __shfl_xor_sync(0xffffffffu, part[rt][h], 1);
                part[rt][h] += __shfl_xor_sync(0xffffffffu, part[rt][h], 2);
            }
        if (ql == 0) {
            #pragma unroll
            for (int rt = 0; rt < 2; rt++)
                #pragma unroll
                for (int h = 0; h < 2; h++)
                    sP[cg * 32 + rl + rt * 16 + h * 8] = part[rt][h];
        }
        BARG(barid);
        if (lt < 32) {
            float s = ba2v;
            #pragma unroll
            for (int g = 0; g < 8; g++) s += sP[g * 32 + lt];
            sAtt[lt] = 1.f / (1.f + expf(-s));
        }
        BARG(barid);

        // GeGLU: x tiles 2,3 pair gate tiles 4,5 (same thread)
        float gvv[2][2][4];
        float s1[2][2] = {{0.f, 0.f}, {0.f, 0.f}};
        float s2[2][2] = {{0.f, 0.f}, {0.f, 0.f}};
        #pragma unroll
        for (int rt = 0; rt < 2; rt++)
            #pragma unroll
            for (int h = 0; h < 2; h++) {
                const float at = sAtt[rl + rt * 16 + h * 8];
                #pragma unroll
                for (int j = 0; j < 2; j++)
                    #pragma unroll
                    for (int q = 0; q < 2; q++) {
                        const int id = j * 2 + q;
                        const int m = cg * 16 + j * 8 + ql * 2 + q;
                        const float zx = fmaf(at, acc[rt][2 + j][2 * h + q] + cx[id],  sBe[m]);
                        const float zg = fmaf(at, acc[rt][4 + j][2 * h + q] + cgt[id], sBe[128 + m]);
                        const float gel = 0.5f * zg * (1.f + erff(zg * 0.70710678118654752f));
                        const float v = zx * gel;
                        gvv[rt][h][id] = v;
                        s1[rt][h] += v;
                        s2[rt][h] = fmaf(v, v, s2[rt][h]);
                    }
            }
        #pragma unroll
        for (int rt = 0; rt < 2; rt++)
            #pragma unroll
            for (int h = 0; h < 2; h++) {
                s1[rt][h] += __shfl_xor_sync(0xffffffffu, s1[rt][h], 1);
                s1[rt][h] += __shfl_xor_sync(0xffffffffu, s1[rt][h], 2);
                s2[rt][h] += __shfl_xor_sync(0xffffffffu, s2[rt][h], 1);
                s2[rt][h] += __shfl_xor_sync(0xffffffffu, s2[rt][h], 2);
            }
        if (ql == 0) {
            #pragma unroll
            for (int rt = 0; rt < 2; rt++)
                #pragma unroll
                for (int h = 0; h < 2; h++) {
                    sS1[cg * 32 + rl + rt * 16 + h * 8] = s1[rt][h];
                    sS2[cg * 32 + rl + rt * 16 + h * 8] = s2[rt][h];
                }
        }
        BARG(barid);
        if (lt < 32) {
            float S1 = 0.f, S2 = 0.f;
            #pragma unroll
            for (int g = 0; g < 8; g++) { S1 += sS1[g * 32 + lt]; S2 += sS2[g * 32 + lt]; }
            const float mu = S1 * (1.f / 128.f);
            const float var = S2 * (1.f / 128.f) - mu * mu;
            sMu[lt] = mu;
            sRs[lt] = rsqrtf(var + 1e-5f);
        }
        BARG(barid);

        #pragma unroll
        for (int rt = 0; rt < 2; rt++)
            #pragma unroll
            for (int h = 0; h < 2; h++) {
                const int r = rl + rt * 16 + h * 8;
                const float mu = sMu[r], rsd = sRs[r];
                float* orow = out + (size_t)(e0 + r) * CDIM;
                #pragma unroll
                for (int j = 0; j < 2; j++) {
                    const int m = cg * 16 + j * 8 + ql * 2;
                    float2 o;
                    o.x = (gvv[rt][h][j * 2]     - mu) * rsd * sGa[m]     + sBt[m];
                    o.y = (gvv[rt][h][j * 2 + 1] - mu) * rsd * sGa[m + 1] + sBt[m + 1];
                    *(float2*)(orow + m) = o;
                }
            }
    }
}

// ---------------------------------------------------------------------------
extern "C" void kernel_launch(void* const* d_in, const int* in_sizes, int n_in,
                              void* d_out, int out_size) {
    const float* emb   = (const float*)d_in[0];
    const void*  eidx  = d_in[1];
    const float* Ws    = (const float*)d_in[2];
    const float* bs    = (const float*)d_in[3];
    const float* Wt    = (const float*)d_in[4];
    const float* bt    = (const float*)d_in[5];
    const float* Wa1   = (const float*)d_in[6];
    const float* ba1   = (const float*)d_in[7];
    const float* Wa2   = (const float*)d_in[8];
    const float* ba2   = (const float*)d_in[9];
    const float* We    = (const float*)d_in[10];
    const float* be    = (const float*)d_in[11];
    const float* gamma = (const float*)d_in[12];
    const float* beta  = (const float*)d_in[13];
    float* out = (float*)d_out;

    cudaFuncSetAttribute(fused_kernel, cudaFuncAttributeMaxDynamicSharedMemorySize, SMEM_BYTES);

    detect_idx_kernel<<<1, 32>>>((const int*)eidx);
    precompute_W_kernel<<<(256 * NCOL + 255) / 256, 256>>>(Ws, Wt, Wa1, We);
    precompute_c_kernel<<<2, 256>>>(Wa1, We, bs, bt, ba1);
    convert_W_kernel<<<(8 * 384 * 32 + 255) / 256, 256>>>();
    fused_kernel<<<GRID_P, 512, SMEM_BYTES>>>(emb, eidx, Wa2, ba2, be, gamma, beta, out);
}

// round 17
// speedup vs baseline: 10.0804x; 1.4561x over previous
#include <cuda_runtime.h>
#include <cuda_fp16.h>
#include <math.h>
#include <stdint.h>

#define E_TOTAL 500000
#define N_NODES 50000
#define NCOL 384
#define CDIM 128
#define NT_A 782              // ceil(50000/64)
#define GRID_A 304            // 152 per half, persistent
#define UVHALF (N_NODES * NCOL)

// fused fp32 weights (logical cols: 0..127 attn-u, 128..255 GeGLU-x, 256..383 gate)
__device__ float g_W[256 * NCOL];
__device__ float g_c[NCOL];
__device__ int   g_idx64;
// f16 hi/lo weights for the node GEMM, physical col order 8 groups of 48 =
// 16u|16x|16gate, pair-packed + swizzled. Layout: [half2][sub4][hi|lo][24576B];
// element (p,k32): r=p>>1, hh=p&1, off = r*128 + (((hh<<6)|(k*2)) ^ ((r&7)<<4)).
__device__ __align__(16) char g_WA[2 * 4 * 2 * 24576];
// node projection tables, f16: U = g_UV[0..UVHALF), V = g_UV[UVHALF..)
__device__ __align__(16) __half g_UV[2 * N_NODES * NCOL];   // 76.8 MB

// ---------------------------------------------------------------------------
__device__ __forceinline__ uint32_t smem_u32(const void* p) {
    uint32_t a;
    asm("{ .reg .u64 t; cvta.to.shared.u64 t, %1; cvt.u32.u64 %0, t; }" : "=r"(a) : "l"(p));
    return a;
}
#define LDMX4(arr, addr) \
    asm volatile("ldmatrix.sync.aligned.m8n8.x4.shared.b16 {%0,%1,%2,%3}, [%4];" \
        : "=r"((arr)[0]), "=r"((arr)[1]), "=r"((arr)[2]), "=r"((arr)[3]) : "r"(addr))
#define MMA_F16(d, a, b0, b1) \
    asm("mma.sync.aligned.m16n8k16.row.col.f32.f16.f16.f32 " \
        "{%0,%1,%2,%3}, {%4,%5,%6,%7}, {%8,%9}, {%0,%1,%2,%3};" \
        : "+f"((d)[0]), "+f"((d)[1]), "+f"((d)[2]), "+f"((d)[3]) \
        : "r"((a)[0]), "r"((a)[1]), "r"((a)[2]), "r"((a)[3]), "r"(b0), "r"(b1))
#define CP_ASYNC16(dst, src) \
    asm volatile("cp.async.cg.shared.global [%0], [%1], 16;" :: "r"(dst), "l"(src) : "memory")
#define CP_COMMIT() asm volatile("cp.async.commit_group;" ::: "memory")
#define CP_WAIT0()  asm volatile("cp.async.wait_group 0;" ::: "memory")

// kernel A smem: [0,196608) resident weights (4 sub x hi|lo), [196608,212992) A tile
#define OFF_WA 0u
#define OFF_AT 196608u
#define SMEM_A_BYTES 212992

// ---------------------------------------------------------------------------
__global__ void detect_idx_kernel(const int* __restrict__ idx32) {
    if (threadIdx.x == 0) {
        int nz = 0;
        for (int i = 0; i < 256; i++) nz |= idx32[2 * i + 1];
        g_idx64 = (nz == 0) ? 1 : 0;
    }
}

__global__ void precompute_W_kernel(const float* __restrict__ Ws, const float* __restrict__ Wt,
                                    const float* __restrict__ Wa1, const float* __restrict__ We) {
    int t = blockIdx.x * blockDim.x + threadIdx.x;
    if (t >= 256 * NCOL) return;
    int k = t / NCOL;
    int j = t % NCOL;
    const float* arow = (k < 128) ? (Ws + k * 128) : (Wt + (k - 128) * 128);
    const int off = (k < 128) ? 0 : 128;
    float sum = 0.f;
    if (j < 128) {
        const float* bcol = Wa1 + off * 128 + j;
        #pragma unroll 4
        for (int m = 0; m < 128; m++) sum = fmaf(arow[m], bcol[m * 128], sum);
    } else {
        const float* bcol = We + off * 256 + (j - 128);
        #pragma unroll 4
        for (int m = 0; m < 128; m++) sum = fmaf(arow[m], bcol[m * 256], sum);
    }
    g_W[k * NCOL + j] = sum;
}

__global__ void precompute_c_kernel(const float* __restrict__ Wa1, const float* __restrict__ We,
                                    const float* __restrict__ bs, const float* __restrict__ bt,
                                    const float* __restrict__ ba1) {
    int j = blockIdx.x * blockDim.x + threadIdx.x;
    if (j >= NCOL) return;
    float s;
    if (j < 128) {
        s = ba1[j];
        for (int m = 0; m < 128; m++)
            s += bs[m] * Wa1[m * 128 + j] + bt[m] * Wa1[(128 + m) * 128 + j];
    } else {
        const int jj = j - 128;
        s = 0.f;
        for (int m = 0; m < 128; m++)
            s += bs[m] * We[m * 256 + jj] + bt[m] * We[(128 + m) * 256 + jj];
    }
    g_c[j] = s;
}

// reorder + f16 hi/lo split + pair-pack + swizzle into g_WA
__global__ void convert_W_kernel() {
    int t = blockIdx.x * blockDim.x + threadIdx.x;
    if (t >= 2 * 4 * 384 * 32) return;
    const int hf  = t / (4 * 384 * 32);
    const int sub = (t / (384 * 32)) & 3;
    const int p   = (t / 32) % 384;
    const int k   = t & 31;
    const int g = p / 48, q = p % 48;
    int L;
    if (q < 16)      L = 16 * g + q;
    else if (q < 32) L = 128 + 16 * g + (q - 16);
    else             L = 256 + 16 * g + (q - 32);
    const int krow = hf * 128 + sub * 32 + k;
    const float v = g_W[krow * NCOL + L];
    const __half hi = __float2half_rn(v);
    const __half lo = __float2half_rn(v - __half2float(hi));
    const int r = p >> 1, hh = p & 1;
    const int off = r * 128 + ((((hh << 6) | (k * 2))) ^ ((r & 7) << 4));
    char* base = g_WA + ((size_t)(hf * 4 + sub)) * 49152;
    *(__half*)(base + off) = hi;
    *(__half*)(base + 24576 + off) = lo;
}

// ---------------------------------------------------------------------------
__device__ __forceinline__ unsigned pack2(float a, float b) {
    const __half2 h = __floats2half2_rn(a, b);
    return *reinterpret_cast<const unsigned*>(&h);
}

// ---------------------------------------------------------------------------
// Kernel A: node projection GEMM. 304 persistent CTAs (152 per half); half 0
// computes U[n] = X[n]·W_top, half 1 computes V[n] = X[n]·W_bot, 2-product
// f16 (W hi+lo), fp32 accum, stored f16 to g_UV. 512 thr = 2 rowg x 8 cg;
// warp 32 rows x 48 cols; A loads are fully coalesced (no gather!).
// ---------------------------------------------------------------------------
__global__ void __launch_bounds__(512, 1) node_kernel(const float* __restrict__ emb)
{
    extern __shared__ char smem[];
    const uint32_t sbase = smem_u32(smem);
    const int tid = threadIdx.x;
    const int wid = tid >> 5;
    const int lane = tid & 31;
    const int rowg = wid >> 3;
    const int cg   = wid & 7;
    const int ql   = lane & 3;
    const int hf   = blockIdx.x & 1;
    const int cta  = blockIdx.x >> 1;

    // load this half's weights (196608 B = 24 x 512 x 16B)
    {
        const char* src = g_WA + (size_t)hf * 196608;
        const uint32_t dst = sbase + OFF_WA;
        #pragma unroll
        for (int it = 0; it < 24; it++)
            CP_ASYNC16(dst + tid * 16 + it * 8192, src + tid * 16 + it * 8192);
        CP_COMMIT();
    }

    // ldmatrix constants
    const uint32_t a_row = (uint32_t)rowg * 32 + ((lane >> 3) & 1) * 8 + (lane & 7);
    const uint32_t a_k   = (uint32_t)(lane >> 4) * 16;
    const uint32_t aconst = a_row * 128 + (a_k ^ (((uint32_t)(lane & 7)) << 4));
    const uint32_t b_k = ((lane >> 3) & 1) * 16;
    const uint32_t p0  = (uint32_t)cg * 48 + (uint32_t)(lane >> 4) * 8 + (lane & 7);
    const uint32_t r0  = p0 >> 1;
    const uint32_t h0  = p0 & 1;
    const uint32_t bconst = r0 * 128 + (((h0 << 6) ^ ((r0 & 7) << 4)) ^ b_k);
    const uint32_t aB = sbase + OFF_AT;
    const uint32_t wB = sbase + OFF_WA;

    // gather constants (coalesced): 8 threads per row
    const int r_g = tid >> 3, qt = tid & 7;
    const uint32_t rs = (uint32_t)(r_g & 7) << 4;
    const int rl = rowg * 32 + (lane >> 2);
    __half* uvout = g_UV + (size_t)hf * UVHALF;

    CP_WAIT0();
    __syncthreads();

    for (int tile = cta; tile < NT_A; tile += 152) {
        const int t64 = tile * 64;
        __syncthreads();   // previous tile's LDSM done before overwrite

        // load A tile: 64 nodes x 128 dims, f16-packed, swizzled (coalesced LDG)
        {
            int node = t64 + r_g;
            if (node >= N_NODES) node = 0;
            const float4* src = (const float4*)(emb + (size_t)node * CDIM + qt * 16);
            const float4 v0 = src[0], v1 = src[1], v2 = src[2], v3 = src[3];
            uint4 H0, H1;
            H0.x = pack2(v0.x, v0.y); H0.y = pack2(v0.z, v0.w);
            H0.z = pack2(v1.x, v1.y); H0.w = pack2(v1.z, v1.w);
            H1.x = pack2(v2.x, v2.y); H1.y = pack2(v2.z, v2.w);
            H1.z = pack2(v3.x, v3.y); H1.w = pack2(v3.z, v3.w);
            const uint32_t kb = (uint32_t)(qt & 3) * 32;
            const uint32_t base = OFF_AT + (qt >> 2) * 8192 + r_g * 128;
            *(uint4*)(smem + base + (kb ^ rs)) = H0;
            *(uint4*)(smem + base + ((kb + 16) ^ rs)) = H1;
        }
        __syncthreads();

        float acc[2][6][4];
        #pragma unroll
        for (int rt = 0; rt < 2; rt++)
            #pragma unroll
            for (int j = 0; j < 6; j++)
                #pragma unroll
                for (int q = 0; q < 4; q++) acc[rt][j][q] = 0.f;

        #pragma unroll
        for (int c = 0; c < 2; c++) {
            const uint32_t kcA = aB + (uint32_t)c * 8192;
            #pragma unroll
            for (int ss = 0; ss < 4; ss++) {
                const uint32_t akx = (uint32_t)ss * 32;
                uint32_t Ah[2][4];
                #pragma unroll
                for (int rt = 0; rt < 2; rt++)
                    LDMX4(Ah[rt], kcA + (uint32_t)rt * 2048 + (aconst ^ akx));
                const uint32_t bsub = wB + (uint32_t)(c * 2 + (ss >> 1)) * 49152;
                const uint32_t bxor = (uint32_t)(ss & 1) * 32;
                uint32_t Bh[3][4], Bl[3][4];
                #pragma unroll
                for (int mi = 0; mi < 3; mi++) {
                    const uint32_t addr = bsub + ((bconst + (uint32_t)mi * 1024) ^ bxor);
                    LDMX4(Bh[mi], addr);
                    LDMX4(Bl[mi], addr + 24576);
                }
                #pragma unroll
                for (int rt = 0; rt < 2; rt++)
                    #pragma unroll
                    for (int mi = 0; mi < 3; mi++) {
                        MMA_F16(acc[rt][2 * mi],     Ah[rt], Bh[mi][0], Bh[mi][1]);
                        MMA_F16(acc[rt][2 * mi + 1], Ah[rt], Bh[mi][2], Bh[mi][3]);
                    }
                #pragma unroll
                for (int rt = 0; rt < 2; rt++)
                    #pragma unroll
                    for (int mi = 0; mi < 3; mi++) {
                        MMA_F16(acc[rt][2 * mi],     Ah[rt], Bl[mi][0], Bl[mi][1]);
                        MMA_F16(acc[rt][2 * mi + 1], Ah[rt], Bl[mi][2], Bl[mi][3]);
                    }
            }
        }

        // store f16 rows to the table (logical layout [n][u128|x128|gate128])
        #pragma unroll
        for (int rt = 0; rt < 2; rt++)
            #pragma unroll
            for (int h = 0; h < 2; h++) {
                const int row = t64 + rl + rt * 16 + h * 8;
                if (row < N_NODES) {
                    __half* orow = uvout + (size_t)row * NCOL;
                    #pragma unroll
                    for (int jj = 0; jj < 6; jj++) {
                        const int mi = jj >> 1, b = jj & 1;
                        const int col = mi * 128 + cg * 16 + b * 8 + ql * 2;
                        *(__half2*)(orow + col) =
                            __floats2half2_rn(acc[rt][jj][2 * h], acc[rt][jj][2 * h + 1]);
                    }
                }
            }
    }
}

// ---------------------------------------------------------------------------
// Kernel B: warp-per-edge epilogue. Y = U[src] + V[tgt] (+c), then attn gate,
// GeGLU, LayerNorm — all warp-shuffle, no smem, no barriers.
// ---------------------------------------------------------------------------
__global__ void __launch_bounds__(256) edge_kernel(
    const void* __restrict__ eidx,
    const float* __restrict__ Wa2, const float* __restrict__ ba2,
    const float* __restrict__ be, const float* __restrict__ gamma,
    const float* __restrict__ beta, float* __restrict__ out)
{
    const int wid = threadIdx.x >> 5;
    const int lane = threadIdx.x & 31;
    const int e = blockIdx.x * 8 + wid;
    const int c0 = lane * 4;

    int src, tgt;
    if (g_idx64) {
        const long long* p = (const long long*)eidx;
        src = (int)p[e]; tgt = (int)p[E_TOTAL + e];
    } else {
        const int* p = (const int*)eidx;
        src = p[e]; tgt = p[E_TOTAL + e];
    }

    // per-lane constants (L1/L2 cached, uniform across blocks)
    const float4 CU = *(const float4*)(g_c + c0);
    const float4 CX = *(const float4*)(g_c + 128 + c0);
    const float4 CG = *(const float4*)(g_c + 256 + c0);
    const float4 WA = *(const float4*)(Wa2 + c0);
    const float4 BX = *(const float4*)(be + c0);
    const float4 BG = *(const float4*)(be + 128 + c0);
    const float ba2v = ba2[0];

    const __half2* Up = (const __half2*)(g_UV + (size_t)src * NCOL);
    const __half2* Vp = (const __half2*)(g_UV + (size_t)UVHALF + (size_t)tgt * NCOL);
    const int hc = lane * 2;   // half2 index of col c0

    float y[3][4];
    #pragma unroll
    for (int sec = 0; sec < 3; sec++) {
        const int o = sec * 64 + hc;
        const float2 u0 = __half22float2(Up[o]),     u1 = __half22float2(Up[o + 1]);
        const float2 v0 = __half22float2(Vp[o]),     v1 = __half22float2(Vp[o + 1]);
        y[sec][0] = u0.x + v0.x; y[sec][1] = u0.y + v0.y;
        y[sec][2] = u1.x + v1.x; y[sec][3] = u1.y + v1.y;
    }

    // attention gate
    float p = fmaxf(y[0][0] + CU.x, 0.f) * WA.x
            + fmaxf(y[0][1] + CU.y, 0.f) * WA.y
            + fmaxf(y[0][2] + CU.z, 0.f) * WA.z
            + fmaxf(y[0][3] + CU.w, 0.f) * WA.w;
    #pragma unroll
    for (int o = 16; o >= 1; o >>= 1)
        p += __shfl_xor_sync(0xffffffffu, p, o);
    const float attn = 1.f / (1.f + expf(-(p + ba2v)));

    // GeGLU
    const float cx[4] = {CX.x, CX.y, CX.z, CX.w};
    const float cgv[4] = {CG.x, CG.y, CG.z, CG.w};
    const float bx[4] = {BX.x, BX.y, BX.z, BX.w};
    const float bg[4] = {BG.x, BG.y, BG.z, BG.w};
    float gv[4], s1 = 0.f, s2 = 0.f;
    #pragma unroll
    for (int q = 0; q < 4; q++) {
        const float zx = fmaf(attn, y[1][q] + cx[q], bx[q]);
        const float zg = fmaf(attn, y[2][q] + cgv[q], bg[q]);
        const float gel = 0.5f * zg * (1.f + erff(zg * 0.70710678118654752f));
        gv[q] = zx * gel;
        s1 += gv[q];
        s2 = fmaf(gv[q], gv[q], s2);
    }
    #pragma unroll
    for (int o = 16; o >= 1; o >>= 1) {
        s1 += __shfl_xor_sync(0xffffffffu, s1, o);
        s2 += __shfl_xor_sync(0xffffffffu, s2, o);
    }
    const float mu = s1 * (1.f / 128.f);
    const float var = s2 * (1.f / 128.f) - mu * mu;
    const float rstd = rsqrtf(var + 1e-5f);

    const float4 GAv = *(const float4*)(gamma + c0);
    const float4 BTv = *(const float4*)(beta + c0);
    float4 o4;
    o4.x = (gv[0] - mu) * rstd * GAv.x + BTv.x;
    o4.y = (gv[1] - mu) * rstd * GAv.y + BTv.y;
    o4.z = (gv[2] - mu) * rstd * GAv.z + BTv.z;
    o4.w = (gv[3] - mu) * rstd * GAv.w + BTv.w;
    *(float4*)(out + (size_t)e * CDIM + c0) = o4;
}

// ---------------------------------------------------------------------------
extern "C" void kernel_launch(void* const* d_in, const int* in_sizes, int n_in,
                              void* d_out, int out_size) {
    const float* emb   = (const float*)d_in[0];
    const void*  eidx  = d_in[1];
    const float* Ws    = (const float*)d_in[2];
    const float* bs    = (const float*)d_in[3];
    const float* Wt    = (const float*)d_in[4];
    const float* bt    = (const float*)d_in[5];
    const float* Wa1   = (const float*)d_in[6];
    const float* ba1   = (const float*)d_in[7];
    const float* Wa2   = (const float*)d_in[8];
    const float* ba2   = (const float*)d_in[9];
    const float* We    = (const float*)d_in[10];
    const float* be    = (const float*)d_in[11];
    const float* gamma = (const float*)d_in[12];
    const float* beta  = (const float*)d_in[13];
    float* out = (float*)d_out;

    cudaFuncSetAttribute(node_kernel, cudaFuncAttributeMaxDynamicSharedMemorySize, SMEM_A_BYTES);

    detect_idx_kernel<<<1, 32>>>((const int*)eidx);
    precompute_W_kernel<<<(256 * NCOL + 255) / 256, 256>>>(Ws, Wt, Wa1, We);
    precompute_c_kernel<<<2, 256>>>(Wa1, We, bs, bt, ba1);
    convert_W_kernel<<<(2 * 4 * 384 * 32 + 255) / 256, 256>>>();
    node_kernel<<<GRID_A, 512, SMEM_A_BYTES>>>(emb);
    edge_kernel<<<E_TOTAL / 8, 256>>>(eidx, Wa2, ba2, be, gamma, beta, out);
}